// round 1
// baseline (speedup 1.0000x reference)
#include <cuda_runtime.h>
#include <math.h>

#define EMB 1024
#define SEQ 1024
#define BATCH 4
#define NH 16
#define HD 64

// ---------------- scratch (device globals; no allocation allowed) ----------
__device__ float g_q[BATCH * SEQ * EMB];
__device__ float g_k[BATCH * SEQ * EMB];
__device__ float g_v[BATCH * SEQ * EMB];
__device__ float g_ctx[BATCH * SEQ * EMB];
__device__ float g_cw[BATCH * SEQ * NH];

// ---------------- SGEMM: C = A(MxK) @ B(KxN) + bias(N) ---------------------
// BM=128, BN=64, BK=16, 256 threads, each thread computes 8x4.
__global__ __launch_bounds__(256) void sgemm_bias(
    const float* __restrict__ A, const float* __restrict__ B,
    const float* __restrict__ bias, float* __restrict__ C,
    int M, int N, int K)
{
    __shared__ float As[16][128];
    __shared__ float Bs[16][64];

    const int tid = threadIdx.x;
    const int tx = tid & 15;   // 0..15 -> 4 cols each
    const int ty = tid >> 4;   // 0..15 -> 8 rows each
    const int row0 = blockIdx.y * 128;
    const int col0 = blockIdx.x * 64;

    float acc[8][4];
#pragma unroll
    for (int i = 0; i < 8; i++)
#pragma unroll
        for (int j = 0; j < 4; j++) acc[i][j] = 0.f;

    for (int k0 = 0; k0 < K; k0 += 16) {
        // load A tile 128x16 (transposed into As[k][m])
#pragma unroll
        for (int li = 0; li < 2; li++) {
            int idx = tid * 2 + li;            // 0..511 float4s
            int r = idx >> 2;                  // 0..127
            int c4 = (idx & 3) * 4;            // 0,4,8,12
            float4 v = *(const float4*)&A[(size_t)(row0 + r) * K + k0 + c4];
            As[c4 + 0][r] = v.x;
            As[c4 + 1][r] = v.y;
            As[c4 + 2][r] = v.z;
            As[c4 + 3][r] = v.w;
        }
        // load B tile 16x64
        {
            int r = tid >> 4;                  // 0..15
            int c4 = (tid & 15) * 4;
            *(float4*)&Bs[r][c4] = *(const float4*)&B[(size_t)(k0 + r) * N + col0 + c4];
        }
        __syncthreads();

#pragma unroll
        for (int kk = 0; kk < 16; kk++) {
            float a[8], bf[4];
#pragma unroll
            for (int i = 0; i < 8; i++) a[i] = As[kk][ty * 8 + i];
#pragma unroll
            for (int j = 0; j < 4; j++) bf[j] = Bs[kk][tx * 4 + j];
#pragma unroll
            for (int i = 0; i < 8; i++)
#pragma unroll
                for (int j = 0; j < 4; j++) acc[i][j] += a[i] * bf[j];
        }
        __syncthreads();
    }

    float4 bv = *(const float4*)&bias[col0 + tx * 4];
#pragma unroll
    for (int i = 0; i < 8; i++) {
        float4 o;
        o.x = acc[i][0] + bv.x;
        o.y = acc[i][1] + bv.y;
        o.z = acc[i][2] + bv.z;
        o.w = acc[i][3] + bv.w;
        *(float4*)&C[(size_t)(row0 + ty * 8 + i) * N + col0 + tx * 4] = o;
    }
}

// ---------------- cw = softmax(query @ Wc + bc, axis=H) --------------------
// 256 threads = 16 rows x 16 heads per block.
__global__ __launch_bounds__(256) void cw_kernel(
    const float* __restrict__ query, const float* __restrict__ Wc,
    const float* __restrict__ bc, float* __restrict__ CW)
{
    const int tid = threadIdx.x;
    const int row = blockIdx.x * 16 + (tid >> 4);
    const int h = tid & 15;

    float acc = bc[h];
    const float* qrow = query + (size_t)row * EMB;
#pragma unroll 4
    for (int i = 0; i < EMB; i++) acc += qrow[i] * Wc[i * NH + h];

    // softmax over the 16-lane group
    float m = acc;
#pragma unroll
    for (int o = 8; o > 0; o >>= 1) m = fmaxf(m, __shfl_xor_sync(0xffffffffu, m, o, 16));
    float e = __expf(acc - m);
    float s = e;
#pragma unroll
    for (int o = 8; o > 0; o >>= 1) s += __shfl_xor_sync(0xffffffffu, s, o, 16);
    CW[(size_t)row * NH + h] = e / s;
}

// ---------------- attention ------------------------------------------------
// Block: one (b,h), 16 query rows. 256 threads.
// Dynamic smem: esc[16][1024] | kv[64][68] | qs[16][64]
#define ROWS 16
#define KT 64
#define KV_STRIDE 68

__global__ __launch_bounds__(256) void attn_kernel(
    const float* __restrict__ Q, const float* __restrict__ Km,
    const float* __restrict__ Vm, const float* __restrict__ CW,
    const float* __restrict__ cons, float* __restrict__ attn_out,
    float* __restrict__ ctx)
{
    extern __shared__ float sm[];
    float* esc = sm;                                // ROWS*1024
    float* kv = sm + ROWS * 1024;                   // KT*KV_STRIDE
    float* qs = kv + KT * KV_STRIDE;                // ROWS*64
    __shared__ float zinv[ROWS];

    const int tid = threadIdx.x;
    const int bh = blockIdx.y;
    const int b = bh >> 4;
    const int h = bh & 15;
    const int q0 = blockIdx.x * ROWS;
    const float INV_SCALE = 1.0f / (8.0f * sqrtf(1.61803398874989485f));

    // load q rows: 1024 floats = 256 float4
    {
        int r = tid >> 4;
        int d4 = (tid & 15) * 4;
        *(float4*)&qs[r * 64 + d4] =
            *(const float4*)&Q[((size_t)(b * SEQ + q0 + r)) * EMB + h * HD + d4];
    }

    const int ty = tid >> 4;   // query row 0..15
    const int tx = tid & 15;   // k/d group
    const int kmax = q0 + ROWS;

    // ---- phase 1: raw scores for k < kmax ----
    for (int kt = 0; kt < kmax; kt += KT) {
#pragma unroll
        for (int li = 0; li < 4; li++) {
            int idx = tid + li * 256;          // 0..1023 float4s
            int r = idx >> 4;
            int d4 = (idx & 15) * 4;
            *(float4*)&kv[r * KV_STRIDE + d4] =
                *(const float4*)&Km[((size_t)(b * SEQ + kt + r)) * EMB + h * HD + d4];
        }
        __syncthreads();

        float acc0 = 0.f, acc1 = 0.f, acc2 = 0.f, acc3 = 0.f;
#pragma unroll
        for (int d = 0; d < HD; d += 4) {
            float4 qv = *(float4*)&qs[ty * 64 + d];
            const float* k0p = &kv[(tx * 4 + 0) * KV_STRIDE + d];
            const float* k1p = &kv[(tx * 4 + 1) * KV_STRIDE + d];
            const float* k2p = &kv[(tx * 4 + 2) * KV_STRIDE + d];
            const float* k3p = &kv[(tx * 4 + 3) * KV_STRIDE + d];
            acc0 += qv.x * k0p[0] + qv.y * k0p[1] + qv.z * k0p[2] + qv.w * k0p[3];
            acc1 += qv.x * k1p[0] + qv.y * k1p[1] + qv.z * k1p[2] + qv.w * k1p[3];
            acc2 += qv.x * k2p[0] + qv.y * k2p[1] + qv.z * k2p[2] + qv.w * k2p[3];
            acc3 += qv.x * k3p[0] + qv.y * k3p[1] + qv.z * k3p[2] + qv.w * k3p[3];
        }
        esc[ty * 1024 + kt + tx * 4 + 0] = acc0 * INV_SCALE;
        esc[ty * 1024 + kt + tx * 4 + 1] = acc1 * INV_SCALE;
        esc[ty * 1024 + kt + tx * 4 + 2] = acc2 * INV_SCALE;
        esc[ty * 1024 + kt + tx * 4 + 3] = acc3 * INV_SCALE;
        __syncthreads();
    }

    // ---- phase 2: softmax1 -> rescale -> softmax2 numerators ----
    // (phi_bias is a per-row constant: cancels in softmax, skipped)
    {
        const int warp = tid >> 5, lane = tid & 31;
        for (int rr = 0; rr < 2; rr++) {
            int r = warp * 2 + rr;
            int q = q0 + r;
            int kc = q + 1;                     // valid (unmasked) count
            float* row = &esc[r * 1024];

            float m = -1e30f;
            for (int k = lane; k < kc; k += 32) m = fmaxf(m, row[k]);
#pragma unroll
            for (int o = 16; o > 0; o >>= 1) m = fmaxf(m, __shfl_xor_sync(0xffffffffu, m, o));

            float s = 0.f;
            for (int k = lane; k < kc; k += 32) {
                float p = __expf(row[k] - m);
                row[k] = p;
                s += p;
            }
#pragma unroll
            for (int o = 16; o > 0; o >>= 1) s += __shfl_xor_sync(0xffffffffu, s, o);

            float cb = cons[b * SEQ + q];
            float cwv = CW[(size_t)(b * SEQ + q) * NH + h];
            float fs = (1.f + cb * cwv) / s;    // attn1*f == p*fs

            float z2 = 0.f;
            for (int k = lane; k < kc; k += 32) {
                float e = __expf(row[k] * fs);
                row[k] = e;
                z2 += e;
            }
            // masked region: attn1 = 0 -> exp(0) = 1 (2nd softmax is unmasked!)
            for (int k = kc + lane; k < SEQ; k += 32) row[k] = 1.f;
#pragma unroll
            for (int o = 16; o > 0; o >>= 1) z2 += __shfl_xor_sync(0xffffffffu, z2, o);
            z2 += (float)(SEQ - kc);
            if (lane == 0) zinv[r] = 1.f / z2;
        }
    }
    __syncthreads();

    // ---- write final attn to output ----
    {
        const size_t abase = ((size_t)bh * SEQ + q0) * SEQ;
        for (int idx4 = tid; idx4 < ROWS * 1024 / 4; idx4 += 256) {
            int r = idx4 >> 8;
            float zi = zinv[r];
            float4 v = *(float4*)&esc[idx4 * 4];
            v.x *= zi; v.y *= zi; v.z *= zi; v.w *= zi;
            *(float4*)&attn_out[abase + (size_t)idx4 * 4] = v;
        }
    }

    // ---- ctx = (sum_k e_k * v_k) * zinv, over ALL k ----
    float c0 = 0.f, c1 = 0.f, c2 = 0.f, c3 = 0.f;
    for (int kt = 0; kt < SEQ; kt += KT) {
#pragma unroll
        for (int li = 0; li < 4; li++) {
            int idx = tid + li * 256;
            int r = idx >> 4;
            int d4 = (idx & 15) * 4;
            *(float4*)&kv[r * KV_STRIDE + d4] =
                *(const float4*)&Vm[((size_t)(b * SEQ + kt + r)) * EMB + h * HD + d4];
        }
        __syncthreads();
#pragma unroll
        for (int kk = 0; kk < KT; kk++) {
            float w = esc[ty * 1024 + kt + kk];
            const float* vr = &kv[kk * KV_STRIDE + tx * 4];
            c0 += w * vr[0];
            c1 += w * vr[1];
            c2 += w * vr[2];
            c3 += w * vr[3];
        }
        __syncthreads();
    }
    {
        float zi = zinv[ty];
        float4 o;
        o.x = c0 * zi; o.y = c1 * zi; o.z = c2 * zi; o.w = c3 * zi;
        *(float4*)&ctx[((size_t)(b * SEQ + q0 + ty)) * EMB + h * HD + tx * 4] = o;
    }
}

// ---------------- launch ----------------------------------------------------
extern "C" void kernel_launch(void* const* d_in, const int* in_sizes, int n_in,
                              void* d_out, int out_size)
{
    const float* query = (const float*)d_in[0];
    const float* key   = (const float*)d_in[1];
    const float* value = (const float*)d_in[2];
    const float* cons  = (const float*)d_in[3];
    // d_in[4] = attn_mask (causal, known statically — unused)
    const float* Wq = (const float*)d_in[5];
    const float* bq = (const float*)d_in[6];
    const float* Wk = (const float*)d_in[7];
    const float* bk = (const float*)d_in[8];
    const float* Wv = (const float*)d_in[9];
    const float* bv = (const float*)d_in[10];
    const float* Wo = (const float*)d_in[11];
    const float* bo = (const float*)d_in[12];
    const float* Wc = (const float*)d_in[13];
    const float* bc = (const float*)d_in[14];
    // d_in[15] = phi_bias (cancels in softmax — unused)

    float* qp; cudaGetSymbolAddress((void**)&qp, g_q);
    float* kp; cudaGetSymbolAddress((void**)&kp, g_k);
    float* vp; cudaGetSymbolAddress((void**)&vp, g_v);
    float* cp; cudaGetSymbolAddress((void**)&cp, g_ctx);
    float* cwp; cudaGetSymbolAddress((void**)&cwp, g_cw);

    float* out = (float*)d_out;                       // (B,S,E) = 4194304 floats
    float* attn_out = out + (size_t)BATCH * SEQ * EMB; // (B,H,S,S)

    const int M = BATCH * SEQ;      // 4096
    dim3 gemm_grid(EMB / 64, M / 128);

    sgemm_bias<<<gemm_grid, 256>>>(query, Wq, bq, qp, M, EMB, EMB);
    sgemm_bias<<<gemm_grid, 256>>>(key,   Wk, bk, kp, M, EMB, EMB);
    sgemm_bias<<<gemm_grid, 256>>>(value, Wv, bv, vp, M, EMB, EMB);

    cw_kernel<<<M / 16, 256>>>(query, Wc, bc, cwp);

    const int smem = (ROWS * 1024 + KT * KV_STRIDE + ROWS * 64) * sizeof(float); // 87040
    cudaFuncSetAttribute(attn_kernel, cudaFuncAttributeMaxDynamicSharedMemorySize, smem);
    dim3 attn_grid(SEQ / ROWS, BATCH * NH);           // (64, 64)
    attn_kernel<<<attn_grid, 256, smem>>>(qp, kp, vp, cwp, cons, attn_out, cp);

    sgemm_bias<<<gemm_grid, 256>>>(cp, Wo, bo, out, M, EMB, EMB);
}

// round 2
// speedup vs baseline: 1.2110x; 1.2110x over previous
#include <cuda_runtime.h>
#include <math.h>

#define EMB 1024
#define SEQ 1024
#define BATCH 4
#define NH 16
#define HD 64

// ---------------- scratch (device globals; no allocation allowed) ----------
__device__ float g_q[BATCH * SEQ * EMB];
__device__ float g_k[BATCH * SEQ * EMB];
__device__ float g_v[BATCH * SEQ * EMB];
__device__ float g_ctx[BATCH * SEQ * EMB];
__device__ float g_cw[BATCH * SEQ * NH];
__device__ float g_vsuf[BATCH * NH * SEQ * HD];   // SufV[bh][q][d] = sum_{k>q} V[k][d]

// ---------------- SGEMM: C = A(MxK) @ B(KxN) + bias(N) ---------------------
// BM=128, BN=128, BK=16, 256 threads, each thread computes 8x8.
__global__ __launch_bounds__(256, 2) void sgemm_bias(
    const float* __restrict__ A, const float* __restrict__ B,
    const float* __restrict__ bias, float* __restrict__ C,
    int M, int N, int K)
{
    __shared__ float As[16][128];
    __shared__ float Bs[16][128];

    const int tid = threadIdx.x;
    const int tx = tid & 15;   // 0..15 -> 8 cols each
    const int ty = tid >> 4;   // 0..15 -> 8 rows each
    const int row0 = blockIdx.y * 128;
    const int col0 = blockIdx.x * 128;

    float acc[8][8];
#pragma unroll
    for (int i = 0; i < 8; i++)
#pragma unroll
        for (int j = 0; j < 8; j++) acc[i][j] = 0.f;

    for (int k0 = 0; k0 < K; k0 += 16) {
        // A tile 128x16 -> As[k][m] (transposed)
#pragma unroll
        for (int li = 0; li < 2; li++) {
            int idx = tid * 2 + li;            // 0..511 float4s
            int r = idx >> 2;                  // 0..127
            int kg = (idx & 3) * 4;            // 0,4,8,12
            float4 v = *(const float4*)&A[(size_t)(row0 + r) * K + k0 + kg];
            As[kg + 0][r] = v.x;
            As[kg + 1][r] = v.y;
            As[kg + 2][r] = v.z;
            As[kg + 3][r] = v.w;
        }
        // B tile 16x128 direct
#pragma unroll
        for (int li = 0; li < 2; li++) {
            int idx = tid * 2 + li;            // 0..511
            int r = idx >> 5;                  // 0..15
            int c4 = (idx & 31) * 4;           // 0..124
            *(float4*)&Bs[r][c4] = *(const float4*)&B[(size_t)(k0 + r) * N + col0 + c4];
        }
        __syncthreads();

#pragma unroll
        for (int kk = 0; kk < 16; kk++) {
            float a[8], bf[8];
            *(float4*)&a[0]  = *(float4*)&As[kk][ty * 8];
            *(float4*)&a[4]  = *(float4*)&As[kk][ty * 8 + 4];
            *(float4*)&bf[0] = *(float4*)&Bs[kk][tx * 8];
            *(float4*)&bf[4] = *(float4*)&Bs[kk][tx * 8 + 4];
#pragma unroll
            for (int i = 0; i < 8; i++)
#pragma unroll
                for (int j = 0; j < 8; j++) acc[i][j] += a[i] * bf[j];
        }
        __syncthreads();
    }

    float4 bv0 = *(const float4*)&bias[col0 + tx * 8];
    float4 bv1 = *(const float4*)&bias[col0 + tx * 8 + 4];
#pragma unroll
    for (int i = 0; i < 8; i++) {
        float4 o0, o1;
        o0.x = acc[i][0] + bv0.x; o0.y = acc[i][1] + bv0.y;
        o0.z = acc[i][2] + bv0.z; o0.w = acc[i][3] + bv0.w;
        o1.x = acc[i][4] + bv1.x; o1.y = acc[i][5] + bv1.y;
        o1.z = acc[i][6] + bv1.z; o1.w = acc[i][7] + bv1.w;
        size_t base = (size_t)(row0 + ty * 8 + i) * N + col0 + tx * 8;
        *(float4*)&C[base]     = o0;
        *(float4*)&C[base + 4] = o1;
    }
}

// ---------------- cw = softmax(query @ Wc + bc, axis=H) --------------------
// 128 threads = 8 rows x 16 heads per block; q rows staged in smem.
__global__ __launch_bounds__(128) void cw_kernel(
    const float* __restrict__ query, const float* __restrict__ Wc,
    const float* __restrict__ bc, float* __restrict__ CW)
{
    __shared__ float qs[8][1024];   // 32 KB
    const int tid = threadIdx.x;
    const int row0 = blockIdx.x * 8;

    // stage 8 q rows: 2048 float4 / 128 threads = 16 each
    for (int idx = tid; idx < 2048; idx += 128) {
        int r = idx >> 8;
        int c4 = (idx & 255) * 4;
        *(float4*)&qs[r][c4] = *(const float4*)&query[(size_t)(row0 + r) * EMB + c4];
    }
    __syncthreads();

    const int r = tid >> 4;
    const int h = tid & 15;
    const float* q = &qs[r][0];

    float a0 = 0.f, a1 = 0.f, a2 = 0.f, a3 = 0.f;
#pragma unroll 4
    for (int i = 0; i < EMB; i += 4) {
        a0 += q[i + 0] * Wc[(i + 0) * NH + h];
        a1 += q[i + 1] * Wc[(i + 1) * NH + h];
        a2 += q[i + 2] * Wc[(i + 2) * NH + h];
        a3 += q[i + 3] * Wc[(i + 3) * NH + h];
    }
    float acc = bc[h] + (a0 + a1) + (a2 + a3);

    // softmax over the 16-lane group
    float m = acc;
#pragma unroll
    for (int o = 8; o > 0; o >>= 1) m = fmaxf(m, __shfl_xor_sync(0xffffffffu, m, o, 16));
    float e = __expf(acc - m);
    float s = e;
#pragma unroll
    for (int o = 8; o > 0; o >>= 1) s += __shfl_xor_sync(0xffffffffu, s, o, 16);
    CW[(size_t)(row0 + r) * NH + h] = e / s;
}

// ---------------- suffix sums of V: Suf[bh][q][d] = sum_{k>q} V[k][d] ------
__global__ __launch_bounds__(256) void vsuffix_kernel(
    const float* __restrict__ V, float* __restrict__ Suf)
{
    __shared__ float T[4][64];
    const int bh = blockIdx.x;
    const int b = bh >> 4;
    const int h = bh & 15;
    const int t = threadIdx.x;
    const int p = t >> 6;      // chunk 0..3
    const int d = t & 63;

    const float* vb = V + (size_t)b * SEQ * EMB + h * HD + d;
    float* sufb = Suf + (size_t)bh * SEQ * HD + d;

    const int k0 = p * 256;
    float s = 0.f;
    for (int k = k0; k < k0 + 256; k++) s += vb[(size_t)k * EMB];
    T[p][d] = s;
    __syncthreads();

    float acc = 0.f;
    for (int pp = p + 1; pp < 4; pp++) acc += T[pp][d];
    // acc = suffix over chunks after p; now walk chunk p backwards
    for (int k = k0 + 255; k >= k0; k--) {
        sufb[(size_t)k * HD] = acc;       // sum over j > k
        acc += vb[(size_t)k * EMB];
    }
}

// ---------------- attention ------------------------------------------------
// Block: one (b,h), 16 query rows. 256 threads.
// Dynamic smem: esc[16][1024] | kv[64][68] | qs[16][64]
#define ROWS 16
#define KT 64
#define KV_STRIDE 68

__global__ __launch_bounds__(256) void attn_kernel(
    const float* __restrict__ Q, const float* __restrict__ Km,
    const float* __restrict__ Vm, const float* __restrict__ CW,
    const float* __restrict__ cons, const float* __restrict__ Suf,
    float* __restrict__ attn_out, float* __restrict__ ctx)
{
    extern __shared__ float sm[];
    float* esc = sm;                                // ROWS*1024
    float* kv = sm + ROWS * 1024;                   // KT*KV_STRIDE
    float* qs = kv + KT * KV_STRIDE;                // ROWS*64
    __shared__ float zinv[ROWS];

    const int tid = threadIdx.x;
    const int bh = blockIdx.y;
    const int b = bh >> 4;
    const int h = bh & 15;
    const int q0 = blockIdx.x * ROWS;
    const float INV_SCALE = 1.0f / (8.0f * sqrtf(1.61803398874989485f));

    // load q rows
    {
        int r = tid >> 4;
        int d4 = (tid & 15) * 4;
        *(float4*)&qs[r * 64 + d4] =
            *(const float4*)&Q[((size_t)(b * SEQ + q0 + r)) * EMB + h * HD + d4];
    }

    const int ty = tid >> 4;   // query row 0..15
    const int tx = tid & 15;   // k/d group
    const int kmax = q0 + ROWS;

    // ---- phase 1: raw scores for k < kmax ----
    for (int kt = 0; kt < kmax; kt += KT) {
#pragma unroll
        for (int li = 0; li < 4; li++) {
            int idx = tid + li * 256;
            int r = idx >> 4;
            int d4 = (idx & 15) * 4;
            *(float4*)&kv[r * KV_STRIDE + d4] =
                *(const float4*)&Km[((size_t)(b * SEQ + kt + r)) * EMB + h * HD + d4];
        }
        __syncthreads();

        float acc0 = 0.f, acc1 = 0.f, acc2 = 0.f, acc3 = 0.f;
#pragma unroll
        for (int d = 0; d < HD; d += 4) {
            float4 qv = *(float4*)&qs[ty * 64 + d];
            const float* k0p = &kv[(tx * 4 + 0) * KV_STRIDE + d];
            const float* k1p = &kv[(tx * 4 + 1) * KV_STRIDE + d];
            const float* k2p = &kv[(tx * 4 + 2) * KV_STRIDE + d];
            const float* k3p = &kv[(tx * 4 + 3) * KV_STRIDE + d];
            acc0 += qv.x * k0p[0] + qv.y * k0p[1] + qv.z * k0p[2] + qv.w * k0p[3];
            acc1 += qv.x * k1p[0] + qv.y * k1p[1] + qv.z * k1p[2] + qv.w * k1p[3];
            acc2 += qv.x * k2p[0] + qv.y * k2p[1] + qv.z * k2p[2] + qv.w * k2p[3];
            acc3 += qv.x * k3p[0] + qv.y * k3p[1] + qv.z * k3p[2] + qv.w * k3p[3];
        }
        esc[ty * 1024 + kt + tx * 4 + 0] = acc0 * INV_SCALE;
        esc[ty * 1024 + kt + tx * 4 + 1] = acc1 * INV_SCALE;
        esc[ty * 1024 + kt + tx * 4 + 2] = acc2 * INV_SCALE;
        esc[ty * 1024 + kt + tx * 4 + 3] = acc3 * INV_SCALE;
        __syncthreads();
    }

    // ---- phase 2: softmax1 -> rescale -> softmax2 numerators ----
    // (phi_bias is a per-row constant: cancels in softmax, skipped)
    {
        const int warp = tid >> 5, lane = tid & 31;
        for (int rr = 0; rr < 2; rr++) {
            int r = warp * 2 + rr;
            int q = q0 + r;
            int kc = q + 1;
            float* row = &esc[r * 1024];

            float m = -1e30f;
            for (int k = lane; k < kc; k += 32) m = fmaxf(m, row[k]);
#pragma unroll
            for (int o = 16; o > 0; o >>= 1) m = fmaxf(m, __shfl_xor_sync(0xffffffffu, m, o));

            float s = 0.f;
            for (int k = lane; k < kc; k += 32) {
                float p = __expf(row[k] - m);
                row[k] = p;
                s += p;
            }
#pragma unroll
            for (int o = 16; o > 0; o >>= 1) s += __shfl_xor_sync(0xffffffffu, s, o);

            float cb = cons[b * SEQ + q];
            float cwv = CW[(size_t)(b * SEQ + q) * NH + h];
            float fs = (1.f + cb * cwv) / s;

            float z2 = 0.f;
            for (int k = lane; k < kc; k += 32) {
                float e = __expf(row[k] * fs);
                row[k] = e;
                z2 += e;
            }
            // masked region: attn1 = 0 -> exp(0) = 1 (2nd softmax is unmasked!)
            for (int k = kc + lane; k < SEQ; k += 32) row[k] = 1.f;
#pragma unroll
            for (int o = 16; o > 0; o >>= 1) z2 += __shfl_xor_sync(0xffffffffu, z2, o);
            z2 += (float)(SEQ - kc);
            if (lane == 0) zinv[r] = 1.f / z2;
        }
    }
    __syncthreads();

    // ---- write final attn to output ----
    {
        const size_t abase = ((size_t)bh * SEQ + q0) * SEQ;
        for (int idx4 = tid; idx4 < ROWS * 1024 / 4; idx4 += 256) {
            int r = idx4 >> 8;
            float zi = zinv[r];
            float4 v = *(float4*)&esc[idx4 * 4];
            v.x *= zi; v.y *= zi; v.z *= zi; v.w *= zi;
            *(float4*)&attn_out[abase + (size_t)idx4 * 4] = v;
        }
    }
    __syncthreads();

    // ---- zero weights for k > q inside the tiles the ctx loop will touch ---
    {
        int r = tid >> 4;
        int q = q0 + r;
        int j = tid & 15;
        int tile_end = ((kmax + 63) >> 6) << 6;   // <= SEQ
        float* row = &esc[r * 1024];
        for (int k = q + 1 + j; k < tile_end; k += 16) row[k] = 0.f;
    }
    __syncthreads();

    // ---- ctx = (sum_{k<=q} e_k * v_k + SufV[q]) * zinv ----
    float c0 = 0.f, c1 = 0.f, c2 = 0.f, c3 = 0.f;
    for (int kt = 0; kt < kmax; kt += KT) {
#pragma unroll
        for (int li = 0; li < 4; li++) {
            int idx = tid + li * 256;
            int r = idx >> 4;
            int d4 = (idx & 15) * 4;
            *(float4*)&kv[r * KV_STRIDE + d4] =
                *(const float4*)&Vm[((size_t)(b * SEQ + kt + r)) * EMB + h * HD + d4];
        }
        __syncthreads();
#pragma unroll
        for (int kk = 0; kk < KT; kk++) {
            float w = esc[ty * 1024 + kt + kk];
            const float* vr = &kv[kk * KV_STRIDE + tx * 4];
            c0 += w * vr[0];
            c1 += w * vr[1];
            c2 += w * vr[2];
            c3 += w * vr[3];
        }
        __syncthreads();
    }
    {
        float zi = zinv[ty];
        float4 sv = *(const float4*)&Suf[((size_t)bh * SEQ + q0 + ty) * HD + tx * 4];
        float4 o;
        o.x = (c0 + sv.x) * zi; o.y = (c1 + sv.y) * zi;
        o.z = (c2 + sv.z) * zi; o.w = (c3 + sv.w) * zi;
        *(float4*)&ctx[((size_t)(b * SEQ + q0 + ty)) * EMB + h * HD + tx * 4] = o;
    }
}

// ---------------- launch ----------------------------------------------------
extern "C" void kernel_launch(void* const* d_in, const int* in_sizes, int n_in,
                              void* d_out, int out_size)
{
    const float* query = (const float*)d_in[0];
    const float* key   = (const float*)d_in[1];
    const float* value = (const float*)d_in[2];
    const float* cons  = (const float*)d_in[3];
    // d_in[4] = attn_mask (causal, known statically — unused)
    const float* Wq = (const float*)d_in[5];
    const float* bq = (const float*)d_in[6];
    const float* Wk = (const float*)d_in[7];
    const float* bk = (const float*)d_in[8];
    const float* Wv = (const float*)d_in[9];
    const float* bv = (const float*)d_in[10];
    const float* Wo = (const float*)d_in[11];
    const float* bo = (const float*)d_in[12];
    const float* Wc = (const float*)d_in[13];
    const float* bc = (const float*)d_in[14];
    // d_in[15] = phi_bias (cancels in softmax — unused)

    float* qp; cudaGetSymbolAddress((void**)&qp, g_q);
    float* kp; cudaGetSymbolAddress((void**)&kp, g_k);
    float* vp; cudaGetSymbolAddress((void**)&vp, g_v);
    float* cp; cudaGetSymbolAddress((void**)&cp, g_ctx);
    float* cwp; cudaGetSymbolAddress((void**)&cwp, g_cw);
    float* sufp; cudaGetSymbolAddress((void**)&sufp, g_vsuf);

    float* out = (float*)d_out;                        // (B,S,E)
    float* attn_out = out + (size_t)BATCH * SEQ * EMB; // (B,H,S,S)

    const int M = BATCH * SEQ;      // 4096
    dim3 gemm_grid(EMB / 128, M / 128);   // (8, 32)

    sgemm_bias<<<gemm_grid, 256>>>(query, Wq, bq, qp, M, EMB, EMB);
    sgemm_bias<<<gemm_grid, 256>>>(key,   Wk, bk, kp, M, EMB, EMB);
    sgemm_bias<<<gemm_grid, 256>>>(value, Wv, bv, vp, M, EMB, EMB);

    cw_kernel<<<M / 8, 128>>>(query, Wc, bc, cwp);
    vsuffix_kernel<<<BATCH * NH, 256>>>(vp, sufp);

    const int smem = (ROWS * 1024 + KT * KV_STRIDE + ROWS * 64) * sizeof(float); // 87040
    cudaFuncSetAttribute(attn_kernel, cudaFuncAttributeMaxDynamicSharedMemorySize, smem);
    dim3 attn_grid(SEQ / ROWS, BATCH * NH);           // (64, 64)
    attn_kernel<<<attn_grid, 256, smem>>>(qp, kp, vp, cwp, cons, sufp, attn_out, cp);

    sgemm_bias<<<gemm_grid, 256>>>(cp, Wo, bo, out, M, EMB, EMB);
}

// round 3
// speedup vs baseline: 1.4755x; 1.2183x over previous
#include <cuda_runtime.h>
#include <cuda_bf16.h>
#include <math.h>
#include <stdint.h>

#define EMB 1024
#define SEQ 1024
#define BATCH 4
#define NH 16
#define HD 64

// ---------------- scratch (device globals; no allocation allowed) ----------
__device__ float g_q[BATCH * SEQ * EMB];
__device__ float g_k[BATCH * SEQ * EMB];
__device__ float g_v[BATCH * SEQ * EMB];
__device__ float g_ctx[BATCH * SEQ * EMB];
__device__ float g_cw[BATCH * SEQ * NH];
__device__ float g_vsuf[BATCH * NH * SEQ * HD];
__device__ __nv_bfloat16 g_ahi[BATCH * SEQ * EMB];
__device__ __nv_bfloat16 g_alo[BATCH * SEQ * EMB];
__device__ __nv_bfloat16 g_bhi[EMB * EMB];
__device__ __nv_bfloat16 g_blo[EMB * EMB];

// ---------------- fp32 -> bf16 hi/lo split ---------------------------------
__global__ __launch_bounds__(256) void split_kernel(
    const float* __restrict__ X, __nv_bfloat16* __restrict__ Hi,
    __nv_bfloat16* __restrict__ Lo, int n4)
{
    int i = blockIdx.x * 256 + threadIdx.x;
    if (i >= n4) return;
    float4 x = ((const float4*)X)[i];
    __nv_bfloat16 h0 = __float2bfloat16(x.x);
    __nv_bfloat16 h1 = __float2bfloat16(x.y);
    __nv_bfloat16 h2 = __float2bfloat16(x.z);
    __nv_bfloat16 h3 = __float2bfloat16(x.w);
    __nv_bfloat162 H0; H0.x = h0; H0.y = h1;
    __nv_bfloat162 H1; H1.x = h2; H1.y = h3;
    __nv_bfloat162 L0;
    L0.x = __float2bfloat16(x.x - __bfloat162float(h0));
    L0.y = __float2bfloat16(x.y - __bfloat162float(h1));
    __nv_bfloat162 L1;
    L1.x = __float2bfloat16(x.z - __bfloat162float(h2));
    L1.y = __float2bfloat16(x.w - __bfloat162float(h3));
    ((__nv_bfloat162*)Hi)[2 * i] = H0;
    ((__nv_bfloat162*)Hi)[2 * i + 1] = H1;
    ((__nv_bfloat162*)Lo)[2 * i] = L0;
    ((__nv_bfloat162*)Lo)[2 * i + 1] = L1;
}

// ---------------- bf16x3 tensor-core GEMM ----------------------------------
// C(MxN) = Ahi@Bhi + Ahi@Blo + Alo@Bhi + bias
// BM=128, BN=128, BK=32, 256 threads (8 warps: 2x4), warp tile 64x32.
#define BM 128
#define BN 128
#define BK 32
#define ASTR 40    // bf16 per A smem row (32 + 8 pad)
#define BSTR 136   // bf16 per B smem row (128 + 8 pad)

#define CP_ASYNC16(dst, src) \
    asm volatile("cp.async.cg.shared.global [%0], [%1], 16;\n" :: "r"(dst), "l"(src))
#define CP_COMMIT asm volatile("cp.async.commit_group;\n" ::)
#define CP_WAIT1  asm volatile("cp.async.wait_group 1;\n" ::)

__global__ __launch_bounds__(256) void gemm_bf16x3(
    const __nv_bfloat16* __restrict__ Ahi, const __nv_bfloat16* __restrict__ Alo,
    const __nv_bfloat16* __restrict__ Bhi, const __nv_bfloat16* __restrict__ Blo,
    const float* __restrict__ bias, float* __restrict__ C,
    int M, int N, int K)
{
    __shared__ __align__(16) __nv_bfloat16 As[2][BM * ASTR];
    __shared__ __align__(16) __nv_bfloat16 Bs[2][BK * BSTR];

    const int tid = threadIdx.x;
    const int lane = tid & 31;
    const int wid = tid >> 5;
    const int wm = wid & 1;        // 0..1 (64-row halves)
    const int wn = wid >> 1;       // 0..3 (32-col quarters)
    const int row0 = blockIdx.y * BM;
    const int col0 = blockIdx.x * BN;

    const __nv_bfloat16* segA[3] = { Ahi, Ahi, Alo };
    const __nv_bfloat16* segB[3] = { Bhi, Blo, Bhi };

    float acc[4][4][4];
#pragma unroll
    for (int i = 0; i < 4; i++)
#pragma unroll
        for (int j = 0; j < 4; j++)
#pragma unroll
            for (int r = 0; r < 4; r++) acc[i][j][r] = 0.f;

    const int KT = K / BK;          // 32
    const int TOT = 3 * KT;         // 96

    // cp.async indices: 2 chunks of 16B each for A and for B per thread
    const int a_idx = tid * 2;                 // 0..510
    const int b_idx = tid * 2;

#define LOAD_TILE(IT, BUF) do {                                              \
    int seg_ = (IT) / KT;                                                    \
    int k0_ = ((IT) % KT) * BK;                                              \
    const __nv_bfloat16* Ag_ = segA[seg_];                                   \
    const __nv_bfloat16* Bg_ = segB[seg_];                                   \
    _Pragma("unroll")                                                        \
    for (int li = 0; li < 2; li++) {                                         \
        int idx = a_idx + li;                                                \
        int r_ = idx >> 2;                                                   \
        int c_ = (idx & 3) * 8;                                              \
        uint32_t d_ = (uint32_t)__cvta_generic_to_shared(                    \
            &As[BUF][r_ * ASTR + c_]);                                       \
        CP_ASYNC16(d_, Ag_ + (size_t)(row0 + r_) * K + k0_ + c_);            \
    }                                                                        \
    _Pragma("unroll")                                                        \
    for (int li = 0; li < 2; li++) {                                         \
        int idx = b_idx + li;                                                \
        int r_ = idx >> 4;                                                   \
        int c_ = (idx & 15) * 8;                                             \
        uint32_t d_ = (uint32_t)__cvta_generic_to_shared(                    \
            &Bs[BUF][r_ * BSTR + c_]);                                       \
        CP_ASYNC16(d_, Bg_ + (size_t)(k0_ + r_) * N + col0 + c_);            \
    }                                                                        \
} while (0)

    LOAD_TILE(0, 0);
    CP_COMMIT;

    for (int it = 0; it < TOT; it++) {
        int buf = it & 1;
        if (it + 1 < TOT) LOAD_TILE(it + 1, buf ^ 1);
        CP_COMMIT;
        CP_WAIT1;
        __syncthreads();

#pragma unroll
        for (int ks = 0; ks < 2; ks++) {
            uint32_t a[4][4];
#pragma unroll
            for (int mi = 0; mi < 4; mi++) {
                uint32_t ad = (uint32_t)__cvta_generic_to_shared(
                    &As[buf][(wm * 64 + mi * 16 + (lane & 15)) * ASTR +
                             ks * 16 + (lane >> 4) * 8]);
                asm volatile(
                    "ldmatrix.sync.aligned.m8n8.x4.shared.b16 {%0,%1,%2,%3},[%4];"
                    : "=r"(a[mi][0]), "=r"(a[mi][1]), "=r"(a[mi][2]), "=r"(a[mi][3])
                    : "r"(ad));
            }
            uint32_t b[2][4];
#pragma unroll
            for (int bi = 0; bi < 2; bi++) {
                uint32_t bd = (uint32_t)__cvta_generic_to_shared(
                    &Bs[buf][(ks * 16 + (lane & 15)) * BSTR +
                             wn * 32 + bi * 16 + (lane >> 4) * 8]);
                asm volatile(
                    "ldmatrix.sync.aligned.m8n8.x4.trans.shared.b16 {%0,%1,%2,%3},[%4];"
                    : "=r"(b[bi][0]), "=r"(b[bi][1]), "=r"(b[bi][2]), "=r"(b[bi][3])
                    : "r"(bd));
            }
#pragma unroll
            for (int mi = 0; mi < 4; mi++)
#pragma unroll
                for (int ni = 0; ni < 4; ni++) {
                    uint32_t b0 = b[ni >> 1][(ni & 1) * 2];
                    uint32_t b1 = b[ni >> 1][(ni & 1) * 2 + 1];
                    asm volatile(
                        "mma.sync.aligned.m16n8k16.row.col.f32.bf16.bf16.f32 "
                        "{%0,%1,%2,%3},{%4,%5,%6,%7},{%8,%9},{%0,%1,%2,%3};"
                        : "+f"(acc[mi][ni][0]), "+f"(acc[mi][ni][1]),
                          "+f"(acc[mi][ni][2]), "+f"(acc[mi][ni][3])
                        : "r"(a[mi][0]), "r"(a[mi][1]), "r"(a[mi][2]), "r"(a[mi][3]),
                          "r"(b0), "r"(b1));
                }
        }
        __syncthreads();
    }

    // epilogue
    const int g = lane >> 2;
    const int t = lane & 3;
#pragma unroll
    for (int ni = 0; ni < 4; ni++) {
        int col = col0 + wn * 32 + ni * 8 + t * 2;
        float b0 = bias[col], b1 = bias[col + 1];
#pragma unroll
        for (int mi = 0; mi < 4; mi++) {
            int row = row0 + wm * 64 + mi * 16 + g;
            float2 o0 = { acc[mi][ni][0] + b0, acc[mi][ni][1] + b1 };
            float2 o1 = { acc[mi][ni][2] + b0, acc[mi][ni][3] + b1 };
            *(float2*)&C[(size_t)row * N + col] = o0;
            *(float2*)&C[(size_t)(row + 8) * N + col] = o1;
        }
    }
}

// ---------------- cw = softmax(query @ Wc + bc, axis=H) --------------------
__global__ __launch_bounds__(128) void cw_kernel(
    const float* __restrict__ query, const float* __restrict__ Wc,
    const float* __restrict__ bc, float* __restrict__ CW)
{
    __shared__ float qs[8][1024];
    const int tid = threadIdx.x;
    const int row0 = blockIdx.x * 8;

    for (int idx = tid; idx < 2048; idx += 128) {
        int r = idx >> 8;
        int c4 = (idx & 255) * 4;
        *(float4*)&qs[r][c4] = *(const float4*)&query[(size_t)(row0 + r) * EMB + c4];
    }
    __syncthreads();

    const int r = tid >> 4;
    const int h = tid & 15;
    const float* q = &qs[r][0];

    float a0 = 0.f, a1 = 0.f, a2 = 0.f, a3 = 0.f;
#pragma unroll 4
    for (int i = 0; i < EMB; i += 4) {
        a0 += q[i + 0] * Wc[(i + 0) * NH + h];
        a1 += q[i + 1] * Wc[(i + 1) * NH + h];
        a2 += q[i + 2] * Wc[(i + 2) * NH + h];
        a3 += q[i + 3] * Wc[(i + 3) * NH + h];
    }
    float acc = bc[h] + (a0 + a1) + (a2 + a3);

    float m = acc;
#pragma unroll
    for (int o = 8; o > 0; o >>= 1) m = fmaxf(m, __shfl_xor_sync(0xffffffffu, m, o, 16));
    float e = __expf(acc - m);
    float s = e;
#pragma unroll
    for (int o = 8; o > 0; o >>= 1) s += __shfl_xor_sync(0xffffffffu, s, o, 16);
    CW[(size_t)(row0 + r) * NH + h] = e / s;
}

// ---------------- suffix sums of V ------------------------------------------
__global__ __launch_bounds__(256) void vsuffix_kernel(
    const float* __restrict__ V, float* __restrict__ Suf)
{
    __shared__ float T[4][64];
    const int bh = blockIdx.x;
    const int b = bh >> 4;
    const int h = bh & 15;
    const int t = threadIdx.x;
    const int p = t >> 6;
    const int d = t & 63;

    const float* vb = V + (size_t)b * SEQ * EMB + h * HD + d;
    float* sufb = Suf + (size_t)bh * SEQ * HD + d;

    const int k0 = p * 256;
    float s = 0.f;
    for (int k = k0; k < k0 + 256; k++) s += vb[(size_t)k * EMB];
    T[p][d] = s;
    __syncthreads();

    float acc = 0.f;
    for (int pp = p + 1; pp < 4; pp++) acc += T[pp][d];
    for (int k = k0 + 255; k >= k0; k--) {
        sufb[(size_t)k * HD] = acc;
        acc += vb[(size_t)k * EMB];
    }
}

// ---------------- attention ------------------------------------------------
#define ROWS 16
#define KT 64
#define KV_STRIDE 68

__global__ __launch_bounds__(256) void attn_kernel(
    const float* __restrict__ Q, const float* __restrict__ Km,
    const float* __restrict__ Vm, const float* __restrict__ CW,
    const float* __restrict__ cons, const float* __restrict__ Suf,
    float* __restrict__ attn_out, float* __restrict__ ctx)
{
    extern __shared__ float sm[];
    float* esc = sm;
    float* kv = sm + ROWS * 1024;
    float* qs = kv + KT * KV_STRIDE;
    __shared__ float zinv[ROWS];

    const int tid = threadIdx.x;
    const int bh = blockIdx.y;
    const int b = bh >> 4;
    const int h = bh & 15;
    const int q0 = blockIdx.x * ROWS;
    const float INV_SCALE = 1.0f / (8.0f * sqrtf(1.61803398874989485f));

    {
        int r = tid >> 4;
        int d4 = (tid & 15) * 4;
        *(float4*)&qs[r * 64 + d4] =
            *(const float4*)&Q[((size_t)(b * SEQ + q0 + r)) * EMB + h * HD + d4];
    }

    const int ty = tid >> 4;
    const int tx = tid & 15;
    const int kmax = q0 + ROWS;

    for (int kt = 0; kt < kmax; kt += KT) {
#pragma unroll
        for (int li = 0; li < 4; li++) {
            int idx = tid + li * 256;
            int r = idx >> 4;
            int d4 = (idx & 15) * 4;
            *(float4*)&kv[r * KV_STRIDE + d4] =
                *(const float4*)&Km[((size_t)(b * SEQ + kt + r)) * EMB + h * HD + d4];
        }
        __syncthreads();

        float acc0 = 0.f, acc1 = 0.f, acc2 = 0.f, acc3 = 0.f;
#pragma unroll
        for (int d = 0; d < HD; d += 4) {
            float4 qv = *(float4*)&qs[ty * 64 + d];
            const float* k0p = &kv[(tx * 4 + 0) * KV_STRIDE + d];
            const float* k1p = &kv[(tx * 4 + 1) * KV_STRIDE + d];
            const float* k2p = &kv[(tx * 4 + 2) * KV_STRIDE + d];
            const float* k3p = &kv[(tx * 4 + 3) * KV_STRIDE + d];
            acc0 += qv.x * k0p[0] + qv.y * k0p[1] + qv.z * k0p[2] + qv.w * k0p[3];
            acc1 += qv.x * k1p[0] + qv.y * k1p[1] + qv.z * k1p[2] + qv.w * k1p[3];
            acc2 += qv.x * k2p[0] + qv.y * k2p[1] + qv.z * k2p[2] + qv.w * k2p[3];
            acc3 += qv.x * k3p[0] + qv.y * k3p[1] + qv.z * k3p[2] + qv.w * k3p[3];
        }
        esc[ty * 1024 + kt + tx * 4 + 0] = acc0 * INV_SCALE;
        esc[ty * 1024 + kt + tx * 4 + 1] = acc1 * INV_SCALE;
        esc[ty * 1024 + kt + tx * 4 + 2] = acc2 * INV_SCALE;
        esc[ty * 1024 + kt + tx * 4 + 3] = acc3 * INV_SCALE;
        __syncthreads();
    }

    {
        const int warp = tid >> 5, lane = tid & 31;
        for (int rr = 0; rr < 2; rr++) {
            int r = warp * 2 + rr;
            int q = q0 + r;
            int kc = q + 1;
            float* row = &esc[r * 1024];

            float m = -1e30f;
            for (int k = lane; k < kc; k += 32) m = fmaxf(m, row[k]);
#pragma unroll
            for (int o = 16; o > 0; o >>= 1) m = fmaxf(m, __shfl_xor_sync(0xffffffffu, m, o));

            float s = 0.f;
            for (int k = lane; k < kc; k += 32) {
                float p = __expf(row[k] - m);
                row[k] = p;
                s += p;
            }
#pragma unroll
            for (int o = 16; o > 0; o >>= 1) s += __shfl_xor_sync(0xffffffffu, s, o);

            float cb = cons[b * SEQ + q];
            float cwv = CW[(size_t)(b * SEQ + q) * NH + h];
            float fs = (1.f + cb * cwv) / s;

            float z2 = 0.f;
            for (int k = lane; k < kc; k += 32) {
                float e = __expf(row[k] * fs);
                row[k] = e;
                z2 += e;
            }
            for (int k = kc + lane; k < SEQ; k += 32) row[k] = 1.f;
#pragma unroll
            for (int o = 16; o > 0; o >>= 1) z2 += __shfl_xor_sync(0xffffffffu, z2, o);
            z2 += (float)(SEQ - kc);
            if (lane == 0) zinv[r] = 1.f / z2;
        }
    }
    __syncthreads();

    {
        const size_t abase = ((size_t)bh * SEQ + q0) * SEQ;
        for (int idx4 = tid; idx4 < ROWS * 1024 / 4; idx4 += 256) {
            int r = idx4 >> 8;
            float zi = zinv[r];
            float4 v = *(float4*)&esc[idx4 * 4];
            v.x *= zi; v.y *= zi; v.z *= zi; v.w *= zi;
            *(float4*)&attn_out[abase + (size_t)idx4 * 4] = v;
        }
    }
    __syncthreads();

    {
        int r = tid >> 4;
        int q = q0 + r;
        int j = tid & 15;
        int tile_end = ((kmax + 63) >> 6) << 6;
        float* row = &esc[r * 1024];
        for (int k = q + 1 + j; k < tile_end; k += 16) row[k] = 0.f;
    }
    __syncthreads();

    float c0 = 0.f, c1 = 0.f, c2 = 0.f, c3 = 0.f;
    for (int kt = 0; kt < kmax; kt += KT) {
#pragma unroll
        for (int li = 0; li < 4; li++) {
            int idx = tid + li * 256;
            int r = idx >> 4;
            int d4 = (idx & 15) * 4;
            *(float4*)&kv[r * KV_STRIDE + d4] =
                *(const float4*)&Vm[((size_t)(b * SEQ + kt + r)) * EMB + h * HD + d4];
        }
        __syncthreads();
#pragma unroll
        for (int kk = 0; kk < KT; kk++) {
            float w = esc[ty * 1024 + kt + kk];
            const float* vr = &kv[kk * KV_STRIDE + tx * 4];
            c0 += w * vr[0];
            c1 += w * vr[1];
            c2 += w * vr[2];
            c3 += w * vr[3];
        }
        __syncthreads();
    }
    {
        float zi = zinv[ty];
        float4 sv = *(const float4*)&Suf[((size_t)bh * SEQ + q0 + ty) * HD + tx * 4];
        float4 o;
        o.x = (c0 + sv.x) * zi; o.y = (c1 + sv.y) * zi;
        o.z = (c2 + sv.z) * zi; o.w = (c3 + sv.w) * zi;
        *(float4*)&ctx[((size_t)(b * SEQ + q0 + ty)) * EMB + h * HD + tx * 4] = o;
    }
}

// ---------------- launch ----------------------------------------------------
extern "C" void kernel_launch(void* const* d_in, const int* in_sizes, int n_in,
                              void* d_out, int out_size)
{
    const float* query = (const float*)d_in[0];
    const float* key   = (const float*)d_in[1];
    const float* value = (const float*)d_in[2];
    const float* cons  = (const float*)d_in[3];
    const float* Wq = (const float*)d_in[5];
    const float* bq = (const float*)d_in[6];
    const float* Wk = (const float*)d_in[7];
    const float* bk = (const float*)d_in[8];
    const float* Wv = (const float*)d_in[9];
    const float* bv = (const float*)d_in[10];
    const float* Wo = (const float*)d_in[11];
    const float* bo = (const float*)d_in[12];
    const float* Wc = (const float*)d_in[13];
    const float* bc = (const float*)d_in[14];

    float* qp; cudaGetSymbolAddress((void**)&qp, g_q);
    float* kp; cudaGetSymbolAddress((void**)&kp, g_k);
    float* vp; cudaGetSymbolAddress((void**)&vp, g_v);
    float* cp; cudaGetSymbolAddress((void**)&cp, g_ctx);
    float* cwp; cudaGetSymbolAddress((void**)&cwp, g_cw);
    float* sufp; cudaGetSymbolAddress((void**)&sufp, g_vsuf);
    __nv_bfloat16* ahi; cudaGetSymbolAddress((void**)&ahi, g_ahi);
    __nv_bfloat16* alo; cudaGetSymbolAddress((void**)&alo, g_alo);
    __nv_bfloat16* bhi; cudaGetSymbolAddress((void**)&bhi, g_bhi);
    __nv_bfloat16* blo; cudaGetSymbolAddress((void**)&blo, g_blo);

    float* out = (float*)d_out;
    float* attn_out = out + (size_t)BATCH * SEQ * EMB;

    const int M = BATCH * SEQ;              // 4096
    const int A4 = M * EMB / 4;             // 1048576
    const int W4 = EMB * EMB / 4;           // 262144
    dim3 gemm_grid(EMB / BN, M / BM);       // (8, 32)

    // Q projection
    split_kernel<<<(A4 + 255) / 256, 256>>>(query, ahi, alo, A4);
    split_kernel<<<(W4 + 255) / 256, 256>>>(Wq, bhi, blo, W4);
    gemm_bf16x3<<<gemm_grid, 256>>>(ahi, alo, bhi, blo, bq, qp, M, EMB, EMB);
    // K projection
    split_kernel<<<(A4 + 255) / 256, 256>>>(key, ahi, alo, A4);
    split_kernel<<<(W4 + 255) / 256, 256>>>(Wk, bhi, blo, W4);
    gemm_bf16x3<<<gemm_grid, 256>>>(ahi, alo, bhi, blo, bk, kp, M, EMB, EMB);
    // V projection
    split_kernel<<<(A4 + 255) / 256, 256>>>(value, ahi, alo, A4);
    split_kernel<<<(W4 + 255) / 256, 256>>>(Wv, bhi, blo, W4);
    gemm_bf16x3<<<gemm_grid, 256>>>(ahi, alo, bhi, blo, bv, vp, M, EMB, EMB);

    cw_kernel<<<M / 8, 128>>>(query, Wc, bc, cwp);
    vsuffix_kernel<<<BATCH * NH, 256>>>(vp, sufp);

    const int smem = (ROWS * 1024 + KT * KV_STRIDE + ROWS * 64) * sizeof(float);
    cudaFuncSetAttribute(attn_kernel, cudaFuncAttributeMaxDynamicSharedMemorySize, smem);
    dim3 attn_grid(SEQ / ROWS, BATCH * NH);
    attn_kernel<<<attn_grid, 256, smem>>>(qp, kp, vp, cwp, cons, sufp, attn_out, cp);

    // O projection
    split_kernel<<<(A4 + 255) / 256, 256>>>(cp, ahi, alo, A4);
    split_kernel<<<(W4 + 255) / 256, 256>>>(Wo, bhi, blo, W4);
    gemm_bf16x3<<<gemm_grid, 256>>>(ahi, alo, bhi, blo, bo, out, M, EMB, EMB);
}

// round 4
// speedup vs baseline: 2.7842x; 1.8870x over previous
#include <cuda_runtime.h>
#include <cuda_bf16.h>
#include <math.h>
#include <stdint.h>

#define EMB 1024
#define SEQ 1024
#define BATCH 4
#define NH 16
#define HD 64

// ---------------- scratch (device globals; no allocation allowed) ----------
__device__ float g_q[BATCH * SEQ * EMB];
__device__ float g_k[BATCH * SEQ * EMB];
__device__ float g_v[BATCH * SEQ * EMB];
__device__ float g_ctx[BATCH * SEQ * EMB];
__device__ float g_cw[BATCH * SEQ * NH];
__device__ float g_vsuf[BATCH * NH * SEQ * HD];
__device__ __nv_bfloat16 g_ahi[BATCH * SEQ * EMB];
__device__ __nv_bfloat16 g_alo[BATCH * SEQ * EMB];
__device__ __nv_bfloat16 g_bhi[EMB * EMB];
__device__ __nv_bfloat16 g_blo[EMB * EMB];

// ---------------- fp32 -> bf16 hi/lo split ---------------------------------
__global__ __launch_bounds__(256) void split_kernel(
    const float* __restrict__ X, __nv_bfloat16* __restrict__ Hi,
    __nv_bfloat16* __restrict__ Lo, int n4)
{
    int i = blockIdx.x * 256 + threadIdx.x;
    if (i >= n4) return;
    float4 x = ((const float4*)X)[i];
    __nv_bfloat16 h0 = __float2bfloat16(x.x);
    __nv_bfloat16 h1 = __float2bfloat16(x.y);
    __nv_bfloat16 h2 = __float2bfloat16(x.z);
    __nv_bfloat16 h3 = __float2bfloat16(x.w);
    __nv_bfloat162 H0; H0.x = h0; H0.y = h1;
    __nv_bfloat162 H1; H1.x = h2; H1.y = h3;
    __nv_bfloat162 L0;
    L0.x = __float2bfloat16(x.x - __bfloat162float(h0));
    L0.y = __float2bfloat16(x.y - __bfloat162float(h1));
    __nv_bfloat162 L1;
    L1.x = __float2bfloat16(x.z - __bfloat162float(h2));
    L1.y = __float2bfloat16(x.w - __bfloat162float(h3));
    ((__nv_bfloat162*)Hi)[2 * i] = H0;
    ((__nv_bfloat162*)Hi)[2 * i + 1] = H1;
    ((__nv_bfloat162*)Lo)[2 * i] = L0;
    ((__nv_bfloat162*)Lo)[2 * i + 1] = L1;
}

// ---------------- bf16x3 tensor-core GEMM ----------------------------------
#define BM 128
#define BN 128
#define BK 32
#define ASTR 40
#define BSTR 136

#define CP_ASYNC16(dst, src) \
    asm volatile("cp.async.cg.shared.global [%0], [%1], 16;\n" :: "r"(dst), "l"(src))
#define CP_COMMIT asm volatile("cp.async.commit_group;\n" ::)
#define CP_WAIT1  asm volatile("cp.async.wait_group 1;\n" ::)

__global__ __launch_bounds__(256) void gemm_bf16x3(
    const __nv_bfloat16* __restrict__ Ahi, const __nv_bfloat16* __restrict__ Alo,
    const __nv_bfloat16* __restrict__ Bhi, const __nv_bfloat16* __restrict__ Blo,
    const float* __restrict__ bias, float* __restrict__ C,
    int M, int N, int K)
{
    __shared__ __align__(16) __nv_bfloat16 As[2][BM * ASTR];
    __shared__ __align__(16) __nv_bfloat16 Bs[2][BK * BSTR];

    const int tid = threadIdx.x;
    const int lane = tid & 31;
    const int wid = tid >> 5;
    const int wm = wid & 1;
    const int wn = wid >> 1;
    const int row0 = blockIdx.y * BM;
    const int col0 = blockIdx.x * BN;

    const __nv_bfloat16* segA[3] = { Ahi, Ahi, Alo };
    const __nv_bfloat16* segB[3] = { Bhi, Blo, Bhi };

    float acc[4][4][4];
#pragma unroll
    for (int i = 0; i < 4; i++)
#pragma unroll
        for (int j = 0; j < 4; j++)
#pragma unroll
            for (int r = 0; r < 4; r++) acc[i][j][r] = 0.f;

    const int KT = K / BK;
    const int TOT = 3 * KT;

    const int a_idx = tid * 2;
    const int b_idx = tid * 2;

#define LOAD_TILE(IT, BUF) do {                                              \
    int seg_ = (IT) / KT;                                                    \
    int k0_ = ((IT) % KT) * BK;                                              \
    const __nv_bfloat16* Ag_ = segA[seg_];                                   \
    const __nv_bfloat16* Bg_ = segB[seg_];                                   \
    _Pragma("unroll")                                                        \
    for (int li = 0; li < 2; li++) {                                         \
        int idx = a_idx + li;                                                \
        int r_ = idx >> 2;                                                   \
        int c_ = (idx & 3) * 8;                                              \
        uint32_t d_ = (uint32_t)__cvta_generic_to_shared(                    \
            &As[BUF][r_ * ASTR + c_]);                                       \
        CP_ASYNC16(d_, Ag_ + (size_t)(row0 + r_) * K + k0_ + c_);            \
    }                                                                        \
    _Pragma("unroll")                                                        \
    for (int li = 0; li < 2; li++) {                                         \
        int idx = b_idx + li;                                                \
        int r_ = idx >> 4;                                                   \
        int c_ = (idx & 15) * 8;                                             \
        uint32_t d_ = (uint32_t)__cvta_generic_to_shared(                    \
            &Bs[BUF][r_ * BSTR + c_]);                                       \
        CP_ASYNC16(d_, Bg_ + (size_t)(k0_ + r_) * N + col0 + c_);            \
    }                                                                        \
} while (0)

    LOAD_TILE(0, 0);
    CP_COMMIT;

    for (int it = 0; it < TOT; it++) {
        int buf = it & 1;
        if (it + 1 < TOT) LOAD_TILE(it + 1, buf ^ 1);
        CP_COMMIT;
        CP_WAIT1;
        __syncthreads();

#pragma unroll
        for (int ks = 0; ks < 2; ks++) {
            uint32_t a[4][4];
#pragma unroll
            for (int mi = 0; mi < 4; mi++) {
                uint32_t ad = (uint32_t)__cvta_generic_to_shared(
                    &As[buf][(wm * 64 + mi * 16 + (lane & 15)) * ASTR +
                             ks * 16 + (lane >> 4) * 8]);
                asm volatile(
                    "ldmatrix.sync.aligned.m8n8.x4.shared.b16 {%0,%1,%2,%3},[%4];"
                    : "=r"(a[mi][0]), "=r"(a[mi][1]), "=r"(a[mi][2]), "=r"(a[mi][3])
                    : "r"(ad));
            }
            uint32_t b[2][4];
#pragma unroll
            for (int bi = 0; bi < 2; bi++) {
                uint32_t bd = (uint32_t)__cvta_generic_to_shared(
                    &Bs[buf][(ks * 16 + (lane & 15)) * BSTR +
                             wn * 32 + bi * 16 + (lane >> 4) * 8]);
                asm volatile(
                    "ldmatrix.sync.aligned.m8n8.x4.trans.shared.b16 {%0,%1,%2,%3},[%4];"
                    : "=r"(b[bi][0]), "=r"(b[bi][1]), "=r"(b[bi][2]), "=r"(b[bi][3])
                    : "r"(bd));
            }
#pragma unroll
            for (int mi = 0; mi < 4; mi++)
#pragma unroll
                for (int ni = 0; ni < 4; ni++) {
                    uint32_t b0 = b[ni >> 1][(ni & 1) * 2];
                    uint32_t b1 = b[ni >> 1][(ni & 1) * 2 + 1];
                    asm volatile(
                        "mma.sync.aligned.m16n8k16.row.col.f32.bf16.bf16.f32 "
                        "{%0,%1,%2,%3},{%4,%5,%6,%7},{%8,%9},{%0,%1,%2,%3};"
                        : "+f"(acc[mi][ni][0]), "+f"(acc[mi][ni][1]),
                          "+f"(acc[mi][ni][2]), "+f"(acc[mi][ni][3])
                        : "r"(a[mi][0]), "r"(a[mi][1]), "r"(a[mi][2]), "r"(a[mi][3]),
                          "r"(b0), "r"(b1));
                }
        }
        __syncthreads();
    }

    const int g = lane >> 2;
    const int t = lane & 3;
#pragma unroll
    for (int ni = 0; ni < 4; ni++) {
        int col = col0 + wn * 32 + ni * 8 + t * 2;
        float b0 = bias[col], b1 = bias[col + 1];
#pragma unroll
        for (int mi = 0; mi < 4; mi++) {
            int row = row0 + wm * 64 + mi * 16 + g;
            float2 o0 = { acc[mi][ni][0] + b0, acc[mi][ni][1] + b1 };
            float2 o1 = { acc[mi][ni][2] + b0, acc[mi][ni][3] + b1 };
            *(float2*)&C[(size_t)row * N + col] = o0;
            *(float2*)&C[(size_t)(row + 8) * N + col] = o1;
        }
    }
}

// ---------------- cw = softmax(query @ Wc + bc, axis=H) --------------------
__global__ __launch_bounds__(128) void cw_kernel(
    const float* __restrict__ query, const float* __restrict__ Wc,
    const float* __restrict__ bc, float* __restrict__ CW)
{
    __shared__ float qs[8][1024];
    const int tid = threadIdx.x;
    const int row0 = blockIdx.x * 8;

    for (int idx = tid; idx < 2048; idx += 128) {
        int r = idx >> 8;
        int c4 = (idx & 255) * 4;
        *(float4*)&qs[r][c4] = *(const float4*)&query[(size_t)(row0 + r) * EMB + c4];
    }
    __syncthreads();

    const int r = tid >> 4;
    const int h = tid & 15;
    const float* q = &qs[r][0];

    float a0 = 0.f, a1 = 0.f, a2 = 0.f, a3 = 0.f;
#pragma unroll 4
    for (int i = 0; i < EMB; i += 4) {
        a0 += q[i + 0] * Wc[(i + 0) * NH + h];
        a1 += q[i + 1] * Wc[(i + 1) * NH + h];
        a2 += q[i + 2] * Wc[(i + 2) * NH + h];
        a3 += q[i + 3] * Wc[(i + 3) * NH + h];
    }
    float acc = bc[h] + (a0 + a1) + (a2 + a3);

    float m = acc;
#pragma unroll
    for (int o = 8; o > 0; o >>= 1) m = fmaxf(m, __shfl_xor_sync(0xffffffffu, m, o, 16));
    float e = __expf(acc - m);
    float s = e;
#pragma unroll
    for (int o = 8; o > 0; o >>= 1) s += __shfl_xor_sync(0xffffffffu, s, o, 16);
    CW[(size_t)(row0 + r) * NH + h] = e / s;
}

// ---------------- suffix sums of V ------------------------------------------
__global__ __launch_bounds__(256) void vsuffix_kernel(
    const float* __restrict__ V, float* __restrict__ Suf)
{
    __shared__ float T[4][64];
    const int bh = blockIdx.x;
    const int b = bh >> 4;
    const int h = bh & 15;
    const int t = threadIdx.x;
    const int p = t >> 6;
    const int d = t & 63;

    const float* vb = V + (size_t)b * SEQ * EMB + h * HD + d;
    float* sufb = Suf + (size_t)bh * SEQ * HD + d;

    const int k0 = p * 256;
    float s = 0.f;
    for (int k = k0; k < k0 + 256; k++) s += vb[(size_t)k * EMB];
    T[p][d] = s;
    __syncthreads();

    float acc = 0.f;
    for (int pp = p + 1; pp < 4; pp++) acc += T[pp][d];
    for (int k = k0 + 255; k >= k0; k--) {
        sufb[(size_t)k * HD] = acc;
        acc += vb[(size_t)k * EMB];
    }
}

// ---------------- attention ------------------------------------------------
// Block: one (b,h), 16 query rows, 256 threads, 2 blocks/SM.
// smem: esc[16][ESTR] | kv[128][68] | qs[16][64]
#define ROWS 16
#define KT2 128
#define KV_STRIDE 68
#define ESTR 1044   // 1044 % 8 == 4 -> row groups 4 apart land on different banks

__global__ __launch_bounds__(256, 2) void attn_kernel(
    const float* __restrict__ Q, const float* __restrict__ Km,
    const float* __restrict__ Vm, const float* __restrict__ CW,
    const float* __restrict__ cons, const float* __restrict__ Suf,
    float* __restrict__ attn_out, float* __restrict__ ctx)
{
    extern __shared__ float sm[];
    float* esc = sm;                                 // ROWS*ESTR
    float* kv = sm + ROWS * ESTR;                    // KT2*KV_STRIDE
    float* qs = kv + KT2 * KV_STRIDE;                // ROWS*64
    __shared__ float zinv[ROWS];

    const int tid = threadIdx.x;
    const int bh = blockIdx.y;
    const int b = bh >> 4;
    const int h = bh & 15;
    const int q0 = blockIdx.x * ROWS;
    const float INV_SCALE = 1.0f / (8.0f * sqrtf(1.61803398874989485f));

    // load q rows: 16 rows x 64 d
    {
        int r = tid >> 4;
        int d4 = (tid & 15) * 4;
        *(float4*)&qs[r * 64 + d4] =
            *(const float4*)&Q[((size_t)(b * SEQ + q0 + r)) * EMB + h * HD + d4];
    }

    const int kmax = q0 + ROWS;

    // ---- scores thread map: h2 | rg | ds | tx -----------------------------
    const int h2 = tid >> 7;            // k-half of the 128 pair (uniform per warp)
    const int rg = (tid >> 5) & 3;      // row group: rows rg*4 .. rg*4+3
    const int lane = tid & 31;
    const int ds = lane >> 4;           // d parity
    const int tx = lane & 15;           // k sub-index: k = h2*64 + tx + 16*j

    // ---- phase 1: raw scores for k < kmax (pairs of 64-k tiles) -----------
    for (int kt = 0; kt < kmax; kt += KT2) {
        // stage K pair: 128 rows x 64 floats = 2048 float4
#pragma unroll
        for (int li = 0; li < 8; li++) {
            int idx = tid + li * 256;
            int r = idx >> 4;
            int d4 = (idx & 15) * 4;
            *(float4*)&kv[r * KV_STRIDE + d4] =
                *(const float4*)&Km[((size_t)(b * SEQ + kt + r)) * EMB + h * HD + d4];
        }
        __syncthreads();

        const bool valid = (kt + h2 * 64) < kmax;
        float acc[4][4];
#pragma unroll
        for (int i = 0; i < 4; i++)
#pragma unroll
            for (int j = 0; j < 4; j++) acc[i][j] = 0.f;

        if (valid) {
            const float* qb = &qs[rg * 4 * 64 + ds];
            const float* kb = &kv[(h2 * 64 + tx) * KV_STRIDE + ds];
#pragma unroll 4
            for (int t = 0; t < 32; t++) {
                int d = 2 * t;          // actual d = 2t + ds via base offset
                float qv[4], kvv[4];
#pragma unroll
                for (int i = 0; i < 4; i++) qv[i] = qb[i * 64 + d];
#pragma unroll
                for (int j = 0; j < 4; j++) kvv[j] = kb[j * 16 * KV_STRIDE + d];
#pragma unroll
                for (int i = 0; i < 4; i++)
#pragma unroll
                    for (int j = 0; j < 4; j++) acc[i][j] += qv[i] * kvv[j];
            }
        }
        // reduce across d parity
#pragma unroll
        for (int i = 0; i < 4; i++)
#pragma unroll
            for (int j = 0; j < 4; j++)
                acc[i][j] += __shfl_xor_sync(0xffffffffu, acc[i][j], 16);
        if (valid && ds == 0) {
#pragma unroll
            for (int i = 0; i < 4; i++)
#pragma unroll
                for (int j = 0; j < 4; j++)
                    esc[(rg * 4 + i) * ESTR + kt + h2 * 64 + tx + 16 * j] =
                        acc[i][j] * INV_SCALE;
        }
        __syncthreads();
    }

    // ---- phase 2: softmax1 -> rescale -> softmax2 numerators --------------
    {
        const int warp = tid >> 5, ln = tid & 31;
        for (int rr = 0; rr < 2; rr++) {
            int r = warp * 2 + rr;
            int q = q0 + r;
            int kc = q + 1;
            float* row = &esc[r * ESTR];

            float m = -1e30f;
            for (int k = ln; k < kc; k += 32) m = fmaxf(m, row[k]);
#pragma unroll
            for (int o = 16; o > 0; o >>= 1) m = fmaxf(m, __shfl_xor_sync(0xffffffffu, m, o));

            float s = 0.f;
            for (int k = ln; k < kc; k += 32) {
                float p = __expf(row[k] - m);
                row[k] = p;
                s += p;
            }
#pragma unroll
            for (int o = 16; o > 0; o >>= 1) s += __shfl_xor_sync(0xffffffffu, s, o);

            float cb = cons[b * SEQ + q];
            float cwv = CW[(size_t)(b * SEQ + q) * NH + h];
            float fs = (1.f + cb * cwv) / s;

            float z2 = 0.f;
            for (int k = ln; k < kc; k += 32) {
                float e = __expf(row[k] * fs);
                row[k] = e;
                z2 += e;
            }
            // masked region: attn1=0 -> exp(0)=1 (2nd softmax is unmasked)
            for (int k = kc + ln; k < SEQ; k += 32) row[k] = 1.f;
#pragma unroll
            for (int o = 16; o > 0; o >>= 1) z2 += __shfl_xor_sync(0xffffffffu, z2, o);
            z2 += (float)(SEQ - kc);
            if (ln == 0) zinv[r] = 1.f / z2;
        }
    }
    __syncthreads();

    // ---- write final attn to output ----------------------------------------
    {
        const size_t abase = ((size_t)bh * SEQ + q0) * SEQ;
        for (int idx4 = tid; idx4 < ROWS * 256; idx4 += 256) {
            int r = idx4 >> 8;
            int c4 = (idx4 & 255) * 4;
            float zi = zinv[r];
            float4 v = *(float4*)&esc[r * ESTR + c4];
            v.x *= zi; v.y *= zi; v.z *= zi; v.w *= zi;
            *(float4*)&attn_out[abase + (size_t)r * SEQ + c4] = v;
        }
    }
    __syncthreads();

    // ---- zero weights for k > q up to pair boundary ------------------------
    {
        int r = tid >> 4;
        int q = q0 + r;
        int j = tid & 15;
        int tile_end = ((kmax + KT2 - 1) / KT2) * KT2;
        if (tile_end > SEQ) tile_end = SEQ;
        float* row = &esc[r * ESTR];
        for (int k = q + 1 + j; k < tile_end; k += 16) row[k] = 0.f;
    }
    __syncthreads();

    // ---- ctx = (sum_{k<=q} e_k * v_k + SufV[q]) * zinv ---------------------
    // thread map: ks = tid>>6 (kk quarter of 128), rg = (tid>>4)&3, txd = tid&15
    const int ks = tid >> 6;
    const int crg = (tid >> 4) & 3;
    const int txd = tid & 15;

    float c[4][4];
#pragma unroll
    for (int i = 0; i < 4; i++)
#pragma unroll
        for (int j = 0; j < 4; j++) c[i][j] = 0.f;

    for (int kt = 0; kt < kmax; kt += KT2) {
#pragma unroll
        for (int li = 0; li < 8; li++) {
            int idx = tid + li * 256;
            int r = idx >> 4;
            int d4 = (idx & 15) * 4;
            *(float4*)&kv[r * KV_STRIDE + d4] =
                *(const float4*)&Vm[((size_t)(b * SEQ + kt + r)) * EMB + h * HD + d4];
        }
        __syncthreads();

        const float* eb = &esc[crg * 4 * ESTR + kt + ks * 32];
        const float* vb = &kv[(ks * 32) * KV_STRIDE + txd * 4];
#pragma unroll 4
        for (int kk = 0; kk < 32; kk++) {
            float w[4];
#pragma unroll
            for (int i = 0; i < 4; i++) w[i] = eb[i * ESTR + kk];
            float4 vv = *(const float4*)&vb[kk * KV_STRIDE];
#pragma unroll
            for (int i = 0; i < 4; i++) {
                c[i][0] += w[i] * vv.x;
                c[i][1] += w[i] * vv.y;
                c[i][2] += w[i] * vv.z;
                c[i][3] += w[i] * vv.w;
            }
        }
        __syncthreads();
    }

    // ---- reduce 4 kk-quarters (reuse kv as scratch) -------------------------
    float* red = kv;   // 3*64*16 floats = 12KB < kv size
    const int rem64 = tid & 63;
    if (ks > 0) {
#pragma unroll
        for (int i = 0; i < 4; i++)
            *(float4*)&red[((ks - 1) * 64 + rem64) * 16 + i * 4] = *(float4*)&c[i][0];
    }
    __syncthreads();
    if (ks == 0) {
#pragma unroll
        for (int s = 0; s < 3; s++)
#pragma unroll
            for (int i = 0; i < 4; i++) {
                float4 p = *(float4*)&red[(s * 64 + rem64) * 16 + i * 4];
                c[i][0] += p.x; c[i][1] += p.y; c[i][2] += p.z; c[i][3] += p.w;
            }
#pragma unroll
        for (int i = 0; i < 4; i++) {
            int row = crg * 4 + i;
            float zi = zinv[row];
            float4 sv = *(const float4*)&Suf[((size_t)bh * SEQ + q0 + row) * HD + txd * 4];
            float4 o;
            o.x = (c[i][0] + sv.x) * zi;
            o.y = (c[i][1] + sv.y) * zi;
            o.z = (c[i][2] + sv.z) * zi;
            o.w = (c[i][3] + sv.w) * zi;
            *(float4*)&ctx[((size_t)(b * SEQ + q0 + row)) * EMB + h * HD + txd * 4] = o;
        }
    }
}

// ---------------- launch ----------------------------------------------------
extern "C" void kernel_launch(void* const* d_in, const int* in_sizes, int n_in,
                              void* d_out, int out_size)
{
    const float* query = (const float*)d_in[0];
    const float* key   = (const float*)d_in[1];
    const float* value = (const float*)d_in[2];
    const float* cons  = (const float*)d_in[3];
    const float* Wq = (const float*)d_in[5];
    const float* bq = (const float*)d_in[6];
    const float* Wk = (const float*)d_in[7];
    const float* bk = (const float*)d_in[8];
    const float* Wv = (const float*)d_in[9];
    const float* bv = (const float*)d_in[10];
    const float* Wo = (const float*)d_in[11];
    const float* bo = (const float*)d_in[12];
    const float* Wc = (const float*)d_in[13];
    const float* bc = (const float*)d_in[14];

    float* qp; cudaGetSymbolAddress((void**)&qp, g_q);
    float* kp; cudaGetSymbolAddress((void**)&kp, g_k);
    float* vp; cudaGetSymbolAddress((void**)&vp, g_v);
    float* cp; cudaGetSymbolAddress((void**)&cp, g_ctx);
    float* cwp; cudaGetSymbolAddress((void**)&cwp, g_cw);
    float* sufp; cudaGetSymbolAddress((void**)&sufp, g_vsuf);
    __nv_bfloat16* ahi; cudaGetSymbolAddress((void**)&ahi, g_ahi);
    __nv_bfloat16* alo; cudaGetSymbolAddress((void**)&alo, g_alo);
    __nv_bfloat16* bhi; cudaGetSymbolAddress((void**)&bhi, g_bhi);
    __nv_bfloat16* blo; cudaGetSymbolAddress((void**)&blo, g_blo);

    float* out = (float*)d_out;
    float* attn_out = out + (size_t)BATCH * SEQ * EMB;

    const int M = BATCH * SEQ;
    const int A4 = M * EMB / 4;
    const int W4 = EMB * EMB / 4;
    dim3 gemm_grid(EMB / BN, M / BM);

    split_kernel<<<(A4 + 255) / 256, 256>>>(query, ahi, alo, A4);
    split_kernel<<<(W4 + 255) / 256, 256>>>(Wq, bhi, blo, W4);
    gemm_bf16x3<<<gemm_grid, 256>>>(ahi, alo, bhi, blo, bq, qp, M, EMB, EMB);
    split_kernel<<<(A4 + 255) / 256, 256>>>(key, ahi, alo, A4);
    split_kernel<<<(W4 + 255) / 256, 256>>>(Wk, bhi, blo, W4);
    gemm_bf16x3<<<gemm_grid, 256>>>(ahi, alo, bhi, blo, bk, kp, M, EMB, EMB);
    split_kernel<<<(A4 + 255) / 256, 256>>>(value, ahi, alo, A4);
    split_kernel<<<(W4 + 255) / 256, 256>>>(Wv, bhi, blo, W4);
    gemm_bf16x3<<<gemm_grid, 256>>>(ahi, alo, bhi, blo, bv, vp, M, EMB, EMB);

    cw_kernel<<<M / 8, 128>>>(query, Wc, bc, cwp);
    vsuffix_kernel<<<BATCH * NH, 256>>>(vp, sufp);

    const int smem = (ROWS * ESTR + KT2 * KV_STRIDE + ROWS * 64) * sizeof(float);
    cudaFuncSetAttribute(attn_kernel, cudaFuncAttributeMaxDynamicSharedMemorySize, smem);
    dim3 attn_grid(SEQ / ROWS, BATCH * NH);
    attn_kernel<<<attn_grid, 256, smem>>>(qp, kp, vp, cwp, cons, sufp, attn_out, cp);

    split_kernel<<<(A4 + 255) / 256, 256>>>(cp, ahi, alo, A4);
    split_kernel<<<(W4 + 255) / 256, 256>>>(Wo, bhi, blo, W4);
    gemm_bf16x3<<<gemm_grid, 256>>>(ahi, alo, bhi, blo, bo, out, M, EMB, EMB);
}

// round 5
// speedup vs baseline: 2.9249x; 1.0505x over previous
#include <cuda_runtime.h>
#include <cuda_bf16.h>
#include <math.h>
#include <stdint.h>

#define EMB 1024
#define SEQ 1024
#define BATCH 4
#define NH 16
#define HD 64

// ---------------- scratch (device globals; no allocation allowed) ----------
__device__ float g_q[BATCH * SEQ * EMB];
__device__ float g_k[BATCH * SEQ * EMB];
__device__ float g_v[BATCH * SEQ * EMB];
__device__ float g_ctx[BATCH * SEQ * EMB];
__device__ float g_cw[BATCH * SEQ * NH];
__device__ float g_vsuf[BATCH * NH * SEQ * HD];
__device__ __nv_bfloat16 g_ahi[3][BATCH * SEQ * EMB];
__device__ __nv_bfloat16 g_alo[3][BATCH * SEQ * EMB];
__device__ __nv_bfloat16 g_whi[4][EMB * EMB];
__device__ __nv_bfloat16 g_wlo[4][EMB * EMB];

// ---------------- fp32 -> bf16 hi/lo split (single tensor) -----------------
__device__ __forceinline__ void split4(
    const float* __restrict__ X, __nv_bfloat16* __restrict__ Hi,
    __nv_bfloat16* __restrict__ Lo, int i)
{
    float4 x = ((const float4*)X)[i];
    __nv_bfloat16 h0 = __float2bfloat16(x.x);
    __nv_bfloat16 h1 = __float2bfloat16(x.y);
    __nv_bfloat16 h2 = __float2bfloat16(x.z);
    __nv_bfloat16 h3 = __float2bfloat16(x.w);
    __nv_bfloat162 H0; H0.x = h0; H0.y = h1;
    __nv_bfloat162 H1; H1.x = h2; H1.y = h3;
    __nv_bfloat162 L0;
    L0.x = __float2bfloat16(x.x - __bfloat162float(h0));
    L0.y = __float2bfloat16(x.y - __bfloat162float(h1));
    __nv_bfloat162 L1;
    L1.x = __float2bfloat16(x.z - __bfloat162float(h2));
    L1.y = __float2bfloat16(x.w - __bfloat162float(h3));
    ((__nv_bfloat162*)Hi)[2 * i] = H0;
    ((__nv_bfloat162*)Hi)[2 * i + 1] = H1;
    ((__nv_bfloat162*)Lo)[2 * i] = L0;
    ((__nv_bfloat162*)Lo)[2 * i + 1] = L1;
}

__global__ __launch_bounds__(256) void split_kernel(
    const float* __restrict__ X, __nv_bfloat16* __restrict__ Hi,
    __nv_bfloat16* __restrict__ Lo, int n4)
{
    int i = blockIdx.x * 256 + threadIdx.x;
    if (i < n4) split4(X, Hi, Lo, i);
}

// 3 activations in one launch (query/key/value)
__global__ __launch_bounds__(256) void split_act3_kernel(
    const float* __restrict__ X0, const float* __restrict__ X1,
    const float* __restrict__ X2, __nv_bfloat16* __restrict__ Hi,
    __nv_bfloat16* __restrict__ Lo, int n4)
{
    int i = blockIdx.x * 256 + threadIdx.x;
    if (i >= n4) return;
    int s = blockIdx.y;
    const float* X = (s == 0) ? X0 : (s == 1) ? X1 : X2;
    split4(X, Hi + (size_t)s * BATCH * SEQ * EMB,
           Lo + (size_t)s * BATCH * SEQ * EMB, i);
}

// 4 weights in one launch
__global__ __launch_bounds__(256) void split_w4_kernel(
    const float* __restrict__ W0, const float* __restrict__ W1,
    const float* __restrict__ W2, const float* __restrict__ W3,
    __nv_bfloat16* __restrict__ Hi, __nv_bfloat16* __restrict__ Lo, int n4)
{
    int i = blockIdx.x * 256 + threadIdx.x;
    if (i >= n4) return;
    int s = blockIdx.y;
    const float* W = (s == 0) ? W0 : (s == 1) ? W1 : (s == 2) ? W2 : W3;
    split4(W, Hi + (size_t)s * EMB * EMB, Lo + (size_t)s * EMB * EMB, i);
}

// ---------------- fused bf16x3 tensor-core GEMM -----------------------------
// C = Ahi@Bhi + Ahi@Blo + Alo@Bhi + bias.  One K pass, 3-stage cp.async ring.
// BM=128, BN=128, BK=32, 256 threads (8 warps 2x4), warp tile 64x32.
#define BM 128
#define BN 128
#define BK 32
#define ASTR 40
#define BSTR 136
#define STAGES 3
#define A_ELEM (BM * ASTR)          // bf16 per A matrix per stage
#define B_ELEM (BK * BSTR)
#define STAGE_ELEM (2 * A_ELEM + 2 * B_ELEM)

#define CP_ASYNC16(dst, src) \
    asm volatile("cp.async.cg.shared.global [%0], [%1], 16;\n" :: "r"(dst), "l"(src))
#define CP_COMMIT asm volatile("cp.async.commit_group;\n" ::)
#define CP_WAITG(n) asm volatile("cp.async.wait_group %0;\n" :: "n"(n))

__global__ __launch_bounds__(256, 1) void gemm_bf16x3f(
    const __nv_bfloat16* __restrict__ Ahi, const __nv_bfloat16* __restrict__ Alo,
    const __nv_bfloat16* __restrict__ Bhi, const __nv_bfloat16* __restrict__ Blo,
    const float* __restrict__ bias, float* __restrict__ C,
    int M, int N, int K)
{
    extern __shared__ __align__(16) __nv_bfloat16 smem[];

    const int tid = threadIdx.x;
    const int lane = tid & 31;
    const int wid = tid >> 5;
    const int wm = wid & 1;
    const int wn = wid >> 1;
    const int row0 = blockIdx.y * BM;
    const int col0 = blockIdx.x * BN;

    float acc[4][4][4];
#pragma unroll
    for (int i = 0; i < 4; i++)
#pragma unroll
        for (int j = 0; j < 4; j++)
#pragma unroll
            for (int r = 0; r < 4; r++) acc[i][j][r] = 0.f;

    const int TOT = K / BK;   // 32

    // per-thread load coords (2 x 16B chunks per matrix)
    const int a_r0 = (tid * 2) >> 2, a_c0 = ((tid * 2) & 3) * 8;
    const int a_r1 = (tid * 2 + 1) >> 2, a_c1 = ((tid * 2 + 1) & 3) * 8;
    const int b_r0 = (tid * 2) >> 4, b_c0 = ((tid * 2) & 15) * 8;
    const int b_r1 = (tid * 2 + 1) >> 4, b_c1 = ((tid * 2 + 1) & 15) * 8;

#define LOAD_STAGE(IT, BUF) do {                                               \
    int k0_ = (IT) * BK;                                                       \
    __nv_bfloat16* sa_hi = smem + (BUF) * STAGE_ELEM;                          \
    __nv_bfloat16* sa_lo = sa_hi + A_ELEM;                                     \
    __nv_bfloat16* sb_hi = sa_lo + A_ELEM;                                     \
    __nv_bfloat16* sb_lo = sb_hi + B_ELEM;                                     \
    CP_ASYNC16((uint32_t)__cvta_generic_to_shared(&sa_hi[a_r0 * ASTR + a_c0]), \
               Ahi + (size_t)(row0 + a_r0) * K + k0_ + a_c0);                  \
    CP_ASYNC16((uint32_t)__cvta_generic_to_shared(&sa_hi[a_r1 * ASTR + a_c1]), \
               Ahi + (size_t)(row0 + a_r1) * K + k0_ + a_c1);                  \
    CP_ASYNC16((uint32_t)__cvta_generic_to_shared(&sa_lo[a_r0 * ASTR + a_c0]), \
               Alo + (size_t)(row0 + a_r0) * K + k0_ + a_c0);                  \
    CP_ASYNC16((uint32_t)__cvta_generic_to_shared(&sa_lo[a_r1 * ASTR + a_c1]), \
               Alo + (size_t)(row0 + a_r1) * K + k0_ + a_c1);                  \
    CP_ASYNC16((uint32_t)__cvta_generic_to_shared(&sb_hi[b_r0 * BSTR + b_c0]), \
               Bhi + (size_t)(k0_ + b_r0) * N + col0 + b_c0);                  \
    CP_ASYNC16((uint32_t)__cvta_generic_to_shared(&sb_hi[b_r1 * BSTR + b_c1]), \
               Bhi + (size_t)(k0_ + b_r1) * N + col0 + b_c1);                  \
    CP_ASYNC16((uint32_t)__cvta_generic_to_shared(&sb_lo[b_r0 * BSTR + b_c0]), \
               Blo + (size_t)(k0_ + b_r0) * N + col0 + b_c0);                  \
    CP_ASYNC16((uint32_t)__cvta_generic_to_shared(&sb_lo[b_r1 * BSTR + b_c1]), \
               Blo + (size_t)(k0_ + b_r1) * N + col0 + b_c1);                  \
} while (0)

#define MMA(ACC, A, B0, B1)                                                    \
    asm volatile(                                                              \
        "mma.sync.aligned.m16n8k16.row.col.f32.bf16.bf16.f32 "                 \
        "{%0,%1,%2,%3},{%4,%5,%6,%7},{%8,%9},{%0,%1,%2,%3};"                   \
        : "+f"((ACC)[0]), "+f"((ACC)[1]), "+f"((ACC)[2]), "+f"((ACC)[3])       \
        : "r"((A)[0]), "r"((A)[1]), "r"((A)[2]), "r"((A)[3]),                  \
          "r"(B0), "r"(B1))

    // prologue: stages 0..STAGES-2
    LOAD_STAGE(0, 0); CP_COMMIT;
    LOAD_STAGE(1, 1); CP_COMMIT;

    for (int it = 0; it < TOT; it++) {
        const int buf = it % STAGES;
        CP_WAITG(STAGES - 2);
        __syncthreads();

        if (it + STAGES - 1 < TOT) {
            LOAD_STAGE(it + STAGES - 1, (it + STAGES - 1) % STAGES);
        }
        CP_COMMIT;

        const __nv_bfloat16* sa_hi = smem + buf * STAGE_ELEM;
        const __nv_bfloat16* sa_lo = sa_hi + A_ELEM;
        const __nv_bfloat16* sb_hi = sa_lo + A_ELEM;
        const __nv_bfloat16* sb_lo = sb_hi + B_ELEM;

#pragma unroll
        for (int ks = 0; ks < 2; ks++) {
            uint32_t ahi[4][4], alo[4][4], bhi[2][4], blo[2][4];
#pragma unroll
            for (int mi = 0; mi < 4; mi++) {
                int roff = (wm * 64 + mi * 16 + (lane & 15)) * ASTR +
                           ks * 16 + (lane >> 4) * 8;
                uint32_t ad = (uint32_t)__cvta_generic_to_shared(&sa_hi[roff]);
                asm volatile(
                    "ldmatrix.sync.aligned.m8n8.x4.shared.b16 {%0,%1,%2,%3},[%4];"
                    : "=r"(ahi[mi][0]), "=r"(ahi[mi][1]),
                      "=r"(ahi[mi][2]), "=r"(ahi[mi][3]) : "r"(ad));
                uint32_t ad2 = (uint32_t)__cvta_generic_to_shared(&sa_lo[roff]);
                asm volatile(
                    "ldmatrix.sync.aligned.m8n8.x4.shared.b16 {%0,%1,%2,%3},[%4];"
                    : "=r"(alo[mi][0]), "=r"(alo[mi][1]),
                      "=r"(alo[mi][2]), "=r"(alo[mi][3]) : "r"(ad2));
            }
#pragma unroll
            for (int bi = 0; bi < 2; bi++) {
                int boff = (ks * 16 + (lane & 15)) * BSTR +
                           wn * 32 + bi * 16 + (lane >> 4) * 8;
                uint32_t bd = (uint32_t)__cvta_generic_to_shared(&sb_hi[boff]);
                asm volatile(
                    "ldmatrix.sync.aligned.m8n8.x4.trans.shared.b16 {%0,%1,%2,%3},[%4];"
                    : "=r"(bhi[bi][0]), "=r"(bhi[bi][1]),
                      "=r"(bhi[bi][2]), "=r"(bhi[bi][3]) : "r"(bd));
                uint32_t bd2 = (uint32_t)__cvta_generic_to_shared(&sb_lo[boff]);
                asm volatile(
                    "ldmatrix.sync.aligned.m8n8.x4.trans.shared.b16 {%0,%1,%2,%3},[%4];"
                    : "=r"(blo[bi][0]), "=r"(blo[bi][1]),
                      "=r"(blo[bi][2]), "=r"(blo[bi][3]) : "r"(bd2));
            }
#pragma unroll
            for (int mi = 0; mi < 4; mi++)
#pragma unroll
                for (int ni = 0; ni < 4; ni++) {
                    int g = ni >> 1, p = (ni & 1) * 2;
                    MMA(acc[mi][ni], ahi[mi], bhi[g][p], bhi[g][p + 1]);
                    MMA(acc[mi][ni], ahi[mi], blo[g][p], blo[g][p + 1]);
                    MMA(acc[mi][ni], alo[mi], bhi[g][p], bhi[g][p + 1]);
                }
        }
    }

    // epilogue
    const int g = lane >> 2;
    const int t = lane & 3;
#pragma unroll
    for (int ni = 0; ni < 4; ni++) {
        int col = col0 + wn * 32 + ni * 8 + t * 2;
        float b0 = bias[col], b1 = bias[col + 1];
#pragma unroll
        for (int mi = 0; mi < 4; mi++) {
            int row = row0 + wm * 64 + mi * 16 + g;
            float2 o0 = { acc[mi][ni][0] + b0, acc[mi][ni][1] + b1 };
            float2 o1 = { acc[mi][ni][2] + b0, acc[mi][ni][3] + b1 };
            *(float2*)&C[(size_t)row * N + col] = o0;
            *(float2*)&C[(size_t)(row + 8) * N + col] = o1;
        }
    }
}

// ---------------- cw = softmax(query @ Wc + bc, axis=H) --------------------
__global__ __launch_bounds__(128) void cw_kernel(
    const float* __restrict__ query, const float* __restrict__ Wc,
    const float* __restrict__ bc, float* __restrict__ CW)
{
    __shared__ float qs[8][1024];
    const int tid = threadIdx.x;
    const int row0 = blockIdx.x * 8;

    for (int idx = tid; idx < 2048; idx += 128) {
        int r = idx >> 8;
        int c4 = (idx & 255) * 4;
        *(float4*)&qs[r][c4] = *(const float4*)&query[(size_t)(row0 + r) * EMB + c4];
    }
    __syncthreads();

    const int r = tid >> 4;
    const int h = tid & 15;
    const float* q = &qs[r][0];

    float a0 = 0.f, a1 = 0.f, a2 = 0.f, a3 = 0.f;
#pragma unroll 4
    for (int i = 0; i < EMB; i += 4) {
        a0 += q[i + 0] * Wc[(i + 0) * NH + h];
        a1 += q[i + 1] * Wc[(i + 1) * NH + h];
        a2 += q[i + 2] * Wc[(i + 2) * NH + h];
        a3 += q[i + 3] * Wc[(i + 3) * NH + h];
    }
    float acc = bc[h] + (a0 + a1) + (a2 + a3);

    float m = acc;
#pragma unroll
    for (int o = 8; o > 0; o >>= 1) m = fmaxf(m, __shfl_xor_sync(0xffffffffu, m, o, 16));
    float e = __expf(acc - m);
    float s = e;
#pragma unroll
    for (int o = 8; o > 0; o >>= 1) s += __shfl_xor_sync(0xffffffffu, s, o, 16);
    CW[(size_t)(row0 + r) * NH + h] = e / s;
}

// ---------------- suffix sums of V ------------------------------------------
__global__ __launch_bounds__(256) void vsuffix_kernel(
    const float* __restrict__ V, float* __restrict__ Suf)
{
    __shared__ float T[4][64];
    const int bh = blockIdx.x;
    const int b = bh >> 4;
    const int h = bh & 15;
    const int t = threadIdx.x;
    const int p = t >> 6;
    const int d = t & 63;

    const float* vb = V + (size_t)b * SEQ * EMB + h * HD + d;
    float* sufb = Suf + (size_t)bh * SEQ * HD + d;

    const int k0 = p * 256;
    float s = 0.f;
    for (int k = k0; k < k0 + 256; k++) s += vb[(size_t)k * EMB];
    T[p][d] = s;
    __syncthreads();

    float acc = 0.f;
    for (int pp = p + 1; pp < 4; pp++) acc += T[pp][d];
    for (int k = k0 + 255; k >= k0; k--) {
        sufb[(size_t)k * HD] = acc;
        acc += vb[(size_t)k * EMB];
    }
}

// ---------------- attention (round-4 layout, unchanged) ---------------------
#define ROWS 16
#define KT2 128
#define KV_STRIDE 68
#define ESTR 1044

__global__ __launch_bounds__(256, 2) void attn_kernel(
    const float* __restrict__ Q, const float* __restrict__ Km,
    const float* __restrict__ Vm, const float* __restrict__ CW,
    const float* __restrict__ cons, const float* __restrict__ Suf,
    float* __restrict__ attn_out, float* __restrict__ ctx)
{
    extern __shared__ float sm[];
    float* esc = sm;
    float* kv = sm + ROWS * ESTR;
    float* qs = kv + KT2 * KV_STRIDE;
    __shared__ float zinv[ROWS];

    const int tid = threadIdx.x;
    const int bh = blockIdx.y;
    const int b = bh >> 4;
    const int h = bh & 15;
    const int q0 = blockIdx.x * ROWS;
    const float INV_SCALE = 1.0f / (8.0f * sqrtf(1.61803398874989485f));

    {
        int r = tid >> 4;
        int d4 = (tid & 15) * 4;
        *(float4*)&qs[r * 64 + d4] =
            *(const float4*)&Q[((size_t)(b * SEQ + q0 + r)) * EMB + h * HD + d4];
    }

    const int kmax = q0 + ROWS;

    const int h2 = tid >> 7;
    const int rg = (tid >> 5) & 3;
    const int lane = tid & 31;
    const int ds = lane >> 4;
    const int tx = lane & 15;

    for (int kt = 0; kt < kmax; kt += KT2) {
#pragma unroll
        for (int li = 0; li < 8; li++) {
            int idx = tid + li * 256;
            int r = idx >> 4;
            int d4 = (idx & 15) * 4;
            *(float4*)&kv[r * KV_STRIDE + d4] =
                *(const float4*)&Km[((size_t)(b * SEQ + kt + r)) * EMB + h * HD + d4];
        }
        __syncthreads();

        const bool valid = (kt + h2 * 64) < kmax;
        float acc[4][4];
#pragma unroll
        for (int i = 0; i < 4; i++)
#pragma unroll
            for (int j = 0; j < 4; j++) acc[i][j] = 0.f;

        if (valid) {
            const float* qb = &qs[rg * 4 * 64 + ds];
            const float* kb = &kv[(h2 * 64 + tx) * KV_STRIDE + ds];
#pragma unroll 4
            for (int t = 0; t < 32; t++) {
                int d = 2 * t;
                float qv[4], kvv[4];
#pragma unroll
                for (int i = 0; i < 4; i++) qv[i] = qb[i * 64 + d];
#pragma unroll
                for (int j = 0; j < 4; j++) kvv[j] = kb[j * 16 * KV_STRIDE + d];
#pragma unroll
                for (int i = 0; i < 4; i++)
#pragma unroll
                    for (int j = 0; j < 4; j++) acc[i][j] += qv[i] * kvv[j];
            }
        }
#pragma unroll
        for (int i = 0; i < 4; i++)
#pragma unroll
            for (int j = 0; j < 4; j++)
                acc[i][j] += __shfl_xor_sync(0xffffffffu, acc[i][j], 16);
        if (valid && ds == 0) {
#pragma unroll
            for (int i = 0; i < 4; i++)
#pragma unroll
                for (int j = 0; j < 4; j++)
                    esc[(rg * 4 + i) * ESTR + kt + h2 * 64 + tx + 16 * j] =
                        acc[i][j] * INV_SCALE;
        }
        __syncthreads();
    }

    {
        const int warp = tid >> 5, ln = tid & 31;
        for (int rr = 0; rr < 2; rr++) {
            int r = warp * 2 + rr;
            int q = q0 + r;
            int kc = q + 1;
            float* row = &esc[r * ESTR];

            float m = -1e30f;
            for (int k = ln; k < kc; k += 32) m = fmaxf(m, row[k]);
#pragma unroll
            for (int o = 16; o > 0; o >>= 1) m = fmaxf(m, __shfl_xor_sync(0xffffffffu, m, o));

            float s = 0.f;
            for (int k = ln; k < kc; k += 32) {
                float p = __expf(row[k] - m);
                row[k] = p;
                s += p;
            }
#pragma unroll
            for (int o = 16; o > 0; o >>= 1) s += __shfl_xor_sync(0xffffffffu, s, o);

            float cb = cons[b * SEQ + q];
            float cwv = CW[(size_t)(b * SEQ + q) * NH + h];
            float fs = (1.f + cb * cwv) / s;

            float z2 = 0.f;
            for (int k = ln; k < kc; k += 32) {
                float e = __expf(row[k] * fs);
                row[k] = e;
                z2 += e;
            }
            for (int k = kc + ln; k < SEQ; k += 32) row[k] = 1.f;
#pragma unroll
            for (int o = 16; o > 0; o >>= 1) z2 += __shfl_xor_sync(0xffffffffu, z2, o);
            z2 += (float)(SEQ - kc);
            if (ln == 0) zinv[r] = 1.f / z2;
        }
    }
    __syncthreads();

    {
        const size_t abase = ((size_t)bh * SEQ + q0) * SEQ;
        for (int idx4 = tid; idx4 < ROWS * 256; idx4 += 256) {
            int r = idx4 >> 8;
            int c4 = (idx4 & 255) * 4;
            float zi = zinv[r];
            float4 v = *(float4*)&esc[r * ESTR + c4];
            v.x *= zi; v.y *= zi; v.z *= zi; v.w *= zi;
            *(float4*)&attn_out[abase + (size_t)r * SEQ + c4] = v;
        }
    }
    __syncthreads();

    {
        int r = tid >> 4;
        int q = q0 + r;
        int j = tid & 15;
        int tile_end = ((kmax + KT2 - 1) / KT2) * KT2;
        if (tile_end > SEQ) tile_end = SEQ;
        float* row = &esc[r * ESTR];
        for (int k = q + 1 + j; k < tile_end; k += 16) row[k] = 0.f;
    }
    __syncthreads();

    const int ks = tid >> 6;
    const int crg = (tid >> 4) & 3;
    const int txd = tid & 15;

    float c[4][4];
#pragma unroll
    for (int i = 0; i < 4; i++)
#pragma unroll
        for (int j = 0; j < 4; j++) c[i][j] = 0.f;

    for (int kt = 0; kt < kmax; kt += KT2) {
#pragma unroll
        for (int li = 0; li < 8; li++) {
            int idx = tid + li * 256;
            int r = idx >> 4;
            int d4 = (idx & 15) * 4;
            *(float4*)&kv[r * KV_STRIDE + d4] =
                *(const float4*)&Vm[((size_t)(b * SEQ + kt + r)) * EMB + h * HD + d4];
        }
        __syncthreads();

        const float* eb = &esc[crg * 4 * ESTR + kt + ks * 32];
        const float* vb = &kv[(ks * 32) * KV_STRIDE + txd * 4];
#pragma unroll 4
        for (int kk = 0; kk < 32; kk++) {
            float w[4];
#pragma unroll
            for (int i = 0; i < 4; i++) w[i] = eb[i * ESTR + kk];
            float4 vv = *(const float4*)&vb[kk * KV_STRIDE];
#pragma unroll
            for (int i = 0; i < 4; i++) {
                c[i][0] += w[i] * vv.x;
                c[i][1] += w[i] * vv.y;
                c[i][2] += w[i] * vv.z;
                c[i][3] += w[i] * vv.w;
            }
        }
        __syncthreads();
    }

    float* red = kv;
    const int rem64 = tid & 63;
    if (ks > 0) {
#pragma unroll
        for (int i = 0; i < 4; i++)
            *(float4*)&red[((ks - 1) * 64 + rem64) * 16 + i * 4] = *(float4*)&c[i][0];
    }
    __syncthreads();
    if (ks == 0) {
#pragma unroll
        for (int s = 0; s < 3; s++)
#pragma unroll
            for (int i = 0; i < 4; i++) {
                float4 p = *(float4*)&red[(s * 64 + rem64) * 16 + i * 4];
                c[i][0] += p.x; c[i][1] += p.y; c[i][2] += p.z; c[i][3] += p.w;
            }
#pragma unroll
        for (int i = 0; i < 4; i++) {
            int row = crg * 4 + i;
            float zi = zinv[row];
            float4 sv = *(const float4*)&Suf[((size_t)bh * SEQ + q0 + row) * HD + txd * 4];
            float4 o;
            o.x = (c[i][0] + sv.x) * zi;
            o.y = (c[i][1] + sv.y) * zi;
            o.z = (c[i][2] + sv.z) * zi;
            o.w = (c[i][3] + sv.w) * zi;
            *(float4*)&ctx[((size_t)(b * SEQ + q0 + row)) * EMB + h * HD + txd * 4] = o;
        }
    }
}

// ---------------- launch ----------------------------------------------------
extern "C" void kernel_launch(void* const* d_in, const int* in_sizes, int n_in,
                              void* d_out, int out_size)
{
    const float* query = (const float*)d_in[0];
    const float* key   = (const float*)d_in[1];
    const float* value = (const float*)d_in[2];
    const float* cons  = (const float*)d_in[3];
    const float* Wq = (const float*)d_in[5];
    const float* bq = (const float*)d_in[6];
    const float* Wk = (const float*)d_in[7];
    const float* bk = (const float*)d_in[8];
    const float* Wv = (const float*)d_in[9];
    const float* bv = (const float*)d_in[10];
    const float* Wo = (const float*)d_in[11];
    const float* bo = (const float*)d_in[12];
    const float* Wc = (const float*)d_in[13];
    const float* bc = (const float*)d_in[14];

    float* qp; cudaGetSymbolAddress((void**)&qp, g_q);
    float* kp; cudaGetSymbolAddress((void**)&kp, g_k);
    float* vp; cudaGetSymbolAddress((void**)&vp, g_v);
    float* cp; cudaGetSymbolAddress((void**)&cp, g_ctx);
    float* cwp; cudaGetSymbolAddress((void**)&cwp, g_cw);
    float* sufp; cudaGetSymbolAddress((void**)&sufp, g_vsuf);
    __nv_bfloat16* ahi; cudaGetSymbolAddress((void**)&ahi, g_ahi);
    __nv_bfloat16* alo; cudaGetSymbolAddress((void**)&alo, g_alo);
    __nv_bfloat16* whi; cudaGetSymbolAddress((void**)&whi, g_whi);
    __nv_bfloat16* wlo; cudaGetSymbolAddress((void**)&wlo, g_wlo);

    float* out = (float*)d_out;
    float* attn_out = out + (size_t)BATCH * SEQ * EMB;

    const int M = BATCH * SEQ;
    const int A4 = M * EMB / 4;
    const int W4 = EMB * EMB / 4;
    const size_t AE = (size_t)M * EMB;
    const size_t WE = (size_t)EMB * EMB;
    dim3 gemm_grid(EMB / BN, M / BM);

    const int gemm_smem = STAGES * STAGE_ELEM * sizeof(__nv_bfloat16); // ~111KB
    cudaFuncSetAttribute(gemm_bf16x3f, cudaFuncAttributeMaxDynamicSharedMemorySize, gemm_smem);

    // split everything up front
    dim3 sa_grid((A4 + 255) / 256, 3);
    split_act3_kernel<<<sa_grid, 256>>>(query, key, value, ahi, alo, A4);
    dim3 sw_grid((W4 + 255) / 256, 4);
    split_w4_kernel<<<sw_grid, 256>>>(Wq, Wk, Wv, Wo, whi, wlo, W4);

    gemm_bf16x3f<<<gemm_grid, 256, gemm_smem>>>(ahi,          alo,          whi,          wlo,          bq, qp, M, EMB, EMB);
    gemm_bf16x3f<<<gemm_grid, 256, gemm_smem>>>(ahi + AE,     alo + AE,     whi + WE,     wlo + WE,     bk, kp, M, EMB, EMB);
    gemm_bf16x3f<<<gemm_grid, 256, gemm_smem>>>(ahi + 2 * AE, alo + 2 * AE, whi + 2 * WE, wlo + 2 * WE, bv, vp, M, EMB, EMB);

    cw_kernel<<<M / 8, 128>>>(query, Wc, bc, cwp);
    vsuffix_kernel<<<BATCH * NH, 256>>>(vp, sufp);

    const int attn_smem = (ROWS * ESTR + KT2 * KV_STRIDE + ROWS * 64) * sizeof(float);
    cudaFuncSetAttribute(attn_kernel, cudaFuncAttributeMaxDynamicSharedMemorySize, attn_smem);
    dim3 attn_grid(SEQ / ROWS, BATCH * NH);
    attn_kernel<<<attn_grid, 256, attn_smem>>>(qp, kp, vp, cwp, cons, sufp, attn_out, cp);

    split_kernel<<<(A4 + 255) / 256, 256>>>(cp, ahi, alo, A4);
    gemm_bf16x3f<<<gemm_grid, 256, gemm_smem>>>(ahi, alo, whi + 3 * WE, wlo + 3 * WE, bo, out, M, EMB, EMB);
}

// round 6
// speedup vs baseline: 3.0254x; 1.0343x over previous
#include <cuda_runtime.h>
#include <cuda_bf16.h>
#include <math.h>
#include <stdint.h>

#define EMB 1024
#define SEQ 1024
#define BATCH 4
#define NH 16
#define HD 64

// ---------------- scratch (device globals; no allocation allowed) ----------
__device__ float g_q[BATCH * SEQ * EMB];
__device__ float g_k[BATCH * SEQ * EMB];
__device__ float g_v[BATCH * SEQ * EMB];
__device__ float g_ctx[BATCH * SEQ * EMB];
__device__ float g_cw[BATCH * SEQ * NH];
__device__ float g_vsuf[BATCH * NH * SEQ * HD];
__device__ __nv_bfloat16 g_ahi[3][BATCH * SEQ * EMB];
__device__ __nv_bfloat16 g_alo[3][BATCH * SEQ * EMB];
__device__ __nv_bfloat16 g_whi[4][EMB * EMB];
__device__ __nv_bfloat16 g_wlo[4][EMB * EMB];

// ---------------- fast exp: FFMA-only, no MUFU ------------------------------
// exp(x) = 2^(x*log2e); i = round(x*log2e) via the 1.5*2^23 trick,
// 2^f (|f|<=0.5) by degree-5 poly, scale by adding i to the exponent bits.
__device__ __forceinline__ float fast_exp(float x)
{
    x = fmaxf(x, -80.0f);                       // avoid denormal/garbage scaling
    const float L2E = 1.4426950408889634f;
    float t = fmaf(x, L2E, 12582912.0f);        // 1.5 * 2^23
    float i = t - 12582912.0f;                  // round(x*log2e)
    float f = fmaf(x, L2E, -i);                 // in [-0.5, 0.5]
    float p = 1.3333558146e-3f;
    p = fmaf(p, f, 9.6181291918e-3f);
    p = fmaf(p, f, 5.5504108664e-2f);
    p = fmaf(p, f, 2.4022650696e-1f);
    p = fmaf(p, f, 6.9314718056e-1f);
    p = fmaf(p, f, 1.0f);
    return __int_as_float(__float_as_int(p) + ((int)i << 23));
}

// ---------------- fp32 -> bf16 hi/lo split ----------------------------------
__device__ __forceinline__ void split4(
    const float* __restrict__ X, __nv_bfloat16* __restrict__ Hi,
    __nv_bfloat16* __restrict__ Lo, int i)
{
    float4 x = ((const float4*)X)[i];
    __nv_bfloat16 h0 = __float2bfloat16(x.x);
    __nv_bfloat16 h1 = __float2bfloat16(x.y);
    __nv_bfloat16 h2 = __float2bfloat16(x.z);
    __nv_bfloat16 h3 = __float2bfloat16(x.w);
    __nv_bfloat162 H0; H0.x = h0; H0.y = h1;
    __nv_bfloat162 H1; H1.x = h2; H1.y = h3;
    __nv_bfloat162 L0;
    L0.x = __float2bfloat16(x.x - __bfloat162float(h0));
    L0.y = __float2bfloat16(x.y - __bfloat162float(h1));
    __nv_bfloat162 L1;
    L1.x = __float2bfloat16(x.z - __bfloat162float(h2));
    L1.y = __float2bfloat16(x.w - __bfloat162float(h3));
    ((__nv_bfloat162*)Hi)[2 * i] = H0;
    ((__nv_bfloat162*)Hi)[2 * i + 1] = H1;
    ((__nv_bfloat162*)Lo)[2 * i] = L0;
    ((__nv_bfloat162*)Lo)[2 * i + 1] = L1;
}

__global__ __launch_bounds__(256) void split_kernel(
    const float* __restrict__ X, __nv_bfloat16* __restrict__ Hi,
    __nv_bfloat16* __restrict__ Lo, int n4)
{
    int i = blockIdx.x * 256 + threadIdx.x;
    if (i < n4) split4(X, Hi, Lo, i);
}

__global__ __launch_bounds__(256) void split_act3_kernel(
    const float* __restrict__ X0, const float* __restrict__ X1,
    const float* __restrict__ X2, __nv_bfloat16* __restrict__ Hi,
    __nv_bfloat16* __restrict__ Lo, int n4)
{
    int i = blockIdx.x * 256 + threadIdx.x;
    if (i >= n4) return;
    int s = blockIdx.y;
    const float* X = (s == 0) ? X0 : (s == 1) ? X1 : X2;
    split4(X, Hi + (size_t)s * BATCH * SEQ * EMB,
           Lo + (size_t)s * BATCH * SEQ * EMB, i);
}

__global__ __launch_bounds__(256) void split_w4_kernel(
    const float* __restrict__ W0, const float* __restrict__ W1,
    const float* __restrict__ W2, const float* __restrict__ W3,
    __nv_bfloat16* __restrict__ Hi, __nv_bfloat16* __restrict__ Lo, int n4)
{
    int i = blockIdx.x * 256 + threadIdx.x;
    if (i >= n4) return;
    int s = blockIdx.y;
    const float* W = (s == 0) ? W0 : (s == 1) ? W1 : (s == 2) ? W2 : W3;
    split4(W, Hi + (size_t)s * EMB * EMB, Lo + (size_t)s * EMB * EMB, i);
}

// ---------------- fused bf16x3 tensor-core GEMM -----------------------------
// 2-stage cp.async ring, 2 CTAs/SM (single wave: 256 blocks <= 296 slots).
#define BM 128
#define BN 128
#define BK 32
#define ASTR 40
#define BSTR 136
#define STAGES 2
#define A_ELEM (BM * ASTR)
#define B_ELEM (BK * BSTR)
#define STAGE_ELEM (2 * A_ELEM + 2 * B_ELEM)

#define CP_ASYNC16(dst, src) \
    asm volatile("cp.async.cg.shared.global [%0], [%1], 16;\n" :: "r"(dst), "l"(src))
#define CP_COMMIT asm volatile("cp.async.commit_group;\n" ::)
#define CP_WAITG(n) asm volatile("cp.async.wait_group %0;\n" :: "n"(n))

__global__ __launch_bounds__(256, 2) void gemm_bf16x3f(
    const __nv_bfloat16* __restrict__ Ahi, const __nv_bfloat16* __restrict__ Alo,
    const __nv_bfloat16* __restrict__ Bhi, const __nv_bfloat16* __restrict__ Blo,
    const float* __restrict__ bias, float* __restrict__ C,
    int M, int N, int K)
{
    extern __shared__ __align__(16) __nv_bfloat16 smem[];

    const int tid = threadIdx.x;
    const int lane = tid & 31;
    const int wid = tid >> 5;
    const int wm = wid & 1;
    const int wn = wid >> 1;
    const int row0 = blockIdx.y * BM;
    const int col0 = blockIdx.x * BN;

    float acc[4][4][4];
#pragma unroll
    for (int i = 0; i < 4; i++)
#pragma unroll
        for (int j = 0; j < 4; j++)
#pragma unroll
            for (int r = 0; r < 4; r++) acc[i][j][r] = 0.f;

    const int TOT = K / BK;   // 32

    const int a_r0 = (tid * 2) >> 2, a_c0 = ((tid * 2) & 3) * 8;
    const int a_r1 = (tid * 2 + 1) >> 2, a_c1 = ((tid * 2 + 1) & 3) * 8;
    const int b_r0 = (tid * 2) >> 4, b_c0 = ((tid * 2) & 15) * 8;
    const int b_r1 = (tid * 2 + 1) >> 4, b_c1 = ((tid * 2 + 1) & 15) * 8;

#define LOAD_STAGE(IT, BUF) do {                                               \
    int k0_ = (IT) * BK;                                                       \
    __nv_bfloat16* sa_hi = smem + (BUF) * STAGE_ELEM;                          \
    __nv_bfloat16* sa_lo = sa_hi + A_ELEM;                                     \
    __nv_bfloat16* sb_hi = sa_lo + A_ELEM;                                     \
    __nv_bfloat16* sb_lo = sb_hi + B_ELEM;                                     \
    CP_ASYNC16((uint32_t)__cvta_generic_to_shared(&sa_hi[a_r0 * ASTR + a_c0]), \
               Ahi + (size_t)(row0 + a_r0) * K + k0_ + a_c0);                  \
    CP_ASYNC16((uint32_t)__cvta_generic_to_shared(&sa_hi[a_r1 * ASTR + a_c1]), \
               Ahi + (size_t)(row0 + a_r1) * K + k0_ + a_c1);                  \
    CP_ASYNC16((uint32_t)__cvta_generic_to_shared(&sa_lo[a_r0 * ASTR + a_c0]), \
               Alo + (size_t)(row0 + a_r0) * K + k0_ + a_c0);                  \
    CP_ASYNC16((uint32_t)__cvta_generic_to_shared(&sa_lo[a_r1 * ASTR + a_c1]), \
               Alo + (size_t)(row0 + a_r1) * K + k0_ + a_c1);                  \
    CP_ASYNC16((uint32_t)__cvta_generic_to_shared(&sb_hi[b_r0 * BSTR + b_c0]), \
               Bhi + (size_t)(k0_ + b_r0) * N + col0 + b_c0);                  \
    CP_ASYNC16((uint32_t)__cvta_generic_to_shared(&sb_hi[b_r1 * BSTR + b_c1]), \
               Bhi + (size_t)(k0_ + b_r1) * N + col0 + b_c1);                  \
    CP_ASYNC16((uint32_t)__cvta_generic_to_shared(&sb_lo[b_r0 * BSTR + b_c0]), \
               Blo + (size_t)(k0_ + b_r0) * N + col0 + b_c0);                  \
    CP_ASYNC16((uint32_t)__cvta_generic_to_shared(&sb_lo[b_r1 * BSTR + b_c1]), \
               Blo + (size_t)(k0_ + b_r1) * N + col0 + b_c1);                  \
} while (0)

#define MMA(ACC, A, B0, B1)                                                    \
    asm volatile(                                                              \
        "mma.sync.aligned.m16n8k16.row.col.f32.bf16.bf16.f32 "                 \
        "{%0,%1,%2,%3},{%4,%5,%6,%7},{%8,%9},{%0,%1,%2,%3};"                   \
        : "+f"((ACC)[0]), "+f"((ACC)[1]), "+f"((ACC)[2]), "+f"((ACC)[3])       \
        : "r"((A)[0]), "r"((A)[1]), "r"((A)[2]), "r"((A)[3]),                  \
          "r"(B0), "r"(B1))

    LOAD_STAGE(0, 0); CP_COMMIT;

    for (int it = 0; it < TOT; it++) {
        const int buf = it & 1;
        if (it + 1 < TOT) {
            LOAD_STAGE(it + 1, (it + 1) & 1);
            CP_COMMIT;
            CP_WAITG(1);
        } else {
            CP_WAITG(0);
        }
        __syncthreads();

        const __nv_bfloat16* sa_hi = smem + buf * STAGE_ELEM;
        const __nv_bfloat16* sa_lo = sa_hi + A_ELEM;
        const __nv_bfloat16* sb_hi = sa_lo + A_ELEM;
        const __nv_bfloat16* sb_lo = sb_hi + B_ELEM;

#pragma unroll
        for (int ks = 0; ks < 2; ks++) {
            uint32_t ahi[4][4], alo[4][4], bhi[2][4], blo[2][4];
#pragma unroll
            for (int mi = 0; mi < 4; mi++) {
                int roff = (wm * 64 + mi * 16 + (lane & 15)) * ASTR +
                           ks * 16 + (lane >> 4) * 8;
                uint32_t ad = (uint32_t)__cvta_generic_to_shared(&sa_hi[roff]);
                asm volatile(
                    "ldmatrix.sync.aligned.m8n8.x4.shared.b16 {%0,%1,%2,%3},[%4];"
                    : "=r"(ahi[mi][0]), "=r"(ahi[mi][1]),
                      "=r"(ahi[mi][2]), "=r"(ahi[mi][3]) : "r"(ad));
                uint32_t ad2 = (uint32_t)__cvta_generic_to_shared(&sa_lo[roff]);
                asm volatile(
                    "ldmatrix.sync.aligned.m8n8.x4.shared.b16 {%0,%1,%2,%3},[%4];"
                    : "=r"(alo[mi][0]), "=r"(alo[mi][1]),
                      "=r"(alo[mi][2]), "=r"(alo[mi][3]) : "r"(ad2));
            }
#pragma unroll
            for (int bi = 0; bi < 2; bi++) {
                int boff = (ks * 16 + (lane & 15)) * BSTR +
                           wn * 32 + bi * 16 + (lane >> 4) * 8;
                uint32_t bd = (uint32_t)__cvta_generic_to_shared(&sb_hi[boff]);
                asm volatile(
                    "ldmatrix.sync.aligned.m8n8.x4.trans.shared.b16 {%0,%1,%2,%3},[%4];"
                    : "=r"(bhi[bi][0]), "=r"(bhi[bi][1]),
                      "=r"(bhi[bi][2]), "=r"(bhi[bi][3]) : "r"(bd));
                uint32_t bd2 = (uint32_t)__cvta_generic_to_shared(&sb_lo[boff]);
                asm volatile(
                    "ldmatrix.sync.aligned.m8n8.x4.trans.shared.b16 {%0,%1,%2,%3},[%4];"
                    : "=r"(blo[bi][0]), "=r"(blo[bi][1]),
                      "=r"(blo[bi][2]), "=r"(blo[bi][3]) : "r"(bd2));
            }
#pragma unroll
            for (int mi = 0; mi < 4; mi++)
#pragma unroll
                for (int ni = 0; ni < 4; ni++) {
                    int g = ni >> 1, p = (ni & 1) * 2;
                    MMA(acc[mi][ni], ahi[mi], bhi[g][p], bhi[g][p + 1]);
                    MMA(acc[mi][ni], ahi[mi], blo[g][p], blo[g][p + 1]);
                    MMA(acc[mi][ni], alo[mi], bhi[g][p], bhi[g][p + 1]);
                }
        }
        __syncthreads();
    }

    const int g = lane >> 2;
    const int t = lane & 3;
#pragma unroll
    for (int ni = 0; ni < 4; ni++) {
        int col = col0 + wn * 32 + ni * 8 + t * 2;
        float b0 = bias[col], b1 = bias[col + 1];
#pragma unroll
        for (int mi = 0; mi < 4; mi++) {
            int row = row0 + wm * 64 + mi * 16 + g;
            float2 o0 = { acc[mi][ni][0] + b0, acc[mi][ni][1] + b1 };
            float2 o1 = { acc[mi][ni][2] + b0, acc[mi][ni][3] + b1 };
            *(float2*)&C[(size_t)row * N + col] = o0;
            *(float2*)&C[(size_t)(row + 8) * N + col] = o1;
        }
    }
}

// ---------------- cw = softmax(query @ Wc + bc, axis=H) --------------------
__global__ __launch_bounds__(128) void cw_kernel(
    const float* __restrict__ query, const float* __restrict__ Wc,
    const float* __restrict__ bc, float* __restrict__ CW)
{
    __shared__ float qs[8][1024];
    const int tid = threadIdx.x;
    const int row0 = blockIdx.x * 8;

    for (int idx = tid; idx < 2048; idx += 128) {
        int r = idx >> 8;
        int c4 = (idx & 255) * 4;
        *(float4*)&qs[r][c4] = *(const float4*)&query[(size_t)(row0 + r) * EMB + c4];
    }
    __syncthreads();

    const int r = tid >> 4;
    const int h = tid & 15;
    const float* q = &qs[r][0];

    float a0 = 0.f, a1 = 0.f, a2 = 0.f, a3 = 0.f;
#pragma unroll 4
    for (int i = 0; i < EMB; i += 4) {
        a0 += q[i + 0] * Wc[(i + 0) * NH + h];
        a1 += q[i + 1] * Wc[(i + 1) * NH + h];
        a2 += q[i + 2] * Wc[(i + 2) * NH + h];
        a3 += q[i + 3] * Wc[(i + 3) * NH + h];
    }
    float acc = bc[h] + (a0 + a1) + (a2 + a3);

    float m = acc;
#pragma unroll
    for (int o = 8; o > 0; o >>= 1) m = fmaxf(m, __shfl_xor_sync(0xffffffffu, m, o, 16));
    float e = fast_exp(acc - m);
    float s = e;
#pragma unroll
    for (int o = 8; o > 0; o >>= 1) s += __shfl_xor_sync(0xffffffffu, s, o, 16);
    CW[(size_t)(row0 + r) * NH + h] = e / s;
}

// ---------------- suffix sums of V ------------------------------------------
__global__ __launch_bounds__(256) void vsuffix_kernel(
    const float* __restrict__ V, float* __restrict__ Suf)
{
    __shared__ float T[4][64];
    const int bh = blockIdx.x;
    const int b = bh >> 4;
    const int h = bh & 15;
    const int t = threadIdx.x;
    const int p = t >> 6;
    const int d = t & 63;

    const float* vb = V + (size_t)b * SEQ * EMB + h * HD + d;
    float* sufb = Suf + (size_t)bh * SEQ * HD + d;

    const int k0 = p * 256;
    float s = 0.f;
    for (int k = k0; k < k0 + 256; k++) s += vb[(size_t)k * EMB];
    T[p][d] = s;
    __syncthreads();

    float acc = 0.f;
    for (int pp = p + 1; pp < 4; pp++) acc += T[pp][d];
    for (int k = k0 + 255; k >= k0; k--) {
        sufb[(size_t)k * HD] = acc;
        acc += vb[(size_t)k * EMB];
    }
}

// ---------------- attention --------------------------------------------------
#define ROWS 16
#define KT2 128
#define KV_STRIDE 68
#define ESTR 1044

__global__ __launch_bounds__(256, 2) void attn_kernel(
    const float* __restrict__ Q, const float* __restrict__ Km,
    const float* __restrict__ Vm, const float* __restrict__ CW,
    const float* __restrict__ cons, const float* __restrict__ Suf,
    float* __restrict__ attn_out, float* __restrict__ ctx)
{
    extern __shared__ float sm[];
    float* esc = sm;
    float* kv = sm + ROWS * ESTR;
    float* qs = kv + KT2 * KV_STRIDE;
    __shared__ float zinv[ROWS];

    const int tid = threadIdx.x;
    const int bh = blockIdx.y;
    const int b = bh >> 4;
    const int h = bh & 15;
    const int q0 = blockIdx.x * ROWS;
    const float INV_SCALE = 1.0f / (8.0f * sqrtf(1.61803398874989485f));

    {
        int r = tid >> 4;
        int d4 = (tid & 15) * 4;
        *(float4*)&qs[r * 64 + d4] =
            *(const float4*)&Q[((size_t)(b * SEQ + q0 + r)) * EMB + h * HD + d4];
    }

    const int kmax = q0 + ROWS;

    const int h2 = tid >> 7;
    const int rg = (tid >> 5) & 3;
    const int lane = tid & 31;
    const int ds = lane >> 4;
    const int tx = lane & 15;

    for (int kt = 0; kt < kmax; kt += KT2) {
#pragma unroll
        for (int li = 0; li < 8; li++) {
            int idx = tid + li * 256;
            int r = idx >> 4;
            int d4 = (idx & 15) * 4;
            *(float4*)&kv[r * KV_STRIDE + d4] =
                *(const float4*)&Km[((size_t)(b * SEQ + kt + r)) * EMB + h * HD + d4];
        }
        __syncthreads();

        const bool valid = (kt + h2 * 64) < kmax;
        float acc[4][4];
#pragma unroll
        for (int i = 0; i < 4; i++)
#pragma unroll
            for (int j = 0; j < 4; j++) acc[i][j] = 0.f;

        if (valid) {
            const float* qb = &qs[rg * 4 * 64 + ds];
            const float* kb = &kv[(h2 * 64 + tx) * KV_STRIDE + ds];
#pragma unroll 4
            for (int t = 0; t < 32; t++) {
                int d = 2 * t;
                float qv[4], kvv[4];
#pragma unroll
                for (int i = 0; i < 4; i++) qv[i] = qb[i * 64 + d];
#pragma unroll
                for (int j = 0; j < 4; j++) kvv[j] = kb[j * 16 * KV_STRIDE + d];
#pragma unroll
                for (int i = 0; i < 4; i++)
#pragma unroll
                    for (int j = 0; j < 4; j++) acc[i][j] += qv[i] * kvv[j];
            }
        }
#pragma unroll
        for (int i = 0; i < 4; i++)
#pragma unroll
            for (int j = 0; j < 4; j++)
                acc[i][j] += __shfl_xor_sync(0xffffffffu, acc[i][j], 16);
        if (valid && ds == 0) {
#pragma unroll
            for (int i = 0; i < 4; i++)
#pragma unroll
                for (int j = 0; j < 4; j++)
                    esc[(rg * 4 + i) * ESTR + kt + h2 * 64 + tx + 16 * j] =
                        acc[i][j] * INV_SCALE;
        }
        __syncthreads();
    }

    // ---- softmax1 -> rescale -> softmax2 numerators (FFMA exp, no MUFU) ----
    {
        const int warp = tid >> 5, ln = tid & 31;
        for (int rr = 0; rr < 2; rr++) {
            int r = warp * 2 + rr;
            int q = q0 + r;
            int kc = q + 1;
            float* row = &esc[r * ESTR];

            float m = -1e30f;
            for (int k = ln; k < kc; k += 32) m = fmaxf(m, row[k]);
#pragma unroll
            for (int o = 16; o > 0; o >>= 1) m = fmaxf(m, __shfl_xor_sync(0xffffffffu, m, o));

            float s = 0.f;
            for (int k = ln; k < kc; k += 32) {
                float p = fast_exp(row[k] - m);
                row[k] = p;
                s += p;
            }
#pragma unroll
            for (int o = 16; o > 0; o >>= 1) s += __shfl_xor_sync(0xffffffffu, s, o);

            float cb = cons[b * SEQ + q];
            float cwv = CW[(size_t)(b * SEQ + q) * NH + h];
            float fs = (1.f + cb * cwv) / s;

            float z2 = 0.f;
            for (int k = ln; k < kc; k += 32) {
                float e = fast_exp(row[k] * fs);
                row[k] = e;
                z2 += e;
            }
            for (int k = kc + ln; k < SEQ; k += 32) row[k] = 1.f;
#pragma unroll
            for (int o = 16; o > 0; o >>= 1) z2 += __shfl_xor_sync(0xffffffffu, z2, o);
            z2 += (float)(SEQ - kc);
            if (ln == 0) zinv[r] = 1.f / z2;
        }
    }
    __syncthreads();

    {
        const size_t abase = ((size_t)bh * SEQ + q0) * SEQ;
        for (int idx4 = tid; idx4 < ROWS * 256; idx4 += 256) {
            int r = idx4 >> 8;
            int c4 = (idx4 & 255) * 4;
            float zi = zinv[r];
            float4 v = *(float4*)&esc[r * ESTR + c4];
            v.x *= zi; v.y *= zi; v.z *= zi; v.w *= zi;
            *(float4*)&attn_out[abase + (size_t)r * SEQ + c4] = v;
        }
    }
    __syncthreads();

    {
        int r = tid >> 4;
        int q = q0 + r;
        int j = tid & 15;
        int tile_end = ((kmax + KT2 - 1) / KT2) * KT2;
        if (tile_end > SEQ) tile_end = SEQ;
        float* row = &esc[r * ESTR];
        for (int k = q + 1 + j; k < tile_end; k += 16) row[k] = 0.f;
    }
    __syncthreads();

    const int ks = tid >> 6;
    const int crg = (tid >> 4) & 3;
    const int txd = tid & 15;

    float c[4][4];
#pragma unroll
    for (int i = 0; i < 4; i++)
#pragma unroll
        for (int j = 0; j < 4; j++) c[i][j] = 0.f;

    for (int kt = 0; kt < kmax; kt += KT2) {
#pragma unroll
        for (int li = 0; li < 8; li++) {
            int idx = tid + li * 256;
            int r = idx >> 4;
            int d4 = (idx & 15) * 4;
            *(float4*)&kv[r * KV_STRIDE + d4] =
                *(const float4*)&Vm[((size_t)(b * SEQ + kt + r)) * EMB + h * HD + d4];
        }
        __syncthreads();

        const float* eb = &esc[crg * 4 * ESTR + kt + ks * 32];
        const float* vb = &kv[(ks * 32) * KV_STRIDE + txd * 4];
#pragma unroll 4
        for (int kk = 0; kk < 32; kk++) {
            float w[4];
#pragma unroll
            for (int i = 0; i < 4; i++) w[i] = eb[i * ESTR + kk];
            float4 vv = *(const float4*)&vb[kk * KV_STRIDE];
#pragma unroll
            for (int i = 0; i < 4; i++) {
                c[i][0] += w[i] * vv.x;
                c[i][1] += w[i] * vv.y;
                c[i][2] += w[i] * vv.z;
                c[i][3] += w[i] * vv.w;
            }
        }
        __syncthreads();
    }

    float* red = kv;
    const int rem64 = tid & 63;
    if (ks > 0) {
#pragma unroll
        for (int i = 0; i < 4; i++)
            *(float4*)&red[((ks - 1) * 64 + rem64) * 16 + i * 4] = *(float4*)&c[i][0];
    }
    __syncthreads();
    if (ks == 0) {
#pragma unroll
        for (int s = 0; s < 3; s++)
#pragma unroll
            for (int i = 0; i < 4; i++) {
                float4 p = *(float4*)&red[(s * 64 + rem64) * 16 + i * 4];
                c[i][0] += p.x; c[i][1] += p.y; c[i][2] += p.z; c[i][3] += p.w;
            }
#pragma unroll
        for (int i = 0; i < 4; i++) {
            int row = crg * 4 + i;
            float zi = zinv[row];
            float4 sv = *(const float4*)&Suf[((size_t)bh * SEQ + q0 + row) * HD + txd * 4];
            float4 o;
            o.x = (c[i][0] + sv.x) * zi;
            o.y = (c[i][1] + sv.y) * zi;
            o.z = (c[i][2] + sv.z) * zi;
            o.w = (c[i][3] + sv.w) * zi;
            *(float4*)&ctx[((size_t)(b * SEQ + q0 + row)) * EMB + h * HD + txd * 4] = o;
        }
    }
}

// ---------------- launch ----------------------------------------------------
extern "C" void kernel_launch(void* const* d_in, const int* in_sizes, int n_in,
                              void* d_out, int out_size)
{
    const float* query = (const float*)d_in[0];
    const float* key   = (const float*)d_in[1];
    const float* value = (const float*)d_in[2];
    const float* cons  = (const float*)d_in[3];
    const float* Wq = (const float*)d_in[5];
    const float* bq = (const float*)d_in[6];
    const float* Wk = (const float*)d_in[7];
    const float* bk = (const float*)d_in[8];
    const float* Wv = (const float*)d_in[9];
    const float* bv = (const float*)d_in[10];
    const float* Wo = (const float*)d_in[11];
    const float* bo = (const float*)d_in[12];
    const float* Wc = (const float*)d_in[13];
    const float* bc = (const float*)d_in[14];

    float* qp; cudaGetSymbolAddress((void**)&qp, g_q);
    float* kp; cudaGetSymbolAddress((void**)&kp, g_k);
    float* vp; cudaGetSymbolAddress((void**)&vp, g_v);
    float* cp; cudaGetSymbolAddress((void**)&cp, g_ctx);
    float* cwp; cudaGetSymbolAddress((void**)&cwp, g_cw);
    float* sufp; cudaGetSymbolAddress((void**)&sufp, g_vsuf);
    __nv_bfloat16* ahi; cudaGetSymbolAddress((void**)&ahi, g_ahi);
    __nv_bfloat16* alo; cudaGetSymbolAddress((void**)&alo, g_alo);
    __nv_bfloat16* whi; cudaGetSymbolAddress((void**)&whi, g_whi);
    __nv_bfloat16* wlo; cudaGetSymbolAddress((void**)&wlo, g_wlo);

    float* out = (float*)d_out;
    float* attn_out = out + (size_t)BATCH * SEQ * EMB;

    const int M = BATCH * SEQ;
    const int A4 = M * EMB / 4;
    const int W4 = EMB * EMB / 4;
    const size_t AE = (size_t)M * EMB;
    const size_t WE = (size_t)EMB * EMB;
    dim3 gemm_grid(EMB / BN, M / BM);

    const int gemm_smem = STAGES * STAGE_ELEM * sizeof(__nv_bfloat16); // ~76KB
    cudaFuncSetAttribute(gemm_bf16x3f, cudaFuncAttributeMaxDynamicSharedMemorySize, gemm_smem);

    dim3 sa_grid((A4 + 255) / 256, 3);
    split_act3_kernel<<<sa_grid, 256>>>(query, key, value, ahi, alo, A4);
    dim3 sw_grid((W4 + 255) / 256, 4);
    split_w4_kernel<<<sw_grid, 256>>>(Wq, Wk, Wv, Wo, whi, wlo, W4);

    gemm_bf16x3f<<<gemm_grid, 256, gemm_smem>>>(ahi,          alo,          whi,          wlo,          bq, qp, M, EMB, EMB);
    gemm_bf16x3f<<<gemm_grid, 256, gemm_smem>>>(ahi + AE,     alo + AE,     whi + WE,     wlo + WE,     bk, kp, M, EMB, EMB);
    gemm_bf16x3f<<<gemm_grid, 256, gemm_smem>>>(ahi + 2 * AE, alo + 2 * AE, whi + 2 * WE, wlo + 2 * WE, bv, vp, M, EMB, EMB);

    cw_kernel<<<M / 8, 128>>>(query, Wc, bc, cwp);
    vsuffix_kernel<<<BATCH * NH, 256>>>(vp, sufp);

    const int attn_smem = (ROWS * ESTR + KT2 * KV_STRIDE + ROWS * 64) * sizeof(float);
    cudaFuncSetAttribute(attn_kernel, cudaFuncAttributeMaxDynamicSharedMemorySize, attn_smem);
    dim3 attn_grid(SEQ / ROWS, BATCH * NH);
    attn_kernel<<<attn_grid, 256, attn_smem>>>(qp, kp, vp, cwp, cons, sufp, attn_out, cp);

    split_kernel<<<(A4 + 255) / 256, 256>>>(cp, ahi, alo, A4);
    gemm_bf16x3f<<<gemm_grid, 256, gemm_smem>>>(ahi, alo, whi + 3 * WE, wlo + 3 * WE, bo, out, M, EMB, EMB);
}

// round 7
// speedup vs baseline: 3.6550x; 1.2081x over previous
#include <cuda_runtime.h>
#include <cuda_bf16.h>
#include <math.h>
#include <stdint.h>

#define EMB 1024
#define SEQ 1024
#define BATCH 4
#define NH 16
#define HD 64

// ---------------- scratch (device globals; no allocation allowed) ----------
__device__ float g_q[BATCH * SEQ * EMB];
__device__ float g_k[BATCH * SEQ * EMB];
__device__ float g_v[BATCH * SEQ * EMB];
__device__ float g_ctx[BATCH * SEQ * EMB];
__device__ float g_cw[BATCH * SEQ * NH];
__device__ float g_vsuf[BATCH * NH * SEQ * HD];
__device__ __nv_bfloat16 g_ahi[3][BATCH * SEQ * EMB];
__device__ __nv_bfloat16 g_alo[3][BATCH * SEQ * EMB];
__device__ __nv_bfloat16 g_whi[4][EMB * EMB];
__device__ __nv_bfloat16 g_wlo[4][EMB * EMB];

// ---------------- fast exp: FFMA-only ---------------------------------------
__device__ __forceinline__ float fast_exp(float x)
{
    x = fmaxf(x, -80.0f);
    const float L2E = 1.4426950408889634f;
    float t = fmaf(x, L2E, 12582912.0f);
    float i = t - 12582912.0f;
    float f = fmaf(x, L2E, -i);
    float p = 1.3333558146e-3f;
    p = fmaf(p, f, 9.6181291918e-3f);
    p = fmaf(p, f, 5.5504108664e-2f);
    p = fmaf(p, f, 2.4022650696e-1f);
    p = fmaf(p, f, 6.9314718056e-1f);
    p = fmaf(p, f, 1.0f);
    return __int_as_float(__float_as_int(p) + ((int)i << 23));
}

// ---------------- mma / ldmatrix helpers -------------------------------------
__device__ __forceinline__ void ldsm4(uint32_t* r, const void* p)
{
    uint32_t a = (uint32_t)__cvta_generic_to_shared(p);
    asm volatile("ldmatrix.sync.aligned.m8n8.x4.shared.b16 {%0,%1,%2,%3},[%4];"
                 : "=r"(r[0]), "=r"(r[1]), "=r"(r[2]), "=r"(r[3]) : "r"(a));
}
__device__ __forceinline__ void ldsm4t(uint32_t* r, const void* p)
{
    uint32_t a = (uint32_t)__cvta_generic_to_shared(p);
    asm volatile("ldmatrix.sync.aligned.m8n8.x4.trans.shared.b16 {%0,%1,%2,%3},[%4];"
                 : "=r"(r[0]), "=r"(r[1]), "=r"(r[2]), "=r"(r[3]) : "r"(a));
}
__device__ __forceinline__ void mma_bf16(float* c, const uint32_t* a,
                                         uint32_t b0, uint32_t b1)
{
    asm volatile(
        "mma.sync.aligned.m16n8k16.row.col.f32.bf16.bf16.f32 "
        "{%0,%1,%2,%3},{%4,%5,%6,%7},{%8,%9},{%0,%1,%2,%3};"
        : "+f"(c[0]), "+f"(c[1]), "+f"(c[2]), "+f"(c[3])
        : "r"(a[0]), "r"(a[1]), "r"(a[2]), "r"(a[3]), "r"(b0), "r"(b1));
}

// ---------------- fp32 -> bf16 hi/lo split ----------------------------------
__device__ __forceinline__ void split4(
    const float* __restrict__ X, __nv_bfloat16* __restrict__ Hi,
    __nv_bfloat16* __restrict__ Lo, int i)
{
    float4 x = ((const float4*)X)[i];
    __nv_bfloat16 h0 = __float2bfloat16(x.x);
    __nv_bfloat16 h1 = __float2bfloat16(x.y);
    __nv_bfloat16 h2 = __float2bfloat16(x.z);
    __nv_bfloat16 h3 = __float2bfloat16(x.w);
    __nv_bfloat162 H0; H0.x = h0; H0.y = h1;
    __nv_bfloat162 H1; H1.x = h2; H1.y = h3;
    __nv_bfloat162 L0;
    L0.x = __float2bfloat16(x.x - __bfloat162float(h0));
    L0.y = __float2bfloat16(x.y - __bfloat162float(h1));
    __nv_bfloat162 L1;
    L1.x = __float2bfloat16(x.z - __bfloat162float(h2));
    L1.y = __float2bfloat16(x.w - __bfloat162float(h3));
    ((__nv_bfloat162*)Hi)[2 * i] = H0;
    ((__nv_bfloat162*)Hi)[2 * i + 1] = H1;
    ((__nv_bfloat162*)Lo)[2 * i] = L0;
    ((__nv_bfloat162*)Lo)[2 * i + 1] = L1;
}

__global__ __launch_bounds__(256) void split_kernel(
    const float* __restrict__ X, __nv_bfloat16* __restrict__ Hi,
    __nv_bfloat16* __restrict__ Lo, int n4)
{
    int i = blockIdx.x * 256 + threadIdx.x;
    if (i < n4) split4(X, Hi, Lo, i);
}

__global__ __launch_bounds__(256) void split_act3_kernel(
    const float* __restrict__ X0, const float* __restrict__ X1,
    const float* __restrict__ X2, __nv_bfloat16* __restrict__ Hi,
    __nv_bfloat16* __restrict__ Lo, int n4)
{
    int i = blockIdx.x * 256 + threadIdx.x;
    if (i >= n4) return;
    int s = blockIdx.y;
    const float* X = (s == 0) ? X0 : (s == 1) ? X1 : X2;
    split4(X, Hi + (size_t)s * BATCH * SEQ * EMB,
           Lo + (size_t)s * BATCH * SEQ * EMB, i);
}

__global__ __launch_bounds__(256) void split_w4_kernel(
    const float* __restrict__ W0, const float* __restrict__ W1,
    const float* __restrict__ W2, const float* __restrict__ W3,
    __nv_bfloat16* __restrict__ Hi, __nv_bfloat16* __restrict__ Lo, int n4)
{
    int i = blockIdx.x * 256 + threadIdx.x;
    if (i >= n4) return;
    int s = blockIdx.y;
    const float* W = (s == 0) ? W0 : (s == 1) ? W1 : (s == 2) ? W2 : W3;
    split4(W, Hi + (size_t)s * EMB * EMB, Lo + (size_t)s * EMB * EMB, i);
}

// ---------------- fused bf16x3 tensor-core GEMM (round-6, unchanged) --------
#define BM 128
#define BN 128
#define BK 32
#define ASTR 40
#define BSTR 136
#define STAGES 2
#define A_ELEM (BM * ASTR)
#define B_ELEM (BK * BSTR)
#define STAGE_ELEM (2 * A_ELEM + 2 * B_ELEM)

#define CP_ASYNC16(dst, src) \
    asm volatile("cp.async.cg.shared.global [%0], [%1], 16;\n" :: "r"(dst), "l"(src))
#define CP_COMMIT asm volatile("cp.async.commit_group;\n" ::)
#define CP_WAITG(n) asm volatile("cp.async.wait_group %0;\n" :: "n"(n))

__global__ __launch_bounds__(256, 2) void gemm_bf16x3f(
    const __nv_bfloat16* __restrict__ Ahi, const __nv_bfloat16* __restrict__ Alo,
    const __nv_bfloat16* __restrict__ Bhi, const __nv_bfloat16* __restrict__ Blo,
    const float* __restrict__ bias, float* __restrict__ C,
    int M, int N, int K)
{
    extern __shared__ __align__(16) __nv_bfloat16 smem[];

    const int tid = threadIdx.x;
    const int lane = tid & 31;
    const int wid = tid >> 5;
    const int wm = wid & 1;
    const int wn = wid >> 1;
    const int row0 = blockIdx.y * BM;
    const int col0 = blockIdx.x * BN;

    float acc[4][4][4];
#pragma unroll
    for (int i = 0; i < 4; i++)
#pragma unroll
        for (int j = 0; j < 4; j++)
#pragma unroll
            for (int r = 0; r < 4; r++) acc[i][j][r] = 0.f;

    const int TOT = K / BK;

    const int a_r0 = (tid * 2) >> 2, a_c0 = ((tid * 2) & 3) * 8;
    const int a_r1 = (tid * 2 + 1) >> 2, a_c1 = ((tid * 2 + 1) & 3) * 8;
    const int b_r0 = (tid * 2) >> 4, b_c0 = ((tid * 2) & 15) * 8;
    const int b_r1 = (tid * 2 + 1) >> 4, b_c1 = ((tid * 2 + 1) & 15) * 8;

#define LOAD_STAGE(IT, BUF) do {                                               \
    int k0_ = (IT) * BK;                                                       \
    __nv_bfloat16* sa_hi = smem + (BUF) * STAGE_ELEM;                          \
    __nv_bfloat16* sa_lo = sa_hi + A_ELEM;                                     \
    __nv_bfloat16* sb_hi = sa_lo + A_ELEM;                                     \
    __nv_bfloat16* sb_lo = sb_hi + B_ELEM;                                     \
    CP_ASYNC16((uint32_t)__cvta_generic_to_shared(&sa_hi[a_r0 * ASTR + a_c0]), \
               Ahi + (size_t)(row0 + a_r0) * K + k0_ + a_c0);                  \
    CP_ASYNC16((uint32_t)__cvta_generic_to_shared(&sa_hi[a_r1 * ASTR + a_c1]), \
               Ahi + (size_t)(row0 + a_r1) * K + k0_ + a_c1);                  \
    CP_ASYNC16((uint32_t)__cvta_generic_to_shared(&sa_lo[a_r0 * ASTR + a_c0]), \
               Alo + (size_t)(row0 + a_r0) * K + k0_ + a_c0);                  \
    CP_ASYNC16((uint32_t)__cvta_generic_to_shared(&sa_lo[a_r1 * ASTR + a_c1]), \
               Alo + (size_t)(row0 + a_r1) * K + k0_ + a_c1);                  \
    CP_ASYNC16((uint32_t)__cvta_generic_to_shared(&sb_hi[b_r0 * BSTR + b_c0]), \
               Bhi + (size_t)(k0_ + b_r0) * N + col0 + b_c0);                  \
    CP_ASYNC16((uint32_t)__cvta_generic_to_shared(&sb_hi[b_r1 * BSTR + b_c1]), \
               Bhi + (size_t)(k0_ + b_r1) * N + col0 + b_c1);                  \
    CP_ASYNC16((uint32_t)__cvta_generic_to_shared(&sb_lo[b_r0 * BSTR + b_c0]), \
               Blo + (size_t)(k0_ + b_r0) * N + col0 + b_c0);                  \
    CP_ASYNC16((uint32_t)__cvta_generic_to_shared(&sb_lo[b_r1 * BSTR + b_c1]), \
               Blo + (size_t)(k0_ + b_r1) * N + col0 + b_c1);                  \
} while (0)

    LOAD_STAGE(0, 0); CP_COMMIT;

    for (int it = 0; it < TOT; it++) {
        const int buf = it & 1;
        if (it + 1 < TOT) {
            LOAD_STAGE(it + 1, (it + 1) & 1);
            CP_COMMIT;
            CP_WAITG(1);
        } else {
            CP_WAITG(0);
        }
        __syncthreads();

        const __nv_bfloat16* sa_hi = smem + buf * STAGE_ELEM;
        const __nv_bfloat16* sa_lo = sa_hi + A_ELEM;
        const __nv_bfloat16* sb_hi = sa_lo + A_ELEM;
        const __nv_bfloat16* sb_lo = sb_hi + B_ELEM;

#pragma unroll
        for (int ks = 0; ks < 2; ks++) {
            uint32_t ahi[4][4], alo[4][4], bhi[2][4], blo[2][4];
#pragma unroll
            for (int mi = 0; mi < 4; mi++) {
                int roff = (wm * 64 + mi * 16 + (lane & 15)) * ASTR +
                           ks * 16 + (lane >> 4) * 8;
                ldsm4(ahi[mi], &sa_hi[roff]);
                ldsm4(alo[mi], &sa_lo[roff]);
            }
#pragma unroll
            for (int bi = 0; bi < 2; bi++) {
                int boff = (ks * 16 + (lane & 15)) * BSTR +
                           wn * 32 + bi * 16 + (lane >> 4) * 8;
                ldsm4t(bhi[bi], &sb_hi[boff]);
                ldsm4t(blo[bi], &sb_lo[boff]);
            }
#pragma unroll
            for (int mi = 0; mi < 4; mi++)
#pragma unroll
                for (int ni = 0; ni < 4; ni++) {
                    int g = ni >> 1, p = (ni & 1) * 2;
                    mma_bf16(acc[mi][ni], ahi[mi], bhi[g][p], bhi[g][p + 1]);
                    mma_bf16(acc[mi][ni], ahi[mi], blo[g][p], blo[g][p + 1]);
                    mma_bf16(acc[mi][ni], alo[mi], bhi[g][p], bhi[g][p + 1]);
                }
        }
        __syncthreads();
    }

    const int g = lane >> 2;
    const int t = lane & 3;
#pragma unroll
    for (int ni = 0; ni < 4; ni++) {
        int col = col0 + wn * 32 + ni * 8 + t * 2;
        float b0 = bias[col], b1 = bias[col + 1];
#pragma unroll
        for (int mi = 0; mi < 4; mi++) {
            int row = row0 + wm * 64 + mi * 16 + g;
            float2 o0 = { acc[mi][ni][0] + b0, acc[mi][ni][1] + b1 };
            float2 o1 = { acc[mi][ni][2] + b0, acc[mi][ni][3] + b1 };
            *(float2*)&C[(size_t)row * N + col] = o0;
            *(float2*)&C[(size_t)(row + 8) * N + col] = o1;
        }
    }
}

// ---------------- cw = softmax(query @ Wc + bc, axis=H) --------------------
__global__ __launch_bounds__(128) void cw_kernel(
    const float* __restrict__ query, const float* __restrict__ Wc,
    const float* __restrict__ bc, float* __restrict__ CW)
{
    __shared__ float qs[8][1024];
    const int tid = threadIdx.x;
    const int row0 = blockIdx.x * 8;

    for (int idx = tid; idx < 2048; idx += 128) {
        int r = idx >> 8;
        int c4 = (idx & 255) * 4;
        *(float4*)&qs[r][c4] = *(const float4*)&query[(size_t)(row0 + r) * EMB + c4];
    }
    __syncthreads();

    const int r = tid >> 4;
    const int h = tid & 15;
    const float* q = &qs[r][0];

    float a0 = 0.f, a1 = 0.f, a2 = 0.f, a3 = 0.f;
#pragma unroll 4
    for (int i = 0; i < EMB; i += 4) {
        a0 += q[i + 0] * Wc[(i + 0) * NH + h];
        a1 += q[i + 1] * Wc[(i + 1) * NH + h];
        a2 += q[i + 2] * Wc[(i + 2) * NH + h];
        a3 += q[i + 3] * Wc[(i + 3) * NH + h];
    }
    float acc = bc[h] + (a0 + a1) + (a2 + a3);

    float m = acc;
#pragma unroll
    for (int o = 8; o > 0; o >>= 1) m = fmaxf(m, __shfl_xor_sync(0xffffffffu, m, o, 16));
    float e = fast_exp(acc - m);
    float s = e;
#pragma unroll
    for (int o = 8; o > 0; o >>= 1) s += __shfl_xor_sync(0xffffffffu, s, o, 16);
    CW[(size_t)(row0 + r) * NH + h] = e / s;
}

// ---------------- suffix sums of V ------------------------------------------
__global__ __launch_bounds__(256) void vsuffix_kernel(
    const float* __restrict__ V, float* __restrict__ Suf)
{
    __shared__ float T[4][64];
    const int bh = blockIdx.x;
    const int b = bh >> 4;
    const int h = bh & 15;
    const int t = threadIdx.x;
    const int p = t >> 6;
    const int d = t & 63;

    const float* vb = V + (size_t)b * SEQ * EMB + h * HD + d;
    float* sufb = Suf + (size_t)bh * SEQ * HD + d;

    const int k0 = p * 256;
    float s = 0.f;
    for (int k = k0; k < k0 + 256; k++) s += vb[(size_t)k * EMB];
    T[p][d] = s;
    __syncthreads();

    float acc = 0.f;
    for (int pp = p + 1; pp < 4; pp++) acc += T[pp][d];
    for (int k = k0 + 255; k >= k0; k--) {
        sufb[(size_t)k * HD] = acc;
        acc += vb[(size_t)k * EMB];
    }
}

// ---------------- tensor-core attention -------------------------------------
// Block: one (b,h), 32 q rows, 256 threads (8 warps), 1 CTA/SM.
#define AR 32
#define QSS 72          // q/k/v smem row stride (bf16); 144B -> 4-bank row step
#define WSS 136         // w tile row stride (bf16); 272B -> 4-bank row step
#define EST 1036        // esc row stride (fp32); 4144B, /16 ok, rows spread banks
#define ESC_BYTES (AR * EST * 4)                    // 132608
#define KV_OFF    ESC_BYTES
#define KV_BYTES  (128 * QSS * 2)                   // 18432
#define QH_OFF    (KV_OFF + 2 * KV_BYTES)           // 169472
#define QMAT_BYTES (AR * QSS * 2)                   // 4608
#define WH_OFF    (QH_OFF + 2 * QMAT_BYTES)         // 178688
#define WMAT_BYTES (AR * WSS * 2)                   // 8704
#define ATTN_SMEM (WH_OFF + 2 * WMAT_BYTES)         // 196096

__global__ __launch_bounds__(256, 1) void attn_mma_kernel(
    const __nv_bfloat16* __restrict__ Qhi, const __nv_bfloat16* __restrict__ Qlo,
    const __nv_bfloat16* __restrict__ Khi, const __nv_bfloat16* __restrict__ Klo,
    const __nv_bfloat16* __restrict__ Vhi, const __nv_bfloat16* __restrict__ Vlo,
    const float* __restrict__ CW, const float* __restrict__ cons,
    const float* __restrict__ Suf, float* __restrict__ attn_out,
    float* __restrict__ ctx)
{
    extern __shared__ __align__(16) char smraw[];
    float* esc = (float*)smraw;
    __nv_bfloat16* kv_hi = (__nv_bfloat16*)(smraw + KV_OFF);
    __nv_bfloat16* kv_lo = (__nv_bfloat16*)(smraw + KV_OFF + KV_BYTES);
    __nv_bfloat16* q_hi  = (__nv_bfloat16*)(smraw + QH_OFF);
    __nv_bfloat16* q_lo  = (__nv_bfloat16*)(smraw + QH_OFF + QMAT_BYTES);
    __nv_bfloat16* w_hi  = (__nv_bfloat16*)(smraw + WH_OFF);
    __nv_bfloat16* w_lo  = (__nv_bfloat16*)(smraw + WH_OFF + WMAT_BYTES);
    __shared__ float zinv[AR];

    const int tid = threadIdx.x;
    const int lane = tid & 31;
    const int w = tid >> 5;
    const int bh = blockIdx.y;
    const int b = bh >> 4;
    const int h = bh & 15;
    const int q0 = (gridDim.x - 1 - blockIdx.x) * AR;   // heavy blocks first
    const int kmax = q0 + AR;
    const float INV_SCALE = 1.0f / (8.0f * sqrtf(1.61803398874989485f));

    // ---- stage Q (hi/lo): 512 x 16B chunks ----
#pragma unroll
    for (int li = 0; li < 2; li++) {
        int c = tid + li * 256;
        int r = (c & 255) >> 3;
        int c16 = c & 7;
        const __nv_bfloat16* src = ((c < 256) ? Qhi : Qlo)
            + (size_t)(b * SEQ + q0 + r) * EMB + h * HD + c16 * 8;
        __nv_bfloat16* dst = ((c < 256) ? q_hi : q_lo) + r * QSS + c16 * 8;
        CP_ASYNC16((uint32_t)__cvta_generic_to_shared(dst), src);
    }
    CP_COMMIT;

    // ---- phase 1: scores via mma (warp w owns k-cols w*16..w*16+15) ----
    for (int kt = 0; kt < kmax; kt += 128) {
#pragma unroll
        for (int li = 0; li < 4; li++) {
            int c = tid + li * 256;             // 0..1023
            int r = c >> 3, c16 = c & 7;
            size_t goff = (size_t)(b * SEQ + kt + r) * EMB + h * HD + c16 * 8;
            CP_ASYNC16((uint32_t)__cvta_generic_to_shared(kv_hi + r * QSS + c16 * 8), Khi + goff);
            CP_ASYNC16((uint32_t)__cvta_generic_to_shared(kv_lo + r * QSS + c16 * 8), Klo + goff);
        }
        CP_COMMIT;
        CP_WAITG(0);
        __syncthreads();

        float accs[2][2][4];
#pragma unroll
        for (int m = 0; m < 2; m++)
#pragma unroll
            for (int n = 0; n < 2; n++)
#pragma unroll
                for (int r = 0; r < 4; r++) accs[m][n][r] = 0.f;

#pragma unroll
        for (int ks = 0; ks < 4; ks++) {
            const int arow = lane & 15;
            const int acol = ks * 16 + (lane >> 4) * 8;
            uint32_t qh[2][4], ql[2][4], kh[4], kl[4];
#pragma unroll
            for (int m = 0; m < 2; m++) {
                ldsm4(qh[m], q_hi + (m * 16 + arow) * QSS + acol);
                ldsm4(ql[m], q_lo + (m * 16 + arow) * QSS + acol);
            }
            ldsm4(kh, kv_hi + (w * 16 + arow) * QSS + acol);
            ldsm4(kl, kv_lo + (w * 16 + arow) * QSS + acol);
#pragma unroll
            for (int m = 0; m < 2; m++)
#pragma unroll
                for (int n8 = 0; n8 < 2; n8++) {
                    mma_bf16(accs[m][n8], qh[m], kh[n8], kh[n8 + 2]);
                    mma_bf16(accs[m][n8], qh[m], kl[n8], kl[n8 + 2]);
                    mma_bf16(accs[m][n8], ql[m], kh[n8], kh[n8 + 2]);
                }
        }
        // epilogue: C frag -> esc fp32 (scaled)
#pragma unroll
        for (int m = 0; m < 2; m++)
#pragma unroll
            for (int n8 = 0; n8 < 2; n8++) {
                int row = m * 16 + (lane >> 2);
                int col = kt + w * 16 + n8 * 8 + (lane & 3) * 2;
                float2 lo = { accs[m][n8][0] * INV_SCALE, accs[m][n8][1] * INV_SCALE };
                float2 hi = { accs[m][n8][2] * INV_SCALE, accs[m][n8][3] * INV_SCALE };
                *(float2*)&esc[row * EST + col] = lo;
                *(float2*)&esc[(row + 8) * EST + col] = hi;
            }
        __syncthreads();
    }

    // ---- phase 2: softmax1 -> rescale -> softmax2 numerators ----
    {
#pragma unroll
        for (int rr = 0; rr < 4; rr++) {
            int r = w * 4 + rr;
            int q = q0 + r;
            int kc = q + 1;
            float* row = &esc[r * EST];

            float m = -1e30f;
            for (int k = lane; k < kc; k += 32) m = fmaxf(m, row[k]);
#pragma unroll
            for (int o = 16; o > 0; o >>= 1) m = fmaxf(m, __shfl_xor_sync(0xffffffffu, m, o));

            float s = 0.f;
            for (int k = lane; k < kc; k += 32) {
                float p = fast_exp(row[k] - m);
                row[k] = p;
                s += p;
            }
#pragma unroll
            for (int o = 16; o > 0; o >>= 1) s += __shfl_xor_sync(0xffffffffu, s, o);

            float cb = cons[b * SEQ + q];
            float cwv = CW[(size_t)(b * SEQ + q) * NH + h];
            float fs = (1.f + cb * cwv) / s;

            float z2 = 0.f;
            for (int k = lane; k < kc; k += 32) {
                float e = fast_exp(row[k] * fs);
                row[k] = e;
                z2 += e;
            }
            // masked region: attn1=0 -> exp(0)=1 (2nd softmax unmasked)
            for (int k = kc + lane; k < SEQ; k += 32) row[k] = 1.f;
#pragma unroll
            for (int o = 16; o > 0; o >>= 1) z2 += __shfl_xor_sync(0xffffffffu, z2, o);
            z2 += (float)(SEQ - kc);
            if (lane == 0) zinv[r] = 1.f / z2;
        }
    }
    __syncthreads();

    // ---- write final attn ----
    {
        const size_t abase = ((size_t)bh * SEQ + q0) * SEQ;
#pragma unroll 4
        for (int it = 0; it < AR; it++) {
            int idx4 = tid + it * 256;
            int r = idx4 >> 8;
            int c4 = (idx4 & 255) * 4;
            float zi = zinv[r];
            float4 v = *(float4*)&esc[r * EST + c4];
            v.x *= zi; v.y *= zi; v.z *= zi; v.w *= zi;
            *(float4*)&attn_out[abase + (size_t)r * SEQ + c4] = v;
        }
    }
    __syncthreads();

    // ---- zero weights for k > q within covered tiles ----
    {
        int r = tid >> 3;
        int q = q0 + r;
        int j = tid & 7;
        int tile_end = ((kmax + 127) >> 7) << 7;
        float* row = &esc[r * EST];
        for (int k = q + 1 + j; k < tile_end; k += 8) row[k] = 0.f;
    }
    __syncthreads();

    // ---- phase 3: ctx via mma. warp = (wm: m16 half, wn: d16 quarter) ----
    const int wm = w & 1;
    const int wn = w >> 1;
    float accc[2][4];
#pragma unroll
    for (int n = 0; n < 2; n++)
#pragma unroll
        for (int r = 0; r < 4; r++) accc[n][r] = 0.f;

    for (int kt = 0; kt < kmax; kt += 128) {
#pragma unroll
        for (int li = 0; li < 4; li++) {
            int c = tid + li * 256;
            int r = c >> 3, c16 = c & 7;
            size_t goff = (size_t)(b * SEQ + kt + r) * EMB + h * HD + c16 * 8;
            CP_ASYNC16((uint32_t)__cvta_generic_to_shared(kv_hi + r * QSS + c16 * 8), Vhi + goff);
            CP_ASYNC16((uint32_t)__cvta_generic_to_shared(kv_lo + r * QSS + c16 * 8), Vlo + goff);
        }
        CP_COMMIT;

        // convert weight tile esc[32][kt..kt+128] -> bf16 hi/lo
#pragma unroll
        for (int e = 0; e < 16; e++) {
            int elem = tid + e * 256;
            int row = elem >> 7, col = elem & 127;
            float v = esc[row * EST + kt + col];
            __nv_bfloat16 hv = __float2bfloat16(v);
            w_hi[row * WSS + col] = hv;
            w_lo[row * WSS + col] = __float2bfloat16(v - __bfloat162float(hv));
        }
        CP_WAITG(0);
        __syncthreads();

#pragma unroll
        for (int ks = 0; ks < 8; ks++) {
            const int arow = lane & 15;
            const int ahalf = (lane >> 4) * 8;
            uint32_t wh[4], wl[4], vh[4], vl[4];
            ldsm4(wh, w_hi + (wm * 16 + arow) * WSS + ks * 16 + ahalf);
            ldsm4(wl, w_lo + (wm * 16 + arow) * WSS + ks * 16 + ahalf);
            ldsm4t(vh, kv_hi + (ks * 16 + arow) * QSS + wn * 16 + ahalf);
            ldsm4t(vl, kv_lo + (ks * 16 + arow) * QSS + wn * 16 + ahalf);
#pragma unroll
            for (int n8 = 0; n8 < 2; n8++) {
                mma_bf16(accc[n8], wh, vh[n8 * 2], vh[n8 * 2 + 1]);
                mma_bf16(accc[n8], wh, vl[n8 * 2], vl[n8 * 2 + 1]);
                mma_bf16(accc[n8], wl, vh[n8 * 2], vh[n8 * 2 + 1]);
            }
        }
        __syncthreads();
    }

    // ---- ctx epilogue: + SufV, * zinv ----
#pragma unroll
    for (int n8 = 0; n8 < 2; n8++) {
        int r0 = wm * 16 + (lane >> 2);
        int dc = wn * 16 + n8 * 8 + (lane & 3) * 2;
        float zi0 = zinv[r0];
        float zi8 = zinv[r0 + 8];
        float2 s0 = *(const float2*)&Suf[((size_t)bh * SEQ + q0 + r0) * HD + dc];
        float2 s8 = *(const float2*)&Suf[((size_t)bh * SEQ + q0 + r0 + 8) * HD + dc];
        float2 o0 = { (accc[n8][0] + s0.x) * zi0, (accc[n8][1] + s0.y) * zi0 };
        float2 o8 = { (accc[n8][2] + s8.x) * zi8, (accc[n8][3] + s8.y) * zi8 };
        *(float2*)&ctx[((size_t)(b * SEQ + q0 + r0)) * EMB + h * HD + dc] = o0;
        *(float2*)&ctx[((size_t)(b * SEQ + q0 + r0 + 8)) * EMB + h * HD + dc] = o8;
    }
}

// ---------------- launch ----------------------------------------------------
extern "C" void kernel_launch(void* const* d_in, const int* in_sizes, int n_in,
                              void* d_out, int out_size)
{
    const float* query = (const float*)d_in[0];
    const float* key   = (const float*)d_in[1];
    const float* value = (const float*)d_in[2];
    const float* cons  = (const float*)d_in[3];
    const float* Wq = (const float*)d_in[5];
    const float* bq = (const float*)d_in[6];
    const float* Wk = (const float*)d_in[7];
    const float* bk = (const float*)d_in[8];
    const float* Wv = (const float*)d_in[9];
    const float* bv = (const float*)d_in[10];
    const float* Wo = (const float*)d_in[11];
    const float* bo = (const float*)d_in[12];
    const float* Wc = (const float*)d_in[13];
    const float* bc = (const float*)d_in[14];

    float* qp; cudaGetSymbolAddress((void**)&qp, g_q);
    float* kp; cudaGetSymbolAddress((void**)&kp, g_k);
    float* vp; cudaGetSymbolAddress((void**)&vp, g_v);
    float* cp; cudaGetSymbolAddress((void**)&cp, g_ctx);
    float* cwp; cudaGetSymbolAddress((void**)&cwp, g_cw);
    float* sufp; cudaGetSymbolAddress((void**)&sufp, g_vsuf);
    __nv_bfloat16* ahi; cudaGetSymbolAddress((void**)&ahi, g_ahi);
    __nv_bfloat16* alo; cudaGetSymbolAddress((void**)&alo, g_alo);
    __nv_bfloat16* whi; cudaGetSymbolAddress((void**)&whi, g_whi);
    __nv_bfloat16* wlo; cudaGetSymbolAddress((void**)&wlo, g_wlo);

    float* out = (float*)d_out;
    float* attn_out = out + (size_t)BATCH * SEQ * EMB;

    const int M = BATCH * SEQ;
    const int A4 = M * EMB / 4;
    const int W4 = EMB * EMB / 4;
    const size_t AE = (size_t)M * EMB;
    const size_t WE = (size_t)EMB * EMB;
    dim3 gemm_grid(EMB / BN, M / BM);

    const int gemm_smem = STAGES * STAGE_ELEM * sizeof(__nv_bfloat16);
    cudaFuncSetAttribute(gemm_bf16x3f, cudaFuncAttributeMaxDynamicSharedMemorySize, gemm_smem);
    cudaFuncSetAttribute(attn_mma_kernel, cudaFuncAttributeMaxDynamicSharedMemorySize, ATTN_SMEM);

    // input splits for projection GEMMs
    dim3 sa_grid((A4 + 255) / 256, 3);
    split_act3_kernel<<<sa_grid, 256>>>(query, key, value, ahi, alo, A4);
    dim3 sw_grid((W4 + 255) / 256, 4);
    split_w4_kernel<<<sw_grid, 256>>>(Wq, Wk, Wv, Wo, whi, wlo, W4);

    gemm_bf16x3f<<<gemm_grid, 256, gemm_smem>>>(ahi,          alo,          whi,          wlo,          bq, qp, M, EMB, EMB);
    gemm_bf16x3f<<<gemm_grid, 256, gemm_smem>>>(ahi + AE,     alo + AE,     whi + WE,     wlo + WE,     bk, kp, M, EMB, EMB);
    gemm_bf16x3f<<<gemm_grid, 256, gemm_smem>>>(ahi + 2 * AE, alo + 2 * AE, whi + 2 * WE, wlo + 2 * WE, bv, vp, M, EMB, EMB);

    cw_kernel<<<M / 8, 128>>>(query, Wc, bc, cwp);
    vsuffix_kernel<<<BATCH * NH, 256>>>(vp, sufp);

    // re-split projected q/k/v into bf16 hi/lo (reuse ahi/alo slots)
    split_act3_kernel<<<sa_grid, 256>>>(qp, kp, vp, ahi, alo, A4);

    dim3 attn_grid(SEQ / AR, BATCH * NH);   // (32, 64)
    attn_mma_kernel<<<attn_grid, 256, ATTN_SMEM>>>(
        ahi,          alo,            // Q hi/lo
        ahi + AE,     alo + AE,       // K hi/lo
        ahi + 2 * AE, alo + 2 * AE,   // V hi/lo
        cwp, cons, sufp, attn_out, cp);

    split_kernel<<<(A4 + 255) / 256, 256>>>(cp, ahi, alo, A4);
    gemm_bf16x3f<<<gemm_grid, 256, gemm_smem>>>(ahi, alo, whi + 3 * WE, wlo + 3 * WE, bo, out, M, EMB, EMB);
}

// round 8
// speedup vs baseline: 3.6918x; 1.0101x over previous
#include <cuda_runtime.h>
#include <cuda_bf16.h>
#include <math.h>
#include <stdint.h>

#define EMB 1024
#define SEQ 1024
#define BATCH 4
#define NH 16
#define HD 64

// ---------------- scratch (device globals; no allocation allowed) ----------
// g_q/g_k/g_v/g_ctx hold bf16 hi|lo pairs now (each 16MB = 2 x 8MB bf16).
__device__ float g_q[BATCH * SEQ * EMB];
__device__ float g_k[BATCH * SEQ * EMB];
__device__ float g_v[BATCH * SEQ * EMB];
__device__ float g_ctx[BATCH * SEQ * EMB];
__device__ float g_cw[BATCH * SEQ * NH];
__device__ float g_vsuf[BATCH * NH * SEQ * HD];
__device__ __nv_bfloat16 g_ahi[3][BATCH * SEQ * EMB];
__device__ __nv_bfloat16 g_alo[3][BATCH * SEQ * EMB];
__device__ __nv_bfloat16 g_whi[4][EMB * EMB];
__device__ __nv_bfloat16 g_wlo[4][EMB * EMB];

// ---------------- fast exp: FFMA-only ---------------------------------------
__device__ __forceinline__ float fast_exp(float x)
{
    x = fmaxf(x, -80.0f);
    const float L2E = 1.4426950408889634f;
    float t = fmaf(x, L2E, 12582912.0f);
    float i = t - 12582912.0f;
    float f = fmaf(x, L2E, -i);
    float p = 1.3333558146e-3f;
    p = fmaf(p, f, 9.6181291918e-3f);
    p = fmaf(p, f, 5.5504108664e-2f);
    p = fmaf(p, f, 2.4022650696e-1f);
    p = fmaf(p, f, 6.9314718056e-1f);
    p = fmaf(p, f, 1.0f);
    return __int_as_float(__float_as_int(p) + ((int)i << 23));
}

// ---------------- mma / ldmatrix helpers -------------------------------------
__device__ __forceinline__ void ldsm4(uint32_t* r, const void* p)
{
    uint32_t a = (uint32_t)__cvta_generic_to_shared(p);
    asm volatile("ldmatrix.sync.aligned.m8n8.x4.shared.b16 {%0,%1,%2,%3},[%4];"
                 : "=r"(r[0]), "=r"(r[1]), "=r"(r[2]), "=r"(r[3]) : "r"(a));
}
__device__ __forceinline__ void ldsm4t(uint32_t* r, const void* p)
{
    uint32_t a = (uint32_t)__cvta_generic_to_shared(p);
    asm volatile("ldmatrix.sync.aligned.m8n8.x4.trans.shared.b16 {%0,%1,%2,%3},[%4];"
                 : "=r"(r[0]), "=r"(r[1]), "=r"(r[2]), "=r"(r[3]) : "r"(a));
}
__device__ __forceinline__ void mma_bf16(float* c, const uint32_t* a,
                                         uint32_t b0, uint32_t b1)
{
    asm volatile(
        "mma.sync.aligned.m16n8k16.row.col.f32.bf16.bf16.f32 "
        "{%0,%1,%2,%3},{%4,%5,%6,%7},{%8,%9},{%0,%1,%2,%3};"
        : "+f"(c[0]), "+f"(c[1]), "+f"(c[2]), "+f"(c[3])
        : "r"(a[0]), "r"(a[1]), "r"(a[2]), "r"(a[3]), "r"(b0), "r"(b1));
}

// ---------------- fp32 -> bf16 hi/lo split ----------------------------------
__device__ __forceinline__ void split4(
    const float* __restrict__ X, __nv_bfloat16* __restrict__ Hi,
    __nv_bfloat16* __restrict__ Lo, int i)
{
    float4 x = ((const float4*)X)[i];
    __nv_bfloat16 h0 = __float2bfloat16(x.x);
    __nv_bfloat16 h1 = __float2bfloat16(x.y);
    __nv_bfloat16 h2 = __float2bfloat16(x.z);
    __nv_bfloat16 h3 = __float2bfloat16(x.w);
    __nv_bfloat162 H0; H0.x = h0; H0.y = h1;
    __nv_bfloat162 H1; H1.x = h2; H1.y = h3;
    __nv_bfloat162 L0;
    L0.x = __float2bfloat16(x.x - __bfloat162float(h0));
    L0.y = __float2bfloat16(x.y - __bfloat162float(h1));
    __nv_bfloat162 L1;
    L1.x = __float2bfloat16(x.z - __bfloat162float(h2));
    L1.y = __float2bfloat16(x.w - __bfloat162float(h3));
    ((__nv_bfloat162*)Hi)[2 * i] = H0;
    ((__nv_bfloat162*)Hi)[2 * i + 1] = H1;
    ((__nv_bfloat162*)Lo)[2 * i] = L0;
    ((__nv_bfloat162*)Lo)[2 * i + 1] = L1;
}

__global__ __launch_bounds__(256) void split_act3_kernel(
    const float* __restrict__ X0, const float* __restrict__ X1,
    const float* __restrict__ X2, __nv_bfloat16* __restrict__ Hi,
    __nv_bfloat16* __restrict__ Lo, int n4)
{
    int i = blockIdx.x * 256 + threadIdx.x;
    if (i >= n4) return;
    int s = blockIdx.y;
    const float* X = (s == 0) ? X0 : (s == 1) ? X1 : X2;
    split4(X, Hi + (size_t)s * BATCH * SEQ * EMB,
           Lo + (size_t)s * BATCH * SEQ * EMB, i);
}

__global__ __launch_bounds__(256) void split_w4_kernel(
    const float* __restrict__ W0, const float* __restrict__ W1,
    const float* __restrict__ W2, const float* __restrict__ W3,
    __nv_bfloat16* __restrict__ Hi, __nv_bfloat16* __restrict__ Lo, int n4)
{
    int i = blockIdx.x * 256 + threadIdx.x;
    if (i >= n4) return;
    int s = blockIdx.y;
    const float* W = (s == 0) ? W0 : (s == 1) ? W1 : (s == 2) ? W2 : W3;
    split4(W, Hi + (size_t)s * EMB * EMB, Lo + (size_t)s * EMB * EMB, i);
}

// ---------------- fused bf16x3 tensor-core GEMM (3-stage ring) ---------------
// C = Ahi@Bhi + Ahi@Blo + Alo@Bhi + bias. Output fp32 (C) or bf16 hi/lo (Chi/Clo).
#define BM 128
#define BN 128
#define BK 32
#define ASTR 40
#define BSTR 136
#define GSTAGES 3
#define A_ELEM (BM * ASTR)
#define B_ELEM (BK * BSTR)
#define STAGE_ELEM (2 * A_ELEM + 2 * B_ELEM)

#define CP_ASYNC16(dst, src) \
    asm volatile("cp.async.cg.shared.global [%0], [%1], 16;\n" :: "r"(dst), "l"(src))
#define CP_COMMIT asm volatile("cp.async.commit_group;\n" ::)
#define CP_WAITG(n) asm volatile("cp.async.wait_group %0;\n" :: "n"(n))

__global__ __launch_bounds__(256, 2) void gemm_bf16x3f(
    const __nv_bfloat16* __restrict__ Ahi, const __nv_bfloat16* __restrict__ Alo,
    const __nv_bfloat16* __restrict__ Bhi, const __nv_bfloat16* __restrict__ Blo,
    const float* __restrict__ bias, float* __restrict__ C,
    __nv_bfloat16* __restrict__ Chi, __nv_bfloat16* __restrict__ Clo,
    int M, int N, int K)
{
    extern __shared__ __align__(16) __nv_bfloat16 smem[];

    const int tid = threadIdx.x;
    const int lane = tid & 31;
    const int wid = tid >> 5;
    const int wm = wid & 1;
    const int wn = wid >> 1;
    const int row0 = blockIdx.y * BM;
    const int col0 = blockIdx.x * BN;

    float acc[4][4][4];
#pragma unroll
    for (int i = 0; i < 4; i++)
#pragma unroll
        for (int j = 0; j < 4; j++)
#pragma unroll
            for (int r = 0; r < 4; r++) acc[i][j][r] = 0.f;

    const int TOT = K / BK;

    const int a_r0 = (tid * 2) >> 2, a_c0 = ((tid * 2) & 3) * 8;
    const int a_r1 = (tid * 2 + 1) >> 2, a_c1 = ((tid * 2 + 1) & 3) * 8;
    const int b_r0 = (tid * 2) >> 4, b_c0 = ((tid * 2) & 15) * 8;
    const int b_r1 = (tid * 2 + 1) >> 4, b_c1 = ((tid * 2 + 1) & 15) * 8;

#define LOAD_STAGE(IT, BUF) do {                                               \
    int k0_ = (IT) * BK;                                                       \
    __nv_bfloat16* sa_hi = smem + (BUF) * STAGE_ELEM;                          \
    __nv_bfloat16* sa_lo = sa_hi + A_ELEM;                                     \
    __nv_bfloat16* sb_hi = sa_lo + A_ELEM;                                     \
    __nv_bfloat16* sb_lo = sb_hi + B_ELEM;                                     \
    CP_ASYNC16((uint32_t)__cvta_generic_to_shared(&sa_hi[a_r0 * ASTR + a_c0]), \
               Ahi + (size_t)(row0 + a_r0) * K + k0_ + a_c0);                  \
    CP_ASYNC16((uint32_t)__cvta_generic_to_shared(&sa_hi[a_r1 * ASTR + a_c1]), \
               Ahi + (size_t)(row0 + a_r1) * K + k0_ + a_c1);                  \
    CP_ASYNC16((uint32_t)__cvta_generic_to_shared(&sa_lo[a_r0 * ASTR + a_c0]), \
               Alo + (size_t)(row0 + a_r0) * K + k0_ + a_c0);                  \
    CP_ASYNC16((uint32_t)__cvta_generic_to_shared(&sa_lo[a_r1 * ASTR + a_c1]), \
               Alo + (size_t)(row0 + a_r1) * K + k0_ + a_c1);                  \
    CP_ASYNC16((uint32_t)__cvta_generic_to_shared(&sb_hi[b_r0 * BSTR + b_c0]), \
               Bhi + (size_t)(k0_ + b_r0) * N + col0 + b_c0);                  \
    CP_ASYNC16((uint32_t)__cvta_generic_to_shared(&sb_hi[b_r1 * BSTR + b_c1]), \
               Bhi + (size_t)(k0_ + b_r1) * N + col0 + b_c1);                  \
    CP_ASYNC16((uint32_t)__cvta_generic_to_shared(&sb_lo[b_r0 * BSTR + b_c0]), \
               Blo + (size_t)(k0_ + b_r0) * N + col0 + b_c0);                  \
    CP_ASYNC16((uint32_t)__cvta_generic_to_shared(&sb_lo[b_r1 * BSTR + b_c1]), \
               Blo + (size_t)(k0_ + b_r1) * N + col0 + b_c1);                  \
} while (0)

    LOAD_STAGE(0, 0); CP_COMMIT;
    LOAD_STAGE(1, 1); CP_COMMIT;

    for (int it = 0; it < TOT; it++) {
        const int buf = it % GSTAGES;
        if (it + 2 < TOT) LOAD_STAGE(it + 2, (it + 2) % GSTAGES);
        CP_COMMIT;
        CP_WAITG(2);
        __syncthreads();

        const __nv_bfloat16* sa_hi = smem + buf * STAGE_ELEM;
        const __nv_bfloat16* sa_lo = sa_hi + A_ELEM;
        const __nv_bfloat16* sb_hi = sa_lo + A_ELEM;
        const __nv_bfloat16* sb_lo = sb_hi + B_ELEM;

#pragma unroll
        for (int ks = 0; ks < 2; ks++) {
            uint32_t ahi[4][4], alo[4][4], bhi[2][4], blo[2][4];
#pragma unroll
            for (int mi = 0; mi < 4; mi++) {
                int roff = (wm * 64 + mi * 16 + (lane & 15)) * ASTR +
                           ks * 16 + (lane >> 4) * 8;
                ldsm4(ahi[mi], &sa_hi[roff]);
                ldsm4(alo[mi], &sa_lo[roff]);
            }
#pragma unroll
            for (int bi = 0; bi < 2; bi++) {
                int boff = (ks * 16 + (lane & 15)) * BSTR +
                           wn * 32 + bi * 16 + (lane >> 4) * 8;
                ldsm4t(bhi[bi], &sb_hi[boff]);
                ldsm4t(blo[bi], &sb_lo[boff]);
            }
#pragma unroll
            for (int mi = 0; mi < 4; mi++)
#pragma unroll
                for (int ni = 0; ni < 4; ni++) {
                    int g = ni >> 1, p = (ni & 1) * 2;
                    mma_bf16(acc[mi][ni], ahi[mi], bhi[g][p], bhi[g][p + 1]);
                    mma_bf16(acc[mi][ni], ahi[mi], blo[g][p], blo[g][p + 1]);
                    mma_bf16(acc[mi][ni], alo[mi], bhi[g][p], bhi[g][p + 1]);
                }
        }
        __syncthreads();
    }

    const int g = lane >> 2;
    const int t = lane & 3;
#pragma unroll
    for (int ni = 0; ni < 4; ni++) {
        int col = col0 + wn * 32 + ni * 8 + t * 2;
        float b0 = bias[col], b1 = bias[col + 1];
#pragma unroll
        for (int mi = 0; mi < 4; mi++) {
            int row = row0 + wm * 64 + mi * 16 + g;
            float v00 = acc[mi][ni][0] + b0, v01 = acc[mi][ni][1] + b1;
            float v10 = acc[mi][ni][2] + b0, v11 = acc[mi][ni][3] + b1;
            if (Chi) {
                __nv_bfloat162 h0, l0, h1, l1;
                h0.x = __float2bfloat16(v00);
                h0.y = __float2bfloat16(v01);
                l0.x = __float2bfloat16(v00 - __bfloat162float(h0.x));
                l0.y = __float2bfloat16(v01 - __bfloat162float(h0.y));
                h1.x = __float2bfloat16(v10);
                h1.y = __float2bfloat16(v11);
                l1.x = __float2bfloat16(v10 - __bfloat162float(h1.x));
                l1.y = __float2bfloat16(v11 - __bfloat162float(h1.y));
                *(__nv_bfloat162*)&Chi[(size_t)row * N + col] = h0;
                *(__nv_bfloat162*)&Clo[(size_t)row * N + col] = l0;
                *(__nv_bfloat162*)&Chi[(size_t)(row + 8) * N + col] = h1;
                *(__nv_bfloat162*)&Clo[(size_t)(row + 8) * N + col] = l1;
            } else {
                float2 o0 = { v00, v01 };
                float2 o1 = { v10, v11 };
                *(float2*)&C[(size_t)row * N + col] = o0;
                *(float2*)&C[(size_t)(row + 8) * N + col] = o1;
            }
        }
    }
}

// ---------------- cw = softmax(query @ Wc + bc, axis=H) --------------------
__global__ __launch_bounds__(128) void cw_kernel(
    const float* __restrict__ query, const float* __restrict__ Wc,
    const float* __restrict__ bc, float* __restrict__ CW)
{
    __shared__ float qs[8][1024];
    const int tid = threadIdx.x;
    const int row0 = blockIdx.x * 8;

    for (int idx = tid; idx < 2048; idx += 128) {
        int r = idx >> 8;
        int c4 = (idx & 255) * 4;
        *(float4*)&qs[r][c4] = *(const float4*)&query[(size_t)(row0 + r) * EMB + c4];
    }
    __syncthreads();

    const int r = tid >> 4;
    const int h = tid & 15;
    const float* q = &qs[r][0];

    float a0 = 0.f, a1 = 0.f, a2 = 0.f, a3 = 0.f;
#pragma unroll 4
    for (int i = 0; i < EMB; i += 4) {
        a0 += q[i + 0] * Wc[(i + 0) * NH + h];
        a1 += q[i + 1] * Wc[(i + 1) * NH + h];
        a2 += q[i + 2] * Wc[(i + 2) * NH + h];
        a3 += q[i + 3] * Wc[(i + 3) * NH + h];
    }
    float acc = bc[h] + (a0 + a1) + (a2 + a3);

    float m = acc;
#pragma unroll
    for (int o = 8; o > 0; o >>= 1) m = fmaxf(m, __shfl_xor_sync(0xffffffffu, m, o, 16));
    float e = fast_exp(acc - m);
    float s = e;
#pragma unroll
    for (int o = 8; o > 0; o >>= 1) s += __shfl_xor_sync(0xffffffffu, s, o, 16);
    CW[(size_t)(row0 + r) * NH + h] = e / s;
}

// ---------------- suffix sums of V (from bf16 hi/lo) -------------------------
__global__ __launch_bounds__(256) void vsuffix_hl_kernel(
    const __nv_bfloat16* __restrict__ Vhi, const __nv_bfloat16* __restrict__ Vlo,
    float* __restrict__ Suf)
{
    __shared__ float T[4][64];
    const int bh = blockIdx.x;
    const int b = bh >> 4;
    const int h = bh & 15;
    const int t = threadIdx.x;
    const int p = t >> 6;
    const int d = t & 63;

    const size_t base = (size_t)b * SEQ * EMB + h * HD + d;
    float* sufb = Suf + (size_t)bh * SEQ * HD + d;

    const int k0 = p * 256;
    float s = 0.f;
    for (int k = k0; k < k0 + 256; k++) {
        size_t o = base + (size_t)k * EMB;
        s += __bfloat162float(Vhi[o]) + __bfloat162float(Vlo[o]);
    }
    T[p][d] = s;
    __syncthreads();

    float acc = 0.f;
    for (int pp = p + 1; pp < 4; pp++) acc += T[pp][d];
    for (int k = k0 + 255; k >= k0; k--) {
        size_t o = base + (size_t)k * EMB;
        sufb[(size_t)k * HD] = acc;
        acc += __bfloat162float(Vhi[o]) + __bfloat162float(Vlo[o]);
    }
}

// ---------------- tensor-core attention (register-pipelined) -----------------
#define AR 32
#define QSS 72
#define WSS 136
#define EST 1036
#define ESC_BYTES (AR * EST * 4)
#define KV_OFF    ESC_BYTES
#define KV_BYTES  (128 * QSS * 2)
#define QH_OFF    (KV_OFF + 2 * KV_BYTES)
#define QMAT_BYTES (AR * QSS * 2)
#define WH_OFF    (QH_OFF + 2 * QMAT_BYTES)
#define WMAT_BYTES (AR * WSS * 2)
#define ATTN_SMEM (WH_OFF + 2 * WMAT_BYTES)

__device__ __forceinline__ void stage_kv128(
    const __nv_bfloat16* __restrict__ Ghi, const __nv_bfloat16* __restrict__ Glo,
    __nv_bfloat16* s_hi, __nv_bfloat16* s_lo, int b, int h, int kt, int tid)
{
#pragma unroll
    for (int li = 0; li < 4; li++) {
        int c = tid + li * 256;
        int r = c >> 3, c16 = c & 7;
        size_t goff = (size_t)(b * SEQ + kt + r) * EMB + h * HD + c16 * 8;
        CP_ASYNC16((uint32_t)__cvta_generic_to_shared(s_hi + r * QSS + c16 * 8), Ghi + goff);
        CP_ASYNC16((uint32_t)__cvta_generic_to_shared(s_lo + r * QSS + c16 * 8), Glo + goff);
    }
}

__global__ __launch_bounds__(256, 1) void attn_mma_kernel(
    const __nv_bfloat16* __restrict__ Qhi, const __nv_bfloat16* __restrict__ Qlo,
    const __nv_bfloat16* __restrict__ Khi, const __nv_bfloat16* __restrict__ Klo,
    const __nv_bfloat16* __restrict__ Vhi, const __nv_bfloat16* __restrict__ Vlo,
    const float* __restrict__ CW, const float* __restrict__ cons,
    const float* __restrict__ Suf, float* __restrict__ attn_out,
    __nv_bfloat16* __restrict__ Chi, __nv_bfloat16* __restrict__ Clo)
{
    extern __shared__ __align__(16) char smraw[];
    float* esc = (float*)smraw;
    __nv_bfloat16* kv_hi = (__nv_bfloat16*)(smraw + KV_OFF);
    __nv_bfloat16* kv_lo = (__nv_bfloat16*)(smraw + KV_OFF + KV_BYTES);
    __nv_bfloat16* q_hi  = (__nv_bfloat16*)(smraw + QH_OFF);
    __nv_bfloat16* q_lo  = (__nv_bfloat16*)(smraw + QH_OFF + QMAT_BYTES);
    __nv_bfloat16* w_hi  = (__nv_bfloat16*)(smraw + WH_OFF);
    __nv_bfloat16* w_lo  = (__nv_bfloat16*)(smraw + WH_OFF + WMAT_BYTES);
    __shared__ float zinv[AR];

    const int tid = threadIdx.x;
    const int lane = tid & 31;
    const int w = tid >> 5;
    const int bh = blockIdx.y;
    const int b = bh >> 4;
    const int h = bh & 15;
    const int q0 = (gridDim.x - 1 - blockIdx.x) * AR;   // heavy blocks first
    const int kmax = q0 + AR;
    const int ntiles = (kmax + 127) >> 7;
    const float INV_SCALE = 1.0f / (8.0f * sqrtf(1.61803398874989485f));

    // ---- stage Q (group 0) ----
#pragma unroll
    for (int li = 0; li < 2; li++) {
        int c = tid + li * 256;
        int r = (c & 255) >> 3;
        int c16 = c & 7;
        const __nv_bfloat16* src = ((c < 256) ? Qhi : Qlo)
            + (size_t)(b * SEQ + q0 + r) * EMB + h * HD + c16 * 8;
        __nv_bfloat16* dst = ((c < 256) ? q_hi : q_lo) + r * QSS + c16 * 8;
        CP_ASYNC16((uint32_t)__cvta_generic_to_shared(dst), src);
    }
    CP_COMMIT;
    // ---- K tile 0 (group 1) ----
    stage_kv128(Khi, Klo, kv_hi, kv_lo, b, h, 0, tid);
    CP_COMMIT;

    // ---- preload Q fragments to registers (Q group retired; K0 in flight) ----
    CP_WAITG(1);
    __syncthreads();
    uint32_t qh[4][2][4], ql[4][2][4];
#pragma unroll
    for (int ks = 0; ks < 4; ks++) {
        const int arow = lane & 15;
        const int acol = ks * 16 + (lane >> 4) * 8;
#pragma unroll
        for (int m = 0; m < 2; m++) {
            ldsm4(qh[ks][m], q_hi + (m * 16 + arow) * QSS + acol);
            ldsm4(ql[ks][m], q_lo + (m * 16 + arow) * QSS + acol);
        }
    }

    // ---- phase 1: scores (K frags -> regs, next tile load overlaps mma) ----
    for (int t = 0; t < ntiles; t++) {
        const int kt = t * 128;
        CP_WAITG(0);
        __syncthreads();

        uint32_t kh[4][4], kl[4][4];
#pragma unroll
        for (int ks = 0; ks < 4; ks++) {
            const int arow = lane & 15;
            const int acol = ks * 16 + (lane >> 4) * 8;
            ldsm4(kh[ks], kv_hi + (w * 16 + arow) * QSS + acol);
            ldsm4(kl[ks], kv_lo + (w * 16 + arow) * QSS + acol);
        }
        __syncthreads();
        if (t + 1 < ntiles) {
            stage_kv128(Khi, Klo, kv_hi, kv_lo, b, h, kt + 128, tid);
            CP_COMMIT;
        }

        float accs[2][2][4];
#pragma unroll
        for (int m = 0; m < 2; m++)
#pragma unroll
            for (int n = 0; n < 2; n++)
#pragma unroll
                for (int r = 0; r < 4; r++) accs[m][n][r] = 0.f;

#pragma unroll
        for (int ks = 0; ks < 4; ks++)
#pragma unroll
            for (int m = 0; m < 2; m++)
#pragma unroll
                for (int n8 = 0; n8 < 2; n8++) {
                    mma_bf16(accs[m][n8], qh[ks][m], kh[ks][n8], kh[ks][n8 + 2]);
                    mma_bf16(accs[m][n8], qh[ks][m], kl[ks][n8], kl[ks][n8 + 2]);
                    mma_bf16(accs[m][n8], ql[ks][m], kh[ks][n8], kh[ks][n8 + 2]);
                }
#pragma unroll
        for (int m = 0; m < 2; m++)
#pragma unroll
            for (int n8 = 0; n8 < 2; n8++) {
                int row = m * 16 + (lane >> 2);
                int col = kt + w * 16 + n8 * 8 + (lane & 3) * 2;
                float2 lo = { accs[m][n8][0] * INV_SCALE, accs[m][n8][1] * INV_SCALE };
                float2 hi = { accs[m][n8][2] * INV_SCALE, accs[m][n8][3] * INV_SCALE };
                *(float2*)&esc[row * EST + col] = lo;
                *(float2*)&esc[(row + 8) * EST + col] = hi;
            }
    }
    // kv buffer free now; start V tile 0 so it hides under softmax + attn write
    stage_kv128(Vhi, Vlo, kv_hi, kv_lo, b, h, 0, tid);
    CP_COMMIT;
    __syncthreads();

    // ---- phase 2: softmax1 -> rescale -> softmax2 numerators ----
    {
#pragma unroll
        for (int rr = 0; rr < 4; rr++) {
            int r = w * 4 + rr;
            int q = q0 + r;
            int kc = q + 1;
            float* row = &esc[r * EST];

            float m = -1e30f;
            for (int k = lane; k < kc; k += 32) m = fmaxf(m, row[k]);
#pragma unroll
            for (int o = 16; o > 0; o >>= 1) m = fmaxf(m, __shfl_xor_sync(0xffffffffu, m, o));

            float s = 0.f;
            for (int k = lane; k < kc; k += 32) {
                float p = fast_exp(row[k] - m);
                row[k] = p;
                s += p;
            }
#pragma unroll
            for (int o = 16; o > 0; o >>= 1) s += __shfl_xor_sync(0xffffffffu, s, o);

            float cb = cons[b * SEQ + q];
            float cwv = CW[(size_t)(b * SEQ + q) * NH + h];
            float fs = (1.f + cb * cwv) / s;

            float z2 = 0.f;
            for (int k = lane; k < kc; k += 32) {
                float e = fast_exp(row[k] * fs);
                row[k] = e;
                z2 += e;
            }
            // masked region: attn1=0 -> exp(0)=1 (2nd softmax unmasked)
            for (int k = kc + lane; k < SEQ; k += 32) row[k] = 1.f;
#pragma unroll
            for (int o = 16; o > 0; o >>= 1) z2 += __shfl_xor_sync(0xffffffffu, z2, o);
            z2 += (float)(SEQ - kc);
            if (lane == 0) zinv[r] = 1.f / z2;
        }
    }
    __syncthreads();

    // ---- write final attn ----
    {
        const size_t abase = ((size_t)bh * SEQ + q0) * SEQ;
#pragma unroll 4
        for (int it = 0; it < AR; it++) {
            int idx4 = tid + it * 256;
            int r = idx4 >> 8;
            int c4 = (idx4 & 255) * 4;
            float zi = zinv[r];
            float4 v = *(float4*)&esc[r * EST + c4];
            v.x *= zi; v.y *= zi; v.z *= zi; v.w *= zi;
            *(float4*)&attn_out[abase + (size_t)r * SEQ + c4] = v;
        }
    }
    __syncthreads();

    // ---- zero weights for k > q within covered tiles ----
    {
        int r = tid >> 3;
        int q = q0 + r;
        int j = tid & 7;
        int tile_end = ntiles * 128;
        float* row = &esc[r * EST];
        for (int k = q + 1 + j; k < tile_end; k += 8) row[k] = 0.f;
    }
    __syncthreads();

    // ---- phase 3: ctx via mma (V frags -> regs, next load overlaps mma) ----
    const int wm = w & 1;
    const int wn = w >> 1;
    float accc[2][4];
#pragma unroll
    for (int n = 0; n < 2; n++)
#pragma unroll
        for (int r = 0; r < 4; r++) accc[n][r] = 0.f;

    for (int t = 0; t < ntiles; t++) {
        const int kt = t * 128;
        // convert weight tile esc[32][kt..kt+128] -> bf16 hi/lo
#pragma unroll
        for (int e = 0; e < 16; e++) {
            int elem = tid + e * 256;
            int row = elem >> 7, col = elem & 127;
            float v = esc[row * EST + kt + col];
            __nv_bfloat16 hv = __float2bfloat16(v);
            w_hi[row * WSS + col] = hv;
            w_lo[row * WSS + col] = __float2bfloat16(v - __bfloat162float(hv));
        }
        CP_WAITG(0);
        __syncthreads();

        uint32_t vh[8][4], vl[8][4];
#pragma unroll
        for (int ks = 0; ks < 8; ks++) {
            const int arow = lane & 15;
            const int ahalf = (lane >> 4) * 8;
            ldsm4t(vh[ks], kv_hi + (ks * 16 + arow) * QSS + wn * 16 + ahalf);
            ldsm4t(vl[ks], kv_lo + (ks * 16 + arow) * QSS + wn * 16 + ahalf);
        }
        __syncthreads();
        if (t + 1 < ntiles) {
            stage_kv128(Vhi, Vlo, kv_hi, kv_lo, b, h, kt + 128, tid);
            CP_COMMIT;
        }

#pragma unroll
        for (int ks = 0; ks < 8; ks++) {
            const int arow = lane & 15;
            const int ahalf = (lane >> 4) * 8;
            uint32_t wh[4], wl[4];
            ldsm4(wh, w_hi + (wm * 16 + arow) * WSS + ks * 16 + ahalf);
            ldsm4(wl, w_lo + (wm * 16 + arow) * WSS + ks * 16 + ahalf);
#pragma unroll
            for (int n8 = 0; n8 < 2; n8++) {
                mma_bf16(accc[n8], wh, vh[ks][n8 * 2], vh[ks][n8 * 2 + 1]);
                mma_bf16(accc[n8], wh, vl[ks][n8 * 2], vl[ks][n8 * 2 + 1]);
                mma_bf16(accc[n8], wl, vh[ks][n8 * 2], vh[ks][n8 * 2 + 1]);
            }
        }
        __syncthreads();   // protect w buffer before next conversion
    }

    // ---- ctx epilogue: (+SufV) * zinv -> bf16 hi/lo ----
#pragma unroll
    for (int n8 = 0; n8 < 2; n8++) {
        int r0 = wm * 16 + (lane >> 2);
        int dc = wn * 16 + n8 * 8 + (lane & 3) * 2;
        float zi0 = zinv[r0];
        float zi8 = zinv[r0 + 8];
        float2 s0 = *(const float2*)&Suf[((size_t)bh * SEQ + q0 + r0) * HD + dc];
        float2 s8 = *(const float2*)&Suf[((size_t)bh * SEQ + q0 + r0 + 8) * HD + dc];
        float v00 = (accc[n8][0] + s0.x) * zi0;
        float v01 = (accc[n8][1] + s0.y) * zi0;
        float v10 = (accc[n8][2] + s8.x) * zi8;
        float v11 = (accc[n8][3] + s8.y) * zi8;
        __nv_bfloat162 h0, l0, h1, l1;
        h0.x = __float2bfloat16(v00); h0.y = __float2bfloat16(v01);
        l0.x = __float2bfloat16(v00 - __bfloat162float(h0.x));
        l0.y = __float2bfloat16(v01 - __bfloat162float(h0.y));
        h1.x = __float2bfloat16(v10); h1.y = __float2bfloat16(v11);
        l1.x = __float2bfloat16(v10 - __bfloat162float(h1.x));
        l1.y = __float2bfloat16(v11 - __bfloat162float(h1.y));
        size_t o0 = ((size_t)(b * SEQ + q0 + r0)) * EMB + h * HD + dc;
        size_t o8 = ((size_t)(b * SEQ + q0 + r0 + 8)) * EMB + h * HD + dc;
        *(__nv_bfloat162*)&Chi[o0] = h0;
        *(__nv_bfloat162*)&Clo[o0] = l0;
        *(__nv_bfloat162*)&Chi[o8] = h1;
        *(__nv_bfloat162*)&Clo[o8] = l1;
    }
}

// ---------------- launch ----------------------------------------------------
extern "C" void kernel_launch(void* const* d_in, const int* in_sizes, int n_in,
                              void* d_out, int out_size)
{
    const float* query = (const float*)d_in[0];
    const float* key   = (const float*)d_in[1];
    const float* value = (const float*)d_in[2];
    const float* cons  = (const float*)d_in[3];
    const float* Wq = (const float*)d_in[5];
    const float* bq = (const float*)d_in[6];
    const float* Wk = (const float*)d_in[7];
    const float* bk = (const float*)d_in[8];
    const float* Wv = (const float*)d_in[9];
    const float* bv = (const float*)d_in[10];
    const float* Wo = (const float*)d_in[11];
    const float* bo = (const float*)d_in[12];
    const float* Wc = (const float*)d_in[13];
    const float* bc = (const float*)d_in[14];

    float* qp; cudaGetSymbolAddress((void**)&qp, g_q);
    float* kp; cudaGetSymbolAddress((void**)&kp, g_k);
    float* vp; cudaGetSymbolAddress((void**)&vp, g_v);
    float* cp; cudaGetSymbolAddress((void**)&cp, g_ctx);
    float* cwp; cudaGetSymbolAddress((void**)&cwp, g_cw);
    float* sufp; cudaGetSymbolAddress((void**)&sufp, g_vsuf);
    __nv_bfloat16* ahi; cudaGetSymbolAddress((void**)&ahi, g_ahi);
    __nv_bfloat16* alo; cudaGetSymbolAddress((void**)&alo, g_alo);
    __nv_bfloat16* whi; cudaGetSymbolAddress((void**)&whi, g_whi);
    __nv_bfloat16* wlo; cudaGetSymbolAddress((void**)&wlo, g_wlo);

    const int M = BATCH * SEQ;
    const int A4 = M * EMB / 4;
    const int W4 = EMB * EMB / 4;
    const size_t AE = (size_t)M * EMB;
    const size_t WE = (size_t)EMB * EMB;

    // bf16 hi/lo views of the fp32 scratch buffers
    __nv_bfloat16* qhi = (__nv_bfloat16*)qp;  __nv_bfloat16* qlo = qhi + AE;
    __nv_bfloat16* khi = (__nv_bfloat16*)kp;  __nv_bfloat16* klo = khi + AE;
    __nv_bfloat16* vhi = (__nv_bfloat16*)vp;  __nv_bfloat16* vlo = vhi + AE;
    __nv_bfloat16* chi = (__nv_bfloat16*)cp;  __nv_bfloat16* clo = chi + AE;

    float* out = (float*)d_out;
    float* attn_out = out + (size_t)BATCH * SEQ * EMB;

    dim3 gemm_grid(EMB / BN, M / BM);
    const int gemm_smem = GSTAGES * STAGE_ELEM * sizeof(__nv_bfloat16); // ~111KB
    cudaFuncSetAttribute(gemm_bf16x3f, cudaFuncAttributeMaxDynamicSharedMemorySize, gemm_smem);
    cudaFuncSetAttribute(attn_mma_kernel, cudaFuncAttributeMaxDynamicSharedMemorySize, ATTN_SMEM);

    // input splits for projection GEMMs
    dim3 sa_grid((A4 + 255) / 256, 3);
    split_act3_kernel<<<sa_grid, 256>>>(query, key, value, ahi, alo, A4);
    dim3 sw_grid((W4 + 255) / 256, 4);
    split_w4_kernel<<<sw_grid, 256>>>(Wq, Wk, Wv, Wo, whi, wlo, W4);

    // QKV projections, bf16 hi/lo outputs (no fp32 intermediate, no re-split)
    gemm_bf16x3f<<<gemm_grid, 256, gemm_smem>>>(ahi,          alo,          whi,          wlo,          bq, nullptr, qhi, qlo, M, EMB, EMB);
    gemm_bf16x3f<<<gemm_grid, 256, gemm_smem>>>(ahi + AE,     alo + AE,     whi + WE,     wlo + WE,     bk, nullptr, khi, klo, M, EMB, EMB);
    gemm_bf16x3f<<<gemm_grid, 256, gemm_smem>>>(ahi + 2 * AE, alo + 2 * AE, whi + 2 * WE, wlo + 2 * WE, bv, nullptr, vhi, vlo, M, EMB, EMB);

    cw_kernel<<<M / 8, 128>>>(query, Wc, bc, cwp);
    vsuffix_hl_kernel<<<BATCH * NH, 256>>>(vhi, vlo, sufp);

    dim3 attn_grid(SEQ / AR, BATCH * NH);   // (32, 64)
    attn_mma_kernel<<<attn_grid, 256, ATTN_SMEM>>>(
        qhi, qlo, khi, klo, vhi, vlo, cwp, cons, sufp, attn_out, chi, clo);

    // O projection from ctx hi/lo, fp32 output
    gemm_bf16x3f<<<gemm_grid, 256, gemm_smem>>>(chi, clo, whi + 3 * WE, wlo + 3 * WE, bo, out, nullptr, nullptr, M, EMB, EMB);
}

// round 10
// speedup vs baseline: 4.1111x; 1.1136x over previous
#include <cuda_runtime.h>
#include <cuda_bf16.h>
#include <math.h>
#include <stdint.h>

#define EMB 1024
#define SEQ 1024
#define BATCH 4
#define NH 16
#define HD 64

// ---------------- scratch (device globals; no allocation allowed) ----------
// g_q/g_k/g_v/g_ctx hold bf16 hi|lo pairs (each 16MB = 2 x 8MB bf16).
__device__ float g_q[BATCH * SEQ * EMB];
__device__ float g_k[BATCH * SEQ * EMB];
__device__ float g_v[BATCH * SEQ * EMB];
__device__ float g_ctx[BATCH * SEQ * EMB];
__device__ float g_cw[BATCH * SEQ * NH];
__device__ float g_vsuf[BATCH * NH * SEQ * HD];
__device__ __nv_bfloat16 g_ahi[3][BATCH * SEQ * EMB];
__device__ __nv_bfloat16 g_alo[3][BATCH * SEQ * EMB];
__device__ __nv_bfloat16 g_whi[4][EMB * EMB];
__device__ __nv_bfloat16 g_wlo[4][EMB * EMB];

// ---------------- fast exp: FFMA-only ---------------------------------------
__device__ __forceinline__ float fast_exp(float x)
{
    x = fmaxf(x, -80.0f);
    const float L2E = 1.4426950408889634f;
    float t = fmaf(x, L2E, 12582912.0f);
    float i = t - 12582912.0f;
    float f = fmaf(x, L2E, -i);
    float p = 1.3333558146e-3f;
    p = fmaf(p, f, 9.6181291918e-3f);
    p = fmaf(p, f, 5.5504108664e-2f);
    p = fmaf(p, f, 2.4022650696e-1f);
    p = fmaf(p, f, 6.9314718056e-1f);
    p = fmaf(p, f, 1.0f);
    return __int_as_float(__float_as_int(p) + ((int)i << 23));
}

// ---------------- mma / ldmatrix helpers -------------------------------------
__device__ __forceinline__ void ldsm4(uint32_t* r, const void* p)
{
    uint32_t a = (uint32_t)__cvta_generic_to_shared(p);
    asm volatile("ldmatrix.sync.aligned.m8n8.x4.shared.b16 {%0,%1,%2,%3},[%4];"
                 : "=r"(r[0]), "=r"(r[1]), "=r"(r[2]), "=r"(r[3]) : "r"(a));
}
__device__ __forceinline__ void ldsm4t(uint32_t* r, const void* p)
{
    uint32_t a = (uint32_t)__cvta_generic_to_shared(p);
    asm volatile("ldmatrix.sync.aligned.m8n8.x4.trans.shared.b16 {%0,%1,%2,%3},[%4];"
                 : "=r"(r[0]), "=r"(r[1]), "=r"(r[2]), "=r"(r[3]) : "r"(a));
}
__device__ __forceinline__ void mma_bf16(float* c, const uint32_t* a,
                                         uint32_t b0, uint32_t b1)
{
    asm volatile(
        "mma.sync.aligned.m16n8k16.row.col.f32.bf16.bf16.f32 "
        "{%0,%1,%2,%3},{%4,%5,%6,%7},{%8,%9},{%0,%1,%2,%3};"
        : "+f"(c[0]), "+f"(c[1]), "+f"(c[2]), "+f"(c[3])
        : "r"(a[0]), "r"(a[1]), "r"(a[2]), "r"(a[3]), "r"(b0), "r"(b1));
}

// ---------------- fp32 -> bf16 hi/lo split ----------------------------------
__device__ __forceinline__ void split4(
    const float* __restrict__ X, __nv_bfloat16* __restrict__ Hi,
    __nv_bfloat16* __restrict__ Lo, int i)
{
    float4 x = ((const float4*)X)[i];
    __nv_bfloat16 h0 = __float2bfloat16(x.x);
    __nv_bfloat16 h1 = __float2bfloat16(x.y);
    __nv_bfloat16 h2 = __float2bfloat16(x.z);
    __nv_bfloat16 h3 = __float2bfloat16(x.w);
    __nv_bfloat162 H0; H0.x = h0; H0.y = h1;
    __nv_bfloat162 H1; H1.x = h2; H1.y = h3;
    __nv_bfloat162 L0;
    L0.x = __float2bfloat16(x.x - __bfloat162float(h0));
    L0.y = __float2bfloat16(x.y - __bfloat162float(h1));
    __nv_bfloat162 L1;
    L1.x = __float2bfloat16(x.z - __bfloat162float(h2));
    L1.y = __float2bfloat16(x.w - __bfloat162float(h3));
    ((__nv_bfloat162*)Hi)[2 * i] = H0;
    ((__nv_bfloat162*)Hi)[2 * i + 1] = H1;
    ((__nv_bfloat162*)Lo)[2 * i] = L0;
    ((__nv_bfloat162*)Lo)[2 * i + 1] = L1;
}

__global__ __launch_bounds__(256) void split_act3_kernel(
    const float* __restrict__ X0, const float* __restrict__ X1,
    const float* __restrict__ X2, __nv_bfloat16* __restrict__ Hi,
    __nv_bfloat16* __restrict__ Lo, int n4)
{
    int i = blockIdx.x * 256 + threadIdx.x;
    if (i >= n4) return;
    int s = blockIdx.y;
    const float* X = (s == 0) ? X0 : (s == 1) ? X1 : X2;
    split4(X, Hi + (size_t)s * BATCH * SEQ * EMB,
           Lo + (size_t)s * BATCH * SEQ * EMB, i);
}

__global__ __launch_bounds__(256) void split_w4_kernel(
    const float* __restrict__ W0, const float* __restrict__ W1,
    const float* __restrict__ W2, const float* __restrict__ W3,
    __nv_bfloat16* __restrict__ Hi, __nv_bfloat16* __restrict__ Lo, int n4)
{
    int i = blockIdx.x * 256 + threadIdx.x;
    if (i >= n4) return;
    int s = blockIdx.y;
    const float* W = (s == 0) ? W0 : (s == 1) ? W1 : (s == 2) ? W2 : W3;
    split4(W, Hi + (size_t)s * EMB * EMB, Lo + (size_t)s * EMB * EMB, i);
}

// ---------------- fused bf16x3 GEMM: 4 warps, warp tile 64x64 ----------------
// C = Ahi@Bhi + Ahi@Blo + Alo@Bhi + bias.
// 128 threads, BM=BN=128, BK=32, 2-stage cp.async ring, 2 CTAs/SM.
#define BM 128
#define BN 128
#define BK 32
#define ASTR 40
#define BSTR 136
#define A_ELEM (BM * ASTR)
#define B_ELEM (BK * BSTR)
#define STAGE_ELEM (2 * A_ELEM + 2 * B_ELEM)
#define GEMM_SMEM (2 * STAGE_ELEM * (int)sizeof(__nv_bfloat16))

#define CP_ASYNC16(dst, src) \
    asm volatile("cp.async.cg.shared.global [%0], [%1], 16;\n" :: "r"(dst), "l"(src))
#define CP_COMMIT asm volatile("cp.async.commit_group;\n" ::)
#define CP_WAITG(n) asm volatile("cp.async.wait_group %0;\n" :: "n"(n))

__device__ __forceinline__ void gemm_core(
    const __nv_bfloat16* __restrict__ Ahi, const __nv_bfloat16* __restrict__ Alo,
    const __nv_bfloat16* __restrict__ Bhi, const __nv_bfloat16* __restrict__ Blo,
    const float* __restrict__ bias, float* __restrict__ C,
    __nv_bfloat16* __restrict__ Chi, __nv_bfloat16* __restrict__ Clo,
    int M, int N, int K)
{
    extern __shared__ __align__(16) __nv_bfloat16 smem[];

    const int tid = threadIdx.x;      // 0..127
    const int lane = tid & 31;
    const int wid = tid >> 5;         // 0..3
    const int wm = wid & 1;           // m 64-half
    const int wn = wid >> 1;          // n 64-half
    const int row0 = blockIdx.y * BM;
    const int col0 = blockIdx.x * BN;

    float acc[4][8][4];
#pragma unroll
    for (int i = 0; i < 4; i++)
#pragma unroll
        for (int j = 0; j < 8; j++)
#pragma unroll
            for (int r = 0; r < 4; r++) acc[i][j][r] = 0.f;

    const int TOT = K / BK;   // 32

#define LOAD_STAGE(IT, BUF) do {                                               \
    int k0_ = (IT) * BK;                                                       \
    __nv_bfloat16* sa_hi = smem + (BUF) * STAGE_ELEM;                          \
    __nv_bfloat16* sa_lo = sa_hi + A_ELEM;                                     \
    __nv_bfloat16* sb_hi = sa_lo + A_ELEM;                                     \
    __nv_bfloat16* sb_lo = sb_hi + B_ELEM;                                     \
    _Pragma("unroll")                                                          \
    for (int li = 0; li < 4; li++) {                                           \
        int idx = tid + li * 128;                                              \
        int ar = idx >> 2, ac = (idx & 3) * 8;                                 \
        int br = idx >> 4, bc = (idx & 15) * 8;                                \
        CP_ASYNC16((uint32_t)__cvta_generic_to_shared(&sa_hi[ar * ASTR + ac]), \
                   Ahi + (size_t)(row0 + ar) * K + k0_ + ac);                  \
        CP_ASYNC16((uint32_t)__cvta_generic_to_shared(&sa_lo[ar * ASTR + ac]), \
                   Alo + (size_t)(row0 + ar) * K + k0_ + ac);                  \
        CP_ASYNC16((uint32_t)__cvta_generic_to_shared(&sb_hi[br * BSTR + bc]), \
                   Bhi + (size_t)(k0_ + br) * N + col0 + bc);                  \
        CP_ASYNC16((uint32_t)__cvta_generic_to_shared(&sb_lo[br * BSTR + bc]), \
                   Blo + (size_t)(k0_ + br) * N + col0 + bc);                  \
    }                                                                          \
} while (0)

    LOAD_STAGE(0, 0); CP_COMMIT;

    for (int it = 0; it < TOT; it++) {
        const int buf = it & 1;
        if (it + 1 < TOT) {
            LOAD_STAGE(it + 1, (it + 1) & 1);
            CP_COMMIT;
            CP_WAITG(1);
        } else {
            CP_WAITG(0);
        }
        __syncthreads();

        const __nv_bfloat16* sa_hi = smem + buf * STAGE_ELEM;
        const __nv_bfloat16* sa_lo = sa_hi + A_ELEM;
        const __nv_bfloat16* sb_hi = sa_lo + A_ELEM;
        const __nv_bfloat16* sb_lo = sb_hi + B_ELEM;

#pragma unroll
        for (int ks = 0; ks < 2; ks++) {
            uint32_t ahi[4][4], alo[4][4];
#pragma unroll
            for (int mi = 0; mi < 4; mi++) {
                int roff = (wm * 64 + mi * 16 + (lane & 15)) * ASTR +
                           ks * 16 + (lane >> 4) * 8;
                ldsm4(ahi[mi], &sa_hi[roff]);
                ldsm4(alo[mi], &sa_lo[roff]);
            }
#pragma unroll
            for (int bi = 0; bi < 4; bi++) {
                uint32_t bhi[4], blo[4];
                int boff = (ks * 16 + (lane & 15)) * BSTR +
                           wn * 64 + bi * 16 + (lane >> 4) * 8;
                ldsm4t(bhi, &sb_hi[boff]);
                ldsm4t(blo, &sb_lo[boff]);
#pragma unroll
                for (int p = 0; p < 2; p++) {
                    int ni = bi * 2 + p;
#pragma unroll
                    for (int mi = 0; mi < 4; mi++) {
                        mma_bf16(acc[mi][ni], ahi[mi], bhi[p * 2], bhi[p * 2 + 1]);
                        mma_bf16(acc[mi][ni], ahi[mi], blo[p * 2], blo[p * 2 + 1]);
                        mma_bf16(acc[mi][ni], alo[mi], bhi[p * 2], bhi[p * 2 + 1]);
                    }
                }
            }
        }
        __syncthreads();
    }

    const int g = lane >> 2;
    const int t = lane & 3;
#pragma unroll
    for (int ni = 0; ni < 8; ni++) {
        int col = col0 + wn * 64 + ni * 8 + t * 2;
        float b0 = bias[col], b1 = bias[col + 1];
#pragma unroll
        for (int mi = 0; mi < 4; mi++) {
            int row = row0 + wm * 64 + mi * 16 + g;
            float v00 = acc[mi][ni][0] + b0, v01 = acc[mi][ni][1] + b1;
            float v10 = acc[mi][ni][2] + b0, v11 = acc[mi][ni][3] + b1;
            if (Chi) {
                __nv_bfloat162 h0, l0, h1, l1;
                h0.x = __float2bfloat16(v00);
                h0.y = __float2bfloat16(v01);
                l0.x = __float2bfloat16(v00 - __bfloat162float(h0.x));
                l0.y = __float2bfloat16(v01 - __bfloat162float(h0.y));
                h1.x = __float2bfloat16(v10);
                h1.y = __float2bfloat16(v11);
                l1.x = __float2bfloat16(v10 - __bfloat162float(h1.x));
                l1.y = __float2bfloat16(v11 - __bfloat162float(h1.y));
                *(__nv_bfloat162*)&Chi[(size_t)row * N + col] = h0;
                *(__nv_bfloat162*)&Clo[(size_t)row * N + col] = l0;
                *(__nv_bfloat162*)&Chi[(size_t)(row + 8) * N + col] = h1;
                *(__nv_bfloat162*)&Clo[(size_t)(row + 8) * N + col] = l1;
            } else {
                float2 o0 = { v00, v01 };
                float2 o1 = { v10, v11 };
                *(float2*)&C[(size_t)row * N + col] = o0;
                *(float2*)&C[(size_t)(row + 8) * N + col] = o1;
            }
        }
    }
#undef LOAD_STAGE
}

// fused QKV: grid.z = 0..2 selects projection
__global__ __launch_bounds__(128, 2) void gemm_qkv(
    const __nv_bfloat16* __restrict__ Ahi, const __nv_bfloat16* __restrict__ Alo,
    const __nv_bfloat16* __restrict__ Whi, const __nv_bfloat16* __restrict__ Wlo,
    const float* __restrict__ b0, const float* __restrict__ b1,
    const float* __restrict__ b2,
    __nv_bfloat16* __restrict__ o0h, __nv_bfloat16* __restrict__ o0l,
    __nv_bfloat16* __restrict__ o1h, __nv_bfloat16* __restrict__ o1l,
    __nv_bfloat16* __restrict__ o2h, __nv_bfloat16* __restrict__ o2l)
{
    const int s = blockIdx.z;
    const size_t AE = (size_t)BATCH * SEQ * EMB;
    const size_t WE = (size_t)EMB * EMB;
    const float* bias = (s == 0) ? b0 : (s == 1) ? b1 : b2;
    __nv_bfloat16* ch = (s == 0) ? o0h : (s == 1) ? o1h : o2h;
    __nv_bfloat16* cl = (s == 0) ? o0l : (s == 1) ? o1l : o2l;
    gemm_core(Ahi + s * AE, Alo + s * AE, Whi + s * WE, Wlo + s * WE,
              bias, nullptr, ch, cl, BATCH * SEQ, EMB, EMB);
}

__global__ __launch_bounds__(128, 2) void gemm_single(
    const __nv_bfloat16* __restrict__ Ahi, const __nv_bfloat16* __restrict__ Alo,
    const __nv_bfloat16* __restrict__ Whi, const __nv_bfloat16* __restrict__ Wlo,
    const float* __restrict__ bias, float* __restrict__ C)
{
    gemm_core(Ahi, Alo, Whi, Wlo, bias, C, nullptr, nullptr,
              BATCH * SEQ, EMB, EMB);
}

// ---------------- cw = softmax(query @ Wc + bc, axis=H) --------------------
__global__ __launch_bounds__(128) void cw_kernel(
    const float* __restrict__ query, const float* __restrict__ Wc,
    const float* __restrict__ bc, float* __restrict__ CW)
{
    __shared__ float qs[8][1024];
    const int tid = threadIdx.x;
    const int row0 = blockIdx.x * 8;

    for (int idx = tid; idx < 2048; idx += 128) {
        int r = idx >> 8;
        int c4 = (idx & 255) * 4;
        *(float4*)&qs[r][c4] = *(const float4*)&query[(size_t)(row0 + r) * EMB + c4];
    }
    __syncthreads();

    const int r = tid >> 4;
    const int h = tid & 15;
    const float* q = &qs[r][0];

    float a0 = 0.f, a1 = 0.f, a2 = 0.f, a3 = 0.f;
#pragma unroll 4
    for (int i = 0; i < EMB; i += 4) {
        a0 += q[i + 0] * Wc[(i + 0) * NH + h];
        a1 += q[i + 1] * Wc[(i + 1) * NH + h];
        a2 += q[i + 2] * Wc[(i + 2) * NH + h];
        a3 += q[i + 3] * Wc[(i + 3) * NH + h];
    }
    float acc = bc[h] + (a0 + a1) + (a2 + a3);

    float m = acc;
#pragma unroll
    for (int o = 8; o > 0; o >>= 1) m = fmaxf(m, __shfl_xor_sync(0xffffffffu, m, o, 16));
    float e = fast_exp(acc - m);
    float s = e;
#pragma unroll
    for (int o = 8; o > 0; o >>= 1) s += __shfl_xor_sync(0xffffffffu, s, o, 16);
    CW[(size_t)(row0 + r) * NH + h] = e / s;
}

// ---------------- suffix sums of V (from bf16 hi/lo) -------------------------
__global__ __launch_bounds__(256) void vsuffix_hl_kernel(
    const __nv_bfloat16* __restrict__ Vhi, const __nv_bfloat16* __restrict__ Vlo,
    float* __restrict__ Suf)
{
    __shared__ float T[4][64];
    const int bh = blockIdx.x;
    const int b = bh >> 4;
    const int h = bh & 15;
    const int t = threadIdx.x;
    const int p = t >> 6;
    const int d = t & 63;

    const size_t base = (size_t)b * SEQ * EMB + h * HD + d;
    float* sufb = Suf + (size_t)bh * SEQ * HD + d;

    const int k0 = p * 256;
    float s = 0.f;
    for (int k = k0; k < k0 + 256; k++) {
        size_t o = base + (size_t)k * EMB;
        s += __bfloat162float(Vhi[o]) + __bfloat162float(Vlo[o]);
    }
    T[p][d] = s;
    __syncthreads();

    float acc = 0.f;
    for (int pp = p + 1; pp < 4; pp++) acc += T[pp][d];
    for (int k = k0 + 255; k >= k0; k--) {
        size_t o = base + (size_t)k * EMB;
        sufb[(size_t)k * HD] = acc;
        acc += __bfloat162float(Vhi[o]) + __bfloat162float(Vlo[o]);
    }
}

// ---------------- tensor-core attention (round-8, verified) ------------------
#define AR 32
#define QSS 72
#define WSS 136
#define EST 1036
#define ESC_BYTES (AR * EST * 4)
#define KV_OFF    ESC_BYTES
#define KV_BYTES  (128 * QSS * 2)
#define QH_OFF    (KV_OFF + 2 * KV_BYTES)
#define QMAT_BYTES (AR * QSS * 2)
#define WH_OFF    (QH_OFF + 2 * QMAT_BYTES)
#define WMAT_BYTES (AR * WSS * 2)
#define ATTN_SMEM (WH_OFF + 2 * WMAT_BYTES)

__device__ __forceinline__ void stage_kv128(
    const __nv_bfloat16* __restrict__ Ghi, const __nv_bfloat16* __restrict__ Glo,
    __nv_bfloat16* s_hi, __nv_bfloat16* s_lo, int b, int h, int kt, int tid)
{
#pragma unroll
    for (int li = 0; li < 4; li++) {
        int c = tid + li * 256;
        int r = c >> 3, c16 = c & 7;
        size_t goff = (size_t)(b * SEQ + kt + r) * EMB + h * HD + c16 * 8;
        CP_ASYNC16((uint32_t)__cvta_generic_to_shared(s_hi + r * QSS + c16 * 8), Ghi + goff);
        CP_ASYNC16((uint32_t)__cvta_generic_to_shared(s_lo + r * QSS + c16 * 8), Glo + goff);
    }
}

__global__ __launch_bounds__(256, 1) void attn_mma_kernel(
    const __nv_bfloat16* __restrict__ Qhi, const __nv_bfloat16* __restrict__ Qlo,
    const __nv_bfloat16* __restrict__ Khi, const __nv_bfloat16* __restrict__ Klo,
    const __nv_bfloat16* __restrict__ Vhi, const __nv_bfloat16* __restrict__ Vlo,
    const float* __restrict__ CW, const float* __restrict__ cons,
    const float* __restrict__ Suf, float* __restrict__ attn_out,
    __nv_bfloat16* __restrict__ Chi, __nv_bfloat16* __restrict__ Clo)
{
    extern __shared__ __align__(16) char smraw[];
    float* esc = (float*)smraw;
    __nv_bfloat16* kv_hi = (__nv_bfloat16*)(smraw + KV_OFF);
    __nv_bfloat16* kv_lo = (__nv_bfloat16*)(smraw + KV_OFF + KV_BYTES);
    __nv_bfloat16* q_hi  = (__nv_bfloat16*)(smraw + QH_OFF);
    __nv_bfloat16* q_lo  = (__nv_bfloat16*)(smraw + QH_OFF + QMAT_BYTES);
    __nv_bfloat16* w_hi  = (__nv_bfloat16*)(smraw + WH_OFF);
    __nv_bfloat16* w_lo  = (__nv_bfloat16*)(smraw + WH_OFF + WMAT_BYTES);
    __shared__ float zinv[AR];

    const int tid = threadIdx.x;
    const int lane = tid & 31;
    const int w = tid >> 5;
    const int bh = blockIdx.y;
    const int b = bh >> 4;
    const int h = bh & 15;
    const int q0 = (gridDim.x - 1 - blockIdx.x) * AR;
    const int kmax = q0 + AR;
    const int ntiles = (kmax + 127) >> 7;
    const float INV_SCALE = 1.0f / (8.0f * sqrtf(1.61803398874989485f));

#pragma unroll
    for (int li = 0; li < 2; li++) {
        int c = tid + li * 256;
        int r = (c & 255) >> 3;
        int c16 = c & 7;
        const __nv_bfloat16* src = ((c < 256) ? Qhi : Qlo)
            + (size_t)(b * SEQ + q0 + r) * EMB + h * HD + c16 * 8;
        __nv_bfloat16* dst = ((c < 256) ? q_hi : q_lo) + r * QSS + c16 * 8;
        CP_ASYNC16((uint32_t)__cvta_generic_to_shared(dst), src);
    }
    CP_COMMIT;
    stage_kv128(Khi, Klo, kv_hi, kv_lo, b, h, 0, tid);
    CP_COMMIT;

    CP_WAITG(1);
    __syncthreads();
    uint32_t qh[4][2][4], ql[4][2][4];
#pragma unroll
    for (int ks = 0; ks < 4; ks++) {
        const int arow = lane & 15;
        const int acol = ks * 16 + (lane >> 4) * 8;
#pragma unroll
        for (int m = 0; m < 2; m++) {
            ldsm4(qh[ks][m], q_hi + (m * 16 + arow) * QSS + acol);
            ldsm4(ql[ks][m], q_lo + (m * 16 + arow) * QSS + acol);
        }
    }

    for (int t = 0; t < ntiles; t++) {
        const int kt = t * 128;
        CP_WAITG(0);
        __syncthreads();

        uint32_t kh[4][4], kl[4][4];
#pragma unroll
        for (int ks = 0; ks < 4; ks++) {
            const int arow = lane & 15;
            const int acol = ks * 16 + (lane >> 4) * 8;
            ldsm4(kh[ks], kv_hi + (w * 16 + arow) * QSS + acol);
            ldsm4(kl[ks], kv_lo + (w * 16 + arow) * QSS + acol);
        }
        __syncthreads();
        if (t + 1 < ntiles) {
            stage_kv128(Khi, Klo, kv_hi, kv_lo, b, h, kt + 128, tid);
            CP_COMMIT;
        }

        float accs[2][2][4];
#pragma unroll
        for (int m = 0; m < 2; m++)
#pragma unroll
            for (int n = 0; n < 2; n++)
#pragma unroll
                for (int r = 0; r < 4; r++) accs[m][n][r] = 0.f;

#pragma unroll
        for (int ks = 0; ks < 4; ks++)
#pragma unroll
            for (int m = 0; m < 2; m++)
#pragma unroll
                for (int n8 = 0; n8 < 2; n8++) {
                    mma_bf16(accs[m][n8], qh[ks][m], kh[ks][n8], kh[ks][n8 + 2]);
                    mma_bf16(accs[m][n8], qh[ks][m], kl[ks][n8], kl[ks][n8 + 2]);
                    mma_bf16(accs[m][n8], ql[ks][m], kh[ks][n8], kh[ks][n8 + 2]);
                }
#pragma unroll
        for (int m = 0; m < 2; m++)
#pragma unroll
            for (int n8 = 0; n8 < 2; n8++) {
                int row = m * 16 + (lane >> 2);
                int col = kt + w * 16 + n8 * 8 + (lane & 3) * 2;
                float2 lo = { accs[m][n8][0] * INV_SCALE, accs[m][n8][1] * INV_SCALE };
                float2 hi = { accs[m][n8][2] * INV_SCALE, accs[m][n8][3] * INV_SCALE };
                *(float2*)&esc[row * EST + col] = lo;
                *(float2*)&esc[(row + 8) * EST + col] = hi;
            }
    }
    stage_kv128(Vhi, Vlo, kv_hi, kv_lo, b, h, 0, tid);
    CP_COMMIT;
    __syncthreads();

    {
#pragma unroll
        for (int rr = 0; rr < 4; rr++) {
            int r = w * 4 + rr;
            int q = q0 + r;
            int kc = q + 1;
            float* row = &esc[r * EST];

            float m = -1e30f;
            for (int k = lane; k < kc; k += 32) m = fmaxf(m, row[k]);
#pragma unroll
            for (int o = 16; o > 0; o >>= 1) m = fmaxf(m, __shfl_xor_sync(0xffffffffu, m, o));

            float s = 0.f;
            for (int k = lane; k < kc; k += 32) {
                float p = fast_exp(row[k] - m);
                row[k] = p;
                s += p;
            }
#pragma unroll
            for (int o = 16; o > 0; o >>= 1) s += __shfl_xor_sync(0xffffffffu, s, o);

            float cb = cons[b * SEQ + q];
            float cwv = CW[(size_t)(b * SEQ + q) * NH + h];
            float fs = (1.f + cb * cwv) / s;

            float z2 = 0.f;
            for (int k = lane; k < kc; k += 32) {
                float e = fast_exp(row[k] * fs);
                row[k] = e;
                z2 += e;
            }
            for (int k = kc + lane; k < SEQ; k += 32) row[k] = 1.f;
#pragma unroll
            for (int o = 16; o > 0; o >>= 1) z2 += __shfl_xor_sync(0xffffffffu, z2, o);
            z2 += (float)(SEQ - kc);
            if (lane == 0) zinv[r] = 1.f / z2;
        }
    }
    __syncthreads();

    {
        const size_t abase = ((size_t)bh * SEQ + q0) * SEQ;
#pragma unroll 4
        for (int it = 0; it < AR; it++) {
            int idx4 = tid + it * 256;
            int r = idx4 >> 8;
            int c4 = (idx4 & 255) * 4;
            float zi = zinv[r];
            float4 v = *(float4*)&esc[r * EST + c4];
            v.x *= zi; v.y *= zi; v.z *= zi; v.w *= zi;
            *(float4*)&attn_out[abase + (size_t)r * SEQ + c4] = v;
        }
    }
    __syncthreads();

    {
        int r = tid >> 3;
        int q = q0 + r;
        int j = tid & 7;
        int tile_end = ntiles * 128;
        float* row = &esc[r * EST];
        for (int k = q + 1 + j; k < tile_end; k += 8) row[k] = 0.f;
    }
    __syncthreads();

    const int wm = w & 1;
    const int wn = w >> 1;
    float accc[2][4];
#pragma unroll
    for (int n = 0; n < 2; n++)
#pragma unroll
        for (int r = 0; r < 4; r++) accc[n][r] = 0.f;

    for (int t = 0; t < ntiles; t++) {
        const int kt = t * 128;
#pragma unroll
        for (int e = 0; e < 16; e++) {
            int elem = tid + e * 256;
            int row = elem >> 7, col = elem & 127;
            float v = esc[row * EST + kt + col];
            __nv_bfloat16 hv = __float2bfloat16(v);
            w_hi[row * WSS + col] = hv;
            w_lo[row * WSS + col] = __float2bfloat16(v - __bfloat162float(hv));
        }
        CP_WAITG(0);
        __syncthreads();

        uint32_t vh[8][4], vl[8][4];
#pragma unroll
        for (int ks = 0; ks < 8; ks++) {
            const int arow = lane & 15;
            const int ahalf = (lane >> 4) * 8;
            ldsm4t(vh[ks], kv_hi + (ks * 16 + arow) * QSS + wn * 16 + ahalf);
            ldsm4t(vl[ks], kv_lo + (ks * 16 + arow) * QSS + wn * 16 + ahalf);
        }
        __syncthreads();
        if (t + 1 < ntiles) {
            stage_kv128(Vhi, Vlo, kv_hi, kv_lo, b, h, kt + 128, tid);
            CP_COMMIT;
        }

#pragma unroll
        for (int ks = 0; ks < 8; ks++) {
            const int arow = lane & 15;
            const int ahalf = (lane >> 4) * 8;
            uint32_t wh[4], wl[4];
            ldsm4(wh, w_hi + (wm * 16 + arow) * WSS + ks * 16 + ahalf);
            ldsm4(wl, w_lo + (wm * 16 + arow) * WSS + ks * 16 + ahalf);
#pragma unroll
            for (int n8 = 0; n8 < 2; n8++) {
                mma_bf16(accc[n8], wh, vh[ks][n8 * 2], vh[ks][n8 * 2 + 1]);
                mma_bf16(accc[n8], wh, vl[ks][n8 * 2], vl[ks][n8 * 2 + 1]);
                mma_bf16(accc[n8], wl, vh[ks][n8 * 2], vh[ks][n8 * 2 + 1]);
            }
        }
        __syncthreads();
    }

#pragma unroll
    for (int n8 = 0; n8 < 2; n8++) {
        int r0 = wm * 16 + (lane >> 2);
        int dc = wn * 16 + n8 * 8 + (lane & 3) * 2;
        float zi0 = zinv[r0];
        float zi8 = zinv[r0 + 8];
        float2 s0 = *(const float2*)&Suf[((size_t)bh * SEQ + q0 + r0) * HD + dc];
        float2 s8 = *(const float2*)&Suf[((size_t)bh * SEQ + q0 + r0 + 8) * HD + dc];
        float v00 = (accc[n8][0] + s0.x) * zi0;
        float v01 = (accc[n8][1] + s0.y) * zi0;
        float v10 = (accc[n8][2] + s8.x) * zi8;
        float v11 = (accc[n8][3] + s8.y) * zi8;
        __nv_bfloat162 h0, l0, h1, l1;
        h0.x = __float2bfloat16(v00); h0.y = __float2bfloat16(v01);
        l0.x = __float2bfloat16(v00 - __bfloat162float(h0.x));
        l0.y = __float2bfloat16(v01 - __bfloat162float(h0.y));
        h1.x = __float2bfloat16(v10); h1.y = __float2bfloat16(v11);
        l1.x = __float2bfloat16(v10 - __bfloat162float(h1.x));
        l1.y = __float2bfloat16(v11 - __bfloat162float(h1.y));
        size_t o0 = ((size_t)(b * SEQ + q0 + r0)) * EMB + h * HD + dc;
        size_t o8 = ((size_t)(b * SEQ + q0 + r0 + 8)) * EMB + h * HD + dc;
        *(__nv_bfloat162*)&Chi[o0] = h0;
        *(__nv_bfloat162*)&Clo[o0] = l0;
        *(__nv_bfloat162*)&Chi[o8] = h1;
        *(__nv_bfloat162*)&Clo[o8] = l1;
    }
}

// ---------------- launch ----------------------------------------------------
extern "C" void kernel_launch(void* const* d_in, const int* in_sizes, int n_in,
                              void* d_out, int out_size)
{
    const float* query = (const float*)d_in[0];
    const float* key   = (const float*)d_in[1];
    const float* value = (const float*)d_in[2];
    const float* cons  = (const float*)d_in[3];
    const float* Wq = (const float*)d_in[5];
    const float* bq = (const float*)d_in[6];
    const float* Wk = (const float*)d_in[7];
    const float* bk = (const float*)d_in[8];
    const float* Wv = (const float*)d_in[9];
    const float* bv = (const float*)d_in[10];
    const float* Wo = (const float*)d_in[11];
    const float* bo = (const float*)d_in[12];
    const float* Wc = (const float*)d_in[13];
    const float* bc = (const float*)d_in[14];

    float* qp; cudaGetSymbolAddress((void**)&qp, g_q);
    float* kp; cudaGetSymbolAddress((void**)&kp, g_k);
    float* vp; cudaGetSymbolAddress((void**)&vp, g_v);
    float* cp; cudaGetSymbolAddress((void**)&cp, g_ctx);
    float* cwp; cudaGetSymbolAddress((void**)&cwp, g_cw);
    float* sufp; cudaGetSymbolAddress((void**)&sufp, g_vsuf);
    __nv_bfloat16* ahi; cudaGetSymbolAddress((void**)&ahi, g_ahi);
    __nv_bfloat16* alo; cudaGetSymbolAddress((void**)&alo, g_alo);
    __nv_bfloat16* whi; cudaGetSymbolAddress((void**)&whi, g_whi);
    __nv_bfloat16* wlo; cudaGetSymbolAddress((void**)&wlo, g_wlo);

    const int M = BATCH * SEQ;
    const int A4 = M * EMB / 4;
    const int W4 = EMB * EMB / 4;
    const size_t AE = (size_t)M * EMB;
    const size_t WE = (size_t)EMB * EMB;

    __nv_bfloat16* qhi = (__nv_bfloat16*)qp;  __nv_bfloat16* qlo = qhi + AE;
    __nv_bfloat16* khi = (__nv_bfloat16*)kp;  __nv_bfloat16* klo = khi + AE;
    __nv_bfloat16* vhi = (__nv_bfloat16*)vp;  __nv_bfloat16* vlo = vhi + AE;
    __nv_bfloat16* chi = (__nv_bfloat16*)cp;  __nv_bfloat16* clo = chi + AE;

    float* out = (float*)d_out;
    float* attn_out = out + (size_t)BATCH * SEQ * EMB;

    cudaFuncSetAttribute(gemm_qkv, cudaFuncAttributeMaxDynamicSharedMemorySize, GEMM_SMEM);
    cudaFuncSetAttribute(gemm_single, cudaFuncAttributeMaxDynamicSharedMemorySize, GEMM_SMEM);
    cudaFuncSetAttribute(attn_mma_kernel, cudaFuncAttributeMaxDynamicSharedMemorySize, ATTN_SMEM);

    dim3 sa_grid((A4 + 255) / 256, 3);
    split_act3_kernel<<<sa_grid, 256>>>(query, key, value, ahi, alo, A4);
    dim3 sw_grid((W4 + 255) / 256, 4);
    split_w4_kernel<<<sw_grid, 256>>>(Wq, Wk, Wv, Wo, whi, wlo, W4);

    // fused QKV projections (one launch, grid.z = 3)
    dim3 qkv_grid(EMB / BN, M / BM, 3);       // (8, 32, 3) = 768 blocks
    gemm_qkv<<<qkv_grid, 128, GEMM_SMEM>>>(
        ahi, alo, whi, wlo, bq, bk, bv,
        qhi, qlo, khi, klo, vhi, vlo);

    cw_kernel<<<M / 8, 128>>>(query, Wc, bc, cwp);
    vsuffix_hl_kernel<<<BATCH * NH, 256>>>(vhi, vlo, sufp);

    dim3 attn_grid(SEQ / AR, BATCH * NH);     // (32, 64)
    attn_mma_kernel<<<attn_grid, 256, ATTN_SMEM>>>(
        qhi, qlo, khi, klo, vhi, vlo, cwp, cons, sufp, attn_out, chi, clo);

    dim3 gemm_grid(EMB / BN, M / BM);         // (8, 32)
    gemm_single<<<gemm_grid, 128, GEMM_SMEM>>>(
        chi, clo, whi + 3 * WE, wlo + 3 * WE, bo, out);
}